// round 2
// baseline (speedup 1.0000x reference)
#include <cuda_runtime.h>
#include <cstddef>

// Problem constants (fixed by setup_inputs)
#define BQ   2
#define TQ   2048
#define DQ   1024
#define HQ   16
#define HDQ  64
#define ROW3 3072   // 3*DQ

// Scratch (device globals — no allocation allowed)
__device__ float g_qkv[(size_t)BQ * TQ * ROW3];  // [B*T, 3D]; q|k|v, normalized in-place
__device__ float g_att[(size_t)BQ * TQ * DQ];    // attention output in [B,T,D] layout

// ---------------------------------------------------------------------------
// Packed fp32x2 helpers (sm_103a FFMA2 path — ptxas never emits this from C++)
// ---------------------------------------------------------------------------
typedef unsigned long long ull;

__device__ __forceinline__ unsigned su32(const void* p) {
    return (unsigned)__cvta_generic_to_shared(p);
}

#define LDSV2(lo, hi, addr) \
    asm volatile("ld.shared.v2.u64 {%0,%1}, [%2];" : "=l"(lo), "=l"(hi) : "r"(addr))

#define FMA2(d, a, b) \
    asm("fma.rn.f32x2 %0, %1, %2, %0;" : "+l"(d) : "l"(a), "l"(b))

#define UNPACK2(lo, hi, v) \
    asm("mov.b64 {%0,%1}, %2;" : "=f"(lo), "=f"(hi) : "l"(v))

#define RCPA(d, a) \
    asm("rcp.approx.f32 %0, %1;" : "=f"(d) : "f"(a))

// ---------------------------------------------------------------------------
// SGEMM:  C[M,N] = A[M,K] @ B[N,K]^T   (both row-major, K contiguous)
// 128x128 tile, BK=8, 256 threads, 8x8 frag via FFMA2:
//  - acc pairs along M rows (A pairs contiguous in smem -> free via v2.u64)
//  - B stored REPLICATED in smem as float2(b,b) -> broadcast pairs free
// ---------------------------------------------------------------------------
__global__ __launch_bounds__(256, 2) void sgemm_tn(const float* __restrict__ A,
                                                   const float* __restrict__ B,
                                                   float* __restrict__ C,
                                                   int M, int N, int K) {
    __shared__ __align__(16) float  As [8][128];
    __shared__ __align__(16) float2 Bs2[8][128];

    const int tid = threadIdx.x;
    const int tx  = tid & 15;   // output cols (x8)
    const int ty  = tid >> 4;   // output rows (x8)

    const int row0 = blockIdx.y * 128;
    const int col0 = blockIdx.x * 128;

    const int lr = tid >> 1;        // tile row (col for B)
    const int lk = (tid & 1) * 4;   // k offset

    const float* Ap = A + (size_t)(row0 + lr) * K + lk;
    const float* Bp = B + (size_t)(col0 + lr) * K + lk;

    ull acc[4][8];
#pragma unroll
    for (int i = 0; i < 4; i++)
#pragma unroll
        for (int j = 0; j < 8; j++) acc[i][j] = 0ull;

    const unsigned aB = su32(As);
    const unsigned bB = su32(Bs2);
    const unsigned aOff = aB + (unsigned)(ty * 8) * 4u;
    const unsigned bOff = bB + (unsigned)(tx * 8) * 8u;

    float4 a4 = *(const float4*)(Ap);
    float4 b4 = *(const float4*)(Bp);

    for (int k0 = 0; k0 < K; k0 += 8) {
        As[lk + 0][lr] = a4.x; As[lk + 1][lr] = a4.y;
        As[lk + 2][lr] = a4.z; As[lk + 3][lr] = a4.w;
        Bs2[lk + 0][lr] = make_float2(b4.x, b4.x);
        Bs2[lk + 1][lr] = make_float2(b4.y, b4.y);
        Bs2[lk + 2][lr] = make_float2(b4.z, b4.z);
        Bs2[lk + 3][lr] = make_float2(b4.w, b4.w);
        __syncthreads();

        if (k0 + 8 < K) {  // prefetch next tile
            a4 = *(const float4*)(Ap + k0 + 8);
            b4 = *(const float4*)(Bp + k0 + 8);
        }

#pragma unroll
        for (int kk = 0; kk < 8; kk++) {
            ull a01, a23, a45, a67;
            LDSV2(a01, a23, aOff + (unsigned)(kk * 128) * 4u);
            LDSV2(a45, a67, aOff + (unsigned)(kk * 128) * 4u + 16u);
            ull bb[8];
            LDSV2(bb[0], bb[1], bOff + (unsigned)(kk * 128) * 8u);
            LDSV2(bb[2], bb[3], bOff + (unsigned)(kk * 128) * 8u + 16u);
            LDSV2(bb[4], bb[5], bOff + (unsigned)(kk * 128) * 8u + 32u);
            LDSV2(bb[6], bb[7], bOff + (unsigned)(kk * 128) * 8u + 48u);
#pragma unroll
            for (int j = 0; j < 8; j++) {
                FMA2(acc[0][j], a01, bb[j]);
                FMA2(acc[1][j], a23, bb[j]);
                FMA2(acc[2][j], a45, bb[j]);
                FMA2(acc[3][j], a67, bb[j]);
            }
        }
        __syncthreads();
    }

    // Epilogue: acc[ip][j] lanes = rows (ty*8+2ip, ty*8+2ip+1)
#pragma unroll
    for (int ip = 0; ip < 4; ip++) {
        float r0[8], r1[8];
#pragma unroll
        for (int j = 0; j < 8; j++) UNPACK2(r0[j], r1[j], acc[ip][j]);
        float* Cp = C + (size_t)(row0 + ty * 8 + 2 * ip) * N + col0 + tx * 8;
        *(float4*)(Cp)                    = make_float4(r0[0], r0[1], r0[2], r0[3]);
        *(float4*)(Cp + 4)                = make_float4(r0[4], r0[5], r0[6], r0[7]);
        *(float4*)(Cp + (size_t)N)        = make_float4(r1[0], r1[1], r1[2], r1[3]);
        *(float4*)(Cp + (size_t)N + 4)    = make_float4(r1[4], r1[5], r1[6], r1[7]);
    }
}

// ---------------------------------------------------------------------------
// L2-normalize q and k head rows of g_qkv in place. One warp per 64-elem row.
// ---------------------------------------------------------------------------
__global__ __launch_bounds__(256) void normalize_qk(float* __restrict__ qkv) {
    const int gw   = (blockIdx.x * blockDim.x + threadIdx.x) >> 5;
    const int lane = threadIdx.x & 31;
    const int h    = gw & 15;
    const int bt   = (gw >> 4) & (BQ * TQ - 1);
    const int part = gw >> 16;     // 0 = q, 1 = k

    float* p = qkv + (size_t)bt * ROW3 + part * DQ + h * HDQ;
    float v0 = p[lane];
    float v1 = p[lane + 32];
    float ss = v0 * v0 + v1 * v1;
#pragma unroll
    for (int m = 16; m; m >>= 1) ss += __shfl_xor_sync(0xffffffffu, ss, m);
    const float s = 1.0f / fmaxf(sqrtf(ss), 1e-12f);
    p[lane]      = v0 * s;
    p[lane + 32] = v1 * s;
}

// ---------------------------------------------------------------------------
// Causal yat attention, FFMA2 everywhere.
// Block = (q-tile of 64, head, batch), 256 threads, 4x4 fragments.
// Phase A: component-pair reduction (lanes = even/odd hd components).
// Phase B: key-pair reduction (lanes = even/odd key index); V transposed in
//          smem as sVt[d][s ^ 4*((d>>2)&7)] so both operands pair for free.
// ---------------------------------------------------------------------------
__global__ __launch_bounds__(256, 2) void yat_attn(const float* __restrict__ qkv,
                                                   float* __restrict__ attn) {
    __shared__ __align__(16) float4 sQ [64 * 16];
    __shared__ __align__(16) float4 sKS[64 * 16];   // K (swizzled) phase A, S (plain) phase B
    __shared__ __align__(16) float  sVt[64 * 64];   // transposed V [d][s], swizzled

    const int tid = threadIdx.x;
    const int tx  = tid & 15;   // key cols c = tx + 16j ; out dims d = 4*tx + dl
    const int ty  = tid >> 4;   // query rows r = ty + 16i

    const int qt = blockIdx.x;
    const int h  = blockIdx.y;
    const int b  = blockIdx.z;
    const int q0 = qt * 64;

    const unsigned qB = su32(sQ);
    const unsigned kB = su32(sKS);
    const unsigned vB = su32(sVt);
    const unsigned ew = 4u * (unsigned)(tx & 7);  // vt swizzle key for this thread's d block

    const float* qb = qkv + ((size_t)(b * TQ) + q0) * ROW3 + h * HDQ;

    // Load Q tile (swizzled float4 atoms)
#pragma unroll
    for (int it = 0; it < 4; it++) {
        int idx = tid + 256 * it;
        int r = idx >> 4, d4 = idx & 15;
        sQ[r * 16 + (d4 ^ (r & 15))] = *(const float4*)(qb + (size_t)r * ROW3 + d4 * 4);
    }

    ull   accO[4][4];
    float accD[4];
#pragma unroll
    for (int i = 0; i < 4; i++) {
        accD[i] = 0.0f;
#pragma unroll
        for (int j = 0; j < 4; j++) accO[i][j] = 0ull;
    }

    const int nt = qt + 1;  // causal: key tiles 0..qt
    for (int kt = 0; kt < nt; kt++) {
        const int s0 = kt * 64;
        const float* kb = qkv + ((size_t)(b * TQ) + s0) * ROW3 + DQ + h * HDQ;
        const float* vb = kb + DQ;

        __syncthreads();  // previous phase B done
#pragma unroll
        for (int it = 0; it < 4; it++) {
            int idx = tid + 256 * it;
            int r = idx >> 4, d4 = idx & 15;
            sKS[r * 16 + (d4 ^ (r & 15))] = *(const float4*)(kb + (size_t)r * ROW3 + d4 * 4);
            float4 v4 = *(const float4*)(vb + (size_t)r * ROW3 + d4 * 4);
            // transposed store: sVt[d][r ^ 4*(d4&7)], d = d4*4 + c
            int col = r ^ (4 * (d4 & 7));
            sVt[(d4 * 4 + 0) * 64 + col] = v4.x;
            sVt[(d4 * 4 + 1) * 64 + col] = v4.y;
            sVt[(d4 * 4 + 2) * 64 + col] = v4.z;
            sVt[(d4 * 4 + 3) * 64 + col] = v4.w;
        }
        __syncthreads();

        // -------- phase A: S = Qn Kn^T (component-pair partials) --------
        ull S2[4][4];
#pragma unroll
        for (int i = 0; i < 4; i++)
#pragma unroll
            for (int j = 0; j < 4; j++) S2[i][j] = 0ull;

#pragma unroll
        for (int d4 = 0; d4 < 16; d4++) {
            ull ql[4], qh[4], kl[4], kh[4];
#pragma unroll
            for (int i = 0; i < 4; i++)
                LDSV2(ql[i], qh[i], qB + (unsigned)((ty + 16 * i) * 16 + (d4 ^ ty)) * 16u);
#pragma unroll
            for (int j = 0; j < 4; j++)
                LDSV2(kl[j], kh[j], kB + (unsigned)((tx + 16 * j) * 16 + (d4 ^ tx)) * 16u);
#pragma unroll
            for (int i = 0; i < 4; i++)
#pragma unroll
                for (int j = 0; j < 4; j++) {
                    FMA2(S2[i][j], ql[i], kl[j]);
                    FMA2(S2[i][j], qh[i], kh[j]);
                }
        }
        __syncthreads();  // done reading K region

        // -------- transform: w = d^2 / max(2.01-2d,1e-6), mask, den, S->smem ----
        const bool diag = (kt == nt - 1);
        float* sS = (float*)sKS;
#pragma unroll
        for (int i = 0; i < 4; i++) {
            const int r = ty + 16 * i;
#pragma unroll
            for (int j = 0; j < 4; j++) {
                const int c = tx + 16 * j;
                float lo, hi;
                UNPACK2(lo, hi, S2[i][j]);
                const float dv = lo + hi;
                const float den = fmaxf(fmaf(-2.0f, dv, 2.01f), 1e-6f);
                float rc; RCPA(rc, den);
                float w = dv * dv * rc;
                if (diag && c > r) w = 0.0f;
                accD[i] += w;
                sS[r * 64 + c] = w;
            }
        }
        __syncthreads();

        // -------- phase B: O += w @ V (key-pair partials) --------
#pragma unroll
        for (int s4 = 0; s4 < 16; s4++) {
            const unsigned s = (unsigned)(s4 * 4);
            ull wl[4], wh[4];
#pragma unroll
            for (int i = 0; i < 4; i++)
                LDSV2(wl[i], wh[i], kB + ((unsigned)((ty + 16 * i) * 64) + s) * 4u);
            ull vl[4], vh[4];
#pragma unroll
            for (int dl = 0; dl < 4; dl++)
                LDSV2(vl[dl], vh[dl], vB + ((unsigned)((tx * 4 + dl) * 64) + (s ^ ew)) * 4u);
#pragma unroll
            for (int i = 0; i < 4; i++)
#pragma unroll
                for (int dl = 0; dl < 4; dl++) {
                    FMA2(accO[i][dl], wl[i], vl[dl]);
                    FMA2(accO[i][dl], wh[i], vh[dl]);
                }
        }
    }

    // Reduce den across the 16 tx-threads sharing each row
#pragma unroll
    for (int i = 0; i < 4; i++) {
        float d = accD[i];
        d += __shfl_xor_sync(0xffffffffu, d, 8);
        d += __shfl_xor_sync(0xffffffffu, d, 4);
        d += __shfl_xor_sync(0xffffffffu, d, 2);
        d += __shfl_xor_sync(0xffffffffu, d, 1);
        accD[i] = d + 1e-6f;
    }

    // Write O / den to [B,T,D] layout
    float* ob = attn + ((size_t)(b * TQ) + q0) * DQ + h * HDQ + tx * 4;
#pragma unroll
    for (int i = 0; i < 4; i++) {
        const int r = ty + 16 * i;
        float inv; RCPA(inv, accD[i]);
        float o[4];
#pragma unroll
        for (int dl = 0; dl < 4; dl++) {
            float lo, hi;
            UNPACK2(lo, hi, accO[i][dl]);
            o[dl] = (lo + hi) * inv;
        }
        *(float4*)(ob + (size_t)r * DQ) = make_float4(o[0], o[1], o[2], o[3]);
    }
}

// ---------------------------------------------------------------------------
// kernel_launch
// ---------------------------------------------------------------------------
extern "C" void kernel_launch(void* const* d_in, const int* in_sizes, int n_in,
                              void* d_out, int out_size) {
    (void)in_sizes; (void)n_in; (void)out_size;
    const float* x    = (const float*)d_in[0];   // [B,T,D]
    const float* Wqkv = (const float*)d_in[1];   // [3D, D]
    const float* Wout = (const float*)d_in[2];   // [D, D]
    float* out = (float*)d_out;                  // [B,T,D]

    void* p_qkv_v = nullptr;
    void* p_att_v = nullptr;
    cudaGetSymbolAddress(&p_qkv_v, g_qkv);
    cudaGetSymbolAddress(&p_att_v, g_att);
    float* p_qkv = (float*)p_qkv_v;
    float* p_att = (float*)p_att_v;

    const int M = BQ * TQ;  // 4096

    // 1) qkv = x @ Wqkv^T : [4096,3072]
    sgemm_tn<<<dim3(ROW3 / 128, M / 128), 256>>>(x, Wqkv, p_qkv, M, ROW3, DQ);

    // 2) L2-normalize q,k per head in place
    normalize_qk<<<(2 * M * HQ) / 8, 256>>>(p_qkv);

    // 3) causal yat attention -> g_att [B,T,D]
    yat_attn<<<dim3(TQ / 64, HQ, BQ), 256>>>(p_qkv, p_att);

    // 4) out = att @ Wout^T : [4096,1024]
    sgemm_tn<<<dim3(DQ / 128, M / 128), 256>>>(p_att, Wout, out, M, DQ, DQ);
}

// round 4
// speedup vs baseline: 2.8394x; 2.8394x over previous
#include <cuda_runtime.h>
#include <cstddef>
#include <cstdint>

// Problem constants (fixed by setup_inputs)
#define BQ   2
#define TQ   2048
#define DQ   1024
#define HQ   16
#define HDQ  64
#define ROW3 3072   // 3*DQ

// Scratch (device globals — no allocation allowed)
__device__ float g_qkv[(size_t)BQ * TQ * ROW3];  // [B*T, 3D]; q|k|v, normalized in-place
__device__ float g_att[(size_t)BQ * TQ * DQ];    // attention output in [B,T,D] layout

typedef unsigned long long ull;

__device__ __forceinline__ unsigned su32(const void* p) {
    return (unsigned)__cvta_generic_to_shared(p);
}

// ---------------------------------------------------------------------------
// Warp-level tensor-core primitives (base-target PTX: works on compute_103)
// ---------------------------------------------------------------------------
#define LDSM_X4(r0, r1, r2, r3, addr) \
    asm volatile("ldmatrix.sync.aligned.m8n8.x4.shared.b16 {%0,%1,%2,%3}, [%4];" \
        : "=r"(r0), "=r"(r1), "=r"(r2), "=r"(r3) : "r"(addr))

#define MMA16816(c, a, b0, b1) \
    asm volatile("mma.sync.aligned.m16n8k16.row.col.f32.bf16.bf16.f32 " \
        "{%0,%1,%2,%3}, {%4,%5,%6,%7}, {%8,%9}, {%0,%1,%2,%3};" \
        : "+f"((c)[0]), "+f"((c)[1]), "+f"((c)[2]), "+f"((c)[3]) \
        : "r"((a)[0]), "r"((a)[1]), "r"((a)[2]), "r"((a)[3]), "r"(b0), "r"(b1))

// Split a float4 into packed bf16x2 hi and lo (lo = exact residual rounded)
__device__ __forceinline__ void split4(float4 f, uint32_t& h0, uint32_t& h1,
                                       uint32_t& l0, uint32_t& l1) {
    asm("cvt.rn.bf16x2.f32 %0, %1, %2;" : "=r"(h0) : "f"(f.y), "f"(f.x));
    asm("cvt.rn.bf16x2.f32 %0, %1, %2;" : "=r"(h1) : "f"(f.w), "f"(f.z));
    float fx = __uint_as_float(h0 << 16);
    float fy = __uint_as_float(h0 & 0xffff0000u);
    float fz = __uint_as_float(h1 << 16);
    float fw = __uint_as_float(h1 & 0xffff0000u);
    asm("cvt.rn.bf16x2.f32 %0, %1, %2;" : "=r"(l0) : "f"(f.y - fy), "f"(f.x - fx));
    asm("cvt.rn.bf16x2.f32 %0, %1, %2;" : "=r"(l1) : "f"(f.w - fw), "f"(f.z - fz));
}

#define STSV2(addr, v0, v1) \
    asm volatile("st.shared.v2.b32 [%0], {%1,%2};" :: "r"(addr), "r"(v0), "r"(v1) : "memory")

// ---------------------------------------------------------------------------
// bf16x3 emulated-fp32 GEMM:  C[M,N] = A[M,K] @ B[N,K]^T  (fp32 in/out)
// CTA tile 128x128, 8 warps (4x2), BK=32, single smem buffer + reg prefetch.
// smem bf16 tiles, 80B row stride (conflict-free ldmatrix phases).
// Requires M%128==0, N%128==0, K%32==0.
// ---------------------------------------------------------------------------
#define RSTR 80   // bytes per smem row (64B data + 16B pad)

__global__ __launch_bounds__(256) void gemm_bf16x3(const float* __restrict__ A,
                                                   const float* __restrict__ B,
                                                   float* __restrict__ C,
                                                   int M, int N, int K) {
    __shared__ __align__(16) unsigned char sAh[128 * RSTR];
    __shared__ __align__(16) unsigned char sAl[128 * RSTR];
    __shared__ __align__(16) unsigned char sBh[128 * RSTR];
    __shared__ __align__(16) unsigned char sBl[128 * RSTR];

    const int tid  = threadIdx.x;
    const int wid  = tid >> 5;
    const int lane = tid & 31;
    const int wm   = wid & 3;   // 4 -> 32 rows each
    const int wn   = wid >> 2;  // 2 -> 64 cols each

    const int row0 = blockIdx.y * 128;
    const int col0 = blockIdx.x * 128;

    // ldmatrix lane addressing (tile i = lane>>3: row += (i&1)*8, kbyte += (i>>1)*16)
    const int lr = (lane & 7) + ((lane >> 3) & 1) * 8;
    const int lk = (lane >> 4) * 16;

    const unsigned aH = su32(sAh), aL = su32(sAl);
    const unsigned bH = su32(sBh), bL = su32(sBl);

    // producer mapping: row = tid/2, float4 index base = (tid&1)*4
    const int prow = tid >> 1;
    const int pf4  = (tid & 1) * 4;
    const float* Ap = A + (size_t)(row0 + prow) * K + pf4 * 4;
    const float* Bp = B + (size_t)(col0 + prow) * K + pf4 * 4;

    float acc[2][8][4];
#pragma unroll
    for (int mt = 0; mt < 2; mt++)
#pragma unroll
        for (int nt = 0; nt < 8; nt++)
#pragma unroll
            for (int e = 0; e < 4; e++) acc[mt][nt][e] = 0.0f;

    float4 av[4], bv[4];
#pragma unroll
    for (int j = 0; j < 4; j++) {
        av[j] = *(const float4*)(Ap + j * 4);
        bv[j] = *(const float4*)(Bp + j * 4);
    }

    const int nchunks = K / 32;
    for (int c = 0; c < nchunks; c++) {
        __syncthreads();  // previous compute done reading smem
        // ---- store current chunk (split into hi/lo bf16) ----
#pragma unroll
        for (int j = 0; j < 4; j++) {
            uint32_t h0, h1, l0, l1;
            const unsigned off = (unsigned)(prow * RSTR + (pf4 + j) * 8);
            split4(av[j], h0, h1, l0, l1);
            STSV2(aH + off, h0, h1);
            STSV2(aL + off, l0, l1);
            split4(bv[j], h0, h1, l0, l1);
            STSV2(bH + off, h0, h1);
            STSV2(bL + off, l0, l1);
        }
        __syncthreads();

        // ---- prefetch next chunk ----
        if (c + 1 < nchunks) {
            const int k0 = (c + 1) * 32;
#pragma unroll
            for (int j = 0; j < 4; j++) {
                av[j] = *(const float4*)(Ap + k0 + j * 4);
                bv[j] = *(const float4*)(Bp + k0 + j * 4);
            }
        }

        // ---- compute: 2 k16 steps, 3 passes (AhBh, AhBl, AlBh) ----
#pragma unroll
        for (int ks = 0; ks < 2; ks++) {
            const unsigned kb = (unsigned)(ks * 32 + lk);
            uint32_t ah[2][4], al[2][4];
#pragma unroll
            for (int mt = 0; mt < 2; mt++) {
                const unsigned ro = (unsigned)((wm * 32 + mt * 16 + lr) * RSTR) + kb;
                LDSM_X4(ah[mt][0], ah[mt][1], ah[mt][2], ah[mt][3], aH + ro);
                LDSM_X4(al[mt][0], al[mt][1], al[mt][2], al[mt][3], aL + ro);
            }
            uint32_t bh[4][4], bl[4][4];
#pragma unroll
            for (int np = 0; np < 4; np++) {
                const unsigned ro = (unsigned)((wn * 64 + np * 16 + lr) * RSTR) + kb;
                LDSM_X4(bh[np][0], bh[np][1], bh[np][2], bh[np][3], bH + ro);
                LDSM_X4(bl[np][0], bl[np][1], bl[np][2], bl[np][3], bL + ro);
            }
#pragma unroll
            for (int mt = 0; mt < 2; mt++)
#pragma unroll
                for (int nt = 0; nt < 8; nt++) {
                    const int np = nt >> 1, sel = nt & 1;
                    MMA16816(acc[mt][nt], ah[mt], bh[np][sel], bh[np][sel + 2]);
                    MMA16816(acc[mt][nt], ah[mt], bl[np][sel], bl[np][sel + 2]);
                    MMA16816(acc[mt][nt], al[mt], bh[np][sel], bh[np][sel + 2]);
                }
        }
    }

    // ---- epilogue: c0,c1 -> (row, col..col+1); c2,c3 -> (row+8, ...) ----
    const int er = lane >> 2;
    const int ec = (lane & 3) * 2;
#pragma unroll
    for (int mt = 0; mt < 2; mt++) {
        const int row = row0 + wm * 32 + mt * 16 + er;
#pragma unroll
        for (int nt = 0; nt < 8; nt++) {
            const int col = col0 + wn * 64 + nt * 8 + ec;
            *(float2*)(C + (size_t)row * N + col) =
                make_float2(acc[mt][nt][0], acc[mt][nt][1]);
            *(float2*)(C + (size_t)(row + 8) * N + col) =
                make_float2(acc[mt][nt][2], acc[mt][nt][3]);
        }
    }
}

// ---------------------------------------------------------------------------
// L2-normalize q and k head rows of g_qkv in place. One warp per 64-elem row.
// ---------------------------------------------------------------------------
__global__ __launch_bounds__(256) void normalize_qk(float* __restrict__ qkv) {
    const int gw   = (blockIdx.x * blockDim.x + threadIdx.x) >> 5;
    const int lane = threadIdx.x & 31;
    const int h    = gw & 15;
    const int bt   = (gw >> 4) & (BQ * TQ - 1);
    const int part = gw >> 16;     // 0 = q, 1 = k

    float* p = qkv + (size_t)bt * ROW3 + part * DQ + h * HDQ;
    float v0 = p[lane];
    float v1 = p[lane + 32];
    float ss = v0 * v0 + v1 * v1;
#pragma unroll
    for (int m = 16; m; m >>= 1) ss += __shfl_xor_sync(0xffffffffu, ss, m);
    const float s = 1.0f / fmaxf(sqrtf(ss), 1e-12f);
    p[lane]      = v0 * s;
    p[lane + 32] = v1 * s;
}

// ---------------------------------------------------------------------------
// Causal yat attention (FFMA2), unchanged.
// ---------------------------------------------------------------------------
#define LDSV2(lo, hi, addr) \
    asm volatile("ld.shared.v2.u64 {%0,%1}, [%2];" : "=l"(lo), "=l"(hi) : "r"(addr))
#define FMA2(d, a, b) \
    asm("fma.rn.f32x2 %0, %1, %2, %0;" : "+l"(d) : "l"(a), "l"(b))
#define UNPACK2(lo, hi, v) \
    asm("mov.b64 {%0,%1}, %2;" : "=f"(lo), "=f"(hi) : "l"(v))
#define RCPA(d, a) \
    asm("rcp.approx.f32 %0, %1;" : "=f"(d) : "f"(a))

__global__ __launch_bounds__(256, 2) void yat_attn(const float* __restrict__ qkv,
                                                   float* __restrict__ attn) {
    __shared__ __align__(16) float4 sQ [64 * 16];
    __shared__ __align__(16) float4 sKS[64 * 16];
    __shared__ __align__(16) float  sVt[64 * 64];

    const int tid = threadIdx.x;
    const int tx  = tid & 15;
    const int ty  = tid >> 4;

    const int qt = blockIdx.x;
    const int h  = blockIdx.y;
    const int b  = blockIdx.z;
    const int q0 = qt * 64;

    const unsigned qB = su32(sQ);
    const unsigned kB = su32(sKS);
    const unsigned vB = su32(sVt);
    const unsigned ew = 4u * (unsigned)(tx & 7);

    const float* qb = qkv + ((size_t)(b * TQ) + q0) * ROW3 + h * HDQ;

#pragma unroll
    for (int it = 0; it < 4; it++) {
        int idx = tid + 256 * it;
        int r = idx >> 4, d4 = idx & 15;
        sQ[r * 16 + (d4 ^ (r & 15))] = *(const float4*)(qb + (size_t)r * ROW3 + d4 * 4);
    }

    ull   accO[4][4];
    float accD[4];
#pragma unroll
    for (int i = 0; i < 4; i++) {
        accD[i] = 0.0f;
#pragma unroll
        for (int j = 0; j < 4; j++) accO[i][j] = 0ull;
    }

    const int nt = qt + 1;
    for (int kt = 0; kt < nt; kt++) {
        const int s0 = kt * 64;
        const float* kb = qkv + ((size_t)(b * TQ) + s0) * ROW3 + DQ + h * HDQ;
        const float* vb = kb + DQ;

        __syncthreads();
#pragma unroll
        for (int it = 0; it < 4; it++) {
            int idx = tid + 256 * it;
            int r = idx >> 4, d4 = idx & 15;
            sKS[r * 16 + (d4 ^ (r & 15))] = *(const float4*)(kb + (size_t)r * ROW3 + d4 * 4);
            float4 v4 = *(const float4*)(vb + (size_t)r * ROW3 + d4 * 4);
            int col = r ^ (4 * (d4 & 7));
            sVt[(d4 * 4 + 0) * 64 + col] = v4.x;
            sVt[(d4 * 4 + 1) * 64 + col] = v4.y;
            sVt[(d4 * 4 + 2) * 64 + col] = v4.z;
            sVt[(d4 * 4 + 3) * 64 + col] = v4.w;
        }
        __syncthreads();

        ull S2[4][4];
#pragma unroll
        for (int i = 0; i < 4; i++)
#pragma unroll
            for (int j = 0; j < 4; j++) S2[i][j] = 0ull;

#pragma unroll
        for (int d4 = 0; d4 < 16; d4++) {
            ull ql[4], qh[4], kl[4], kh[4];
#pragma unroll
            for (int i = 0; i < 4; i++)
                LDSV2(ql[i], qh[i], qB + (unsigned)((ty + 16 * i) * 16 + (d4 ^ ty)) * 16u);
#pragma unroll
            for (int j = 0; j < 4; j++)
                LDSV2(kl[j], kh[j], kB + (unsigned)((tx + 16 * j) * 16 + (d4 ^ tx)) * 16u);
#pragma unroll
            for (int i = 0; i < 4; i++)
#pragma unroll
                for (int j = 0; j < 4; j++) {
                    FMA2(S2[i][j], ql[i], kl[j]);
                    FMA2(S2[i][j], qh[i], kh[j]);
                }
        }
        __syncthreads();

        const bool diag = (kt == nt - 1);
        float* sS = (float*)sKS;
#pragma unroll
        for (int i = 0; i < 4; i++) {
            const int r = ty + 16 * i;
#pragma unroll
            for (int j = 0; j < 4; j++) {
                const int c = tx + 16 * j;
                float lo, hi;
                UNPACK2(lo, hi, S2[i][j]);
                const float dv = lo + hi;
                const float den = fmaxf(fmaf(-2.0f, dv, 2.01f), 1e-6f);
                float rc; RCPA(rc, den);
                float w = dv * dv * rc;
                if (diag && c > r) w = 0.0f;
                accD[i] += w;
                sS[r * 64 + c] = w;
            }
        }
        __syncthreads();

#pragma unroll
        for (int s4 = 0; s4 < 16; s4++) {
            const unsigned s = (unsigned)(s4 * 4);
            ull wl[4], wh[4];
#pragma unroll
            for (int i = 0; i < 4; i++)
                LDSV2(wl[i], wh[i], kB + ((unsigned)((ty + 16 * i) * 64) + s) * 4u);
            ull vl[4], vh[4];
#pragma unroll
            for (int dl = 0; dl < 4; dl++)
                LDSV2(vl[dl], vh[dl], vB + ((unsigned)((tx * 4 + dl) * 64) + (s ^ ew)) * 4u);
#pragma unroll
            for (int i = 0; i < 4; i++)
#pragma unroll
                for (int dl = 0; dl < 4; dl++) {
                    FMA2(accO[i][dl], wl[i], vl[dl]);
                    FMA2(accO[i][dl], wh[i], vh[dl]);
                }
        }
    }

#pragma unroll
    for (int i = 0; i < 4; i++) {
        float d = accD[i];
        d += __shfl_xor_sync(0xffffffffu, d, 8);
        d += __shfl_xor_sync(0xffffffffu, d, 4);
        d += __shfl_xor_sync(0xffffffffu, d, 2);
        d += __shfl_xor_sync(0xffffffffu, d, 1);
        accD[i] = d + 1e-6f;
    }

    float* ob = attn + ((size_t)(b * TQ) + q0) * DQ + h * HDQ + tx * 4;
#pragma unroll
    for (int i = 0; i < 4; i++) {
        const int r = ty + 16 * i;
        float inv; RCPA(inv, accD[i]);
        float o[4];
#pragma unroll
        for (int dl = 0; dl < 4; dl++) {
            float lo, hi;
            UNPACK2(lo, hi, accO[i][dl]);
            o[dl] = (lo + hi) * inv;
        }
        *(float4*)(ob + (size_t)r * DQ) = make_float4(o[0], o[1], o[2], o[3]);
    }
}

// ---------------------------------------------------------------------------
// kernel_launch
// ---------------------------------------------------------------------------
extern "C" void kernel_launch(void* const* d_in, const int* in_sizes, int n_in,
                              void* d_out, int out_size) {
    (void)in_sizes; (void)n_in; (void)out_size;
    const float* x    = (const float*)d_in[0];   // [B,T,D]
    const float* Wqkv = (const float*)d_in[1];   // [3D, D]
    const float* Wout = (const float*)d_in[2];   // [D, D]
    float* out = (float*)d_out;                  // [B,T,D]

    void* p_qkv_v = nullptr;
    void* p_att_v = nullptr;
    cudaGetSymbolAddress(&p_qkv_v, g_qkv);
    cudaGetSymbolAddress(&p_att_v, g_att);
    float* p_qkv = (float*)p_qkv_v;
    float* p_att = (float*)p_att_v;

    const int M = BQ * TQ;  // 4096

    // 1) qkv = x @ Wqkv^T : [4096,3072]  (bf16x3 tensor-core)
    gemm_bf16x3<<<dim3(ROW3 / 128, M / 128), 256>>>(x, Wqkv, p_qkv, M, ROW3, DQ);

    // 2) L2-normalize q,k per head in place
    normalize_qk<<<(2 * M * HQ) / 8, 256>>>(p_qkv);

    // 3) causal yat attention -> g_att [B,T,D]
    yat_attn<<<dim3(TQ / 64, HQ, BQ), 256>>>(p_qkv, p_att);

    // 4) out = att @ Wout^T : [4096,1024]  (bf16x3 tensor-core)
    gemm_bf16x3<<<dim3(DQ / 128, M / 128), 256>>>(p_att, Wout, out, M, DQ, DQ);
}

// round 5
// speedup vs baseline: 4.1586x; 1.4646x over previous
#include <cuda_runtime.h>
#include <cstddef>
#include <cstdint>

// Problem constants (fixed by setup_inputs)
#define BQ   2
#define TQ   2048
#define DQ   1024
#define HQ   16
#define HDQ  64
#define ROW3 3072   // 3*DQ

// Scratch (device globals — no allocation allowed)
__device__ float g_qkv[(size_t)BQ * TQ * ROW3];  // [B*T, 3D]; q|k|v, normalized in-place
__device__ float g_att[(size_t)BQ * TQ * DQ];    // attention output in [B,T,D] layout

typedef unsigned long long ull;

__device__ __forceinline__ unsigned su32(const void* p) {
    return (unsigned)__cvta_generic_to_shared(p);
}

// ---------------------------------------------------------------------------
// Warp-level tensor-core primitives (base-target PTX: works on compute_103)
// ---------------------------------------------------------------------------
#define LDSM_X4(r0, r1, r2, r3, addr) \
    asm volatile("ldmatrix.sync.aligned.m8n8.x4.shared.b16 {%0,%1,%2,%3}, [%4];" \
        : "=r"(r0), "=r"(r1), "=r"(r2), "=r"(r3) : "r"(addr))

#define LDSM_X4_T(r0, r1, r2, r3, addr) \
    asm volatile("ldmatrix.sync.aligned.m8n8.x4.trans.shared.b16 {%0,%1,%2,%3}, [%4];" \
        : "=r"(r0), "=r"(r1), "=r"(r2), "=r"(r3) : "r"(addr))

#define MMA16816(c, a, b0, b1) \
    asm volatile("mma.sync.aligned.m16n8k16.row.col.f32.bf16.bf16.f32 " \
        "{%0,%1,%2,%3}, {%4,%5,%6,%7}, {%8,%9}, {%0,%1,%2,%3};" \
        : "+f"((c)[0]), "+f"((c)[1]), "+f"((c)[2]), "+f"((c)[3]) \
        : "r"((a)[0]), "r"((a)[1]), "r"((a)[2]), "r"((a)[3]), "r"(b0), "r"(b1))

// Split a float4 into packed bf16x2 hi and lo (lo = rounded residual)
__device__ __forceinline__ void split4(float4 f, uint32_t& h0, uint32_t& h1,
                                       uint32_t& l0, uint32_t& l1) {
    asm("cvt.rn.bf16x2.f32 %0, %1, %2;" : "=r"(h0) : "f"(f.y), "f"(f.x));
    asm("cvt.rn.bf16x2.f32 %0, %1, %2;" : "=r"(h1) : "f"(f.w), "f"(f.z));
    float fx = __uint_as_float(h0 << 16);
    float fy = __uint_as_float(h0 & 0xffff0000u);
    float fz = __uint_as_float(h1 << 16);
    float fw = __uint_as_float(h1 & 0xffff0000u);
    asm("cvt.rn.bf16x2.f32 %0, %1, %2;" : "=r"(l0) : "f"(f.y - fy), "f"(f.x - fx));
    asm("cvt.rn.bf16x2.f32 %0, %1, %2;" : "=r"(l1) : "f"(f.w - fw), "f"(f.z - fz));
}

// Pack two fp32 into bf16x2 hi + residual lo (low half = first arg)
__device__ __forceinline__ void packsplit2(float w0, float w1, uint32_t& h, uint32_t& l) {
    asm("cvt.rn.bf16x2.f32 %0, %1, %2;" : "=r"(h) : "f"(w1), "f"(w0));
    float r0 = w0 - __uint_as_float(h << 16);
    float r1 = w1 - __uint_as_float(h & 0xffff0000u);
    asm("cvt.rn.bf16x2.f32 %0, %1, %2;" : "=r"(l) : "f"(r1), "f"(r0));
}

#define STSV2(addr, v0, v1) \
    asm volatile("st.shared.v2.b32 [%0], {%1,%2};" :: "r"(addr), "r"(v0), "r"(v1) : "memory")

#define RCPA(d, a) \
    asm("rcp.approx.f32 %0, %1;" : "=f"(d) : "f"(a))

// ---------------------------------------------------------------------------
// bf16x3 emulated-fp32 GEMM:  C[M,N] = A[M,K] @ B[N,K]^T  (fp32 in/out)
// (unchanged from R4 — proven: rel_err 1.2e-5, tensor pipe 30%)
// ---------------------------------------------------------------------------
#define RSTR 80   // bytes per smem row (64B data + 16B pad)

__global__ __launch_bounds__(256) void gemm_bf16x3(const float* __restrict__ A,
                                                   const float* __restrict__ B,
                                                   float* __restrict__ C,
                                                   int M, int N, int K) {
    __shared__ __align__(16) unsigned char sAh[128 * RSTR];
    __shared__ __align__(16) unsigned char sAl[128 * RSTR];
    __shared__ __align__(16) unsigned char sBh[128 * RSTR];
    __shared__ __align__(16) unsigned char sBl[128 * RSTR];

    const int tid  = threadIdx.x;
    const int wid  = tid >> 5;
    const int lane = tid & 31;
    const int wm   = wid & 3;
    const int wn   = wid >> 2;

    const int row0 = blockIdx.y * 128;
    const int col0 = blockIdx.x * 128;

    const int lr = (lane & 7) + ((lane >> 3) & 1) * 8;
    const int lk = (lane >> 4) * 16;

    const unsigned aH = su32(sAh), aL = su32(sAl);
    const unsigned bH = su32(sBh), bL = su32(sBl);

    const int prow = tid >> 1;
    const int pf4  = (tid & 1) * 4;
    const float* Ap = A + (size_t)(row0 + prow) * K + pf4 * 4;
    const float* Bp = B + (size_t)(col0 + prow) * K + pf4 * 4;

    float acc[2][8][4];
#pragma unroll
    for (int mt = 0; mt < 2; mt++)
#pragma unroll
        for (int nt = 0; nt < 8; nt++)
#pragma unroll
            for (int e = 0; e < 4; e++) acc[mt][nt][e] = 0.0f;

    float4 av[4], bv[4];
#pragma unroll
    for (int j = 0; j < 4; j++) {
        av[j] = *(const float4*)(Ap + j * 4);
        bv[j] = *(const float4*)(Bp + j * 4);
    }

    const int nchunks = K / 32;
    for (int c = 0; c < nchunks; c++) {
        __syncthreads();
#pragma unroll
        for (int j = 0; j < 4; j++) {
            uint32_t h0, h1, l0, l1;
            const unsigned off = (unsigned)(prow * RSTR + (pf4 + j) * 8);
            split4(av[j], h0, h1, l0, l1);
            STSV2(aH + off, h0, h1);
            STSV2(aL + off, l0, l1);
            split4(bv[j], h0, h1, l0, l1);
            STSV2(bH + off, h0, h1);
            STSV2(bL + off, l0, l1);
        }
        __syncthreads();

        if (c + 1 < nchunks) {
            const int k0 = (c + 1) * 32;
#pragma unroll
            for (int j = 0; j < 4; j++) {
                av[j] = *(const float4*)(Ap + k0 + j * 4);
                bv[j] = *(const float4*)(Bp + k0 + j * 4);
            }
        }

#pragma unroll
        for (int ks = 0; ks < 2; ks++) {
            const unsigned kb = (unsigned)(ks * 32 + lk);
            uint32_t ah[2][4], al[2][4];
#pragma unroll
            for (int mt = 0; mt < 2; mt++) {
                const unsigned ro = (unsigned)((wm * 32 + mt * 16 + lr) * RSTR) + kb;
                LDSM_X4(ah[mt][0], ah[mt][1], ah[mt][2], ah[mt][3], aH + ro);
                LDSM_X4(al[mt][0], al[mt][1], al[mt][2], al[mt][3], aL + ro);
            }
            uint32_t bh[4][4], bl[4][4];
#pragma unroll
            for (int np = 0; np < 4; np++) {
                const unsigned ro = (unsigned)((wn * 64 + np * 16 + lr) * RSTR) + kb;
                LDSM_X4(bh[np][0], bh[np][1], bh[np][2], bh[np][3], bH + ro);
                LDSM_X4(bl[np][0], bl[np][1], bl[np][2], bl[np][3], bL + ro);
            }
#pragma unroll
            for (int mt = 0; mt < 2; mt++)
#pragma unroll
                for (int nt = 0; nt < 8; nt++) {
                    const int np = nt >> 1, sel = nt & 1;
                    MMA16816(acc[mt][nt], ah[mt], bh[np][sel], bh[np][sel + 2]);
                    MMA16816(acc[mt][nt], ah[mt], bl[np][sel], bl[np][sel + 2]);
                    MMA16816(acc[mt][nt], al[mt], bh[np][sel], bh[np][sel + 2]);
                }
        }
    }

    const int er = lane >> 2;
    const int ec = (lane & 3) * 2;
#pragma unroll
    for (int mt = 0; mt < 2; mt++) {
        const int row = row0 + wm * 32 + mt * 16 + er;
#pragma unroll
        for (int nt = 0; nt < 8; nt++) {
            const int col = col0 + wn * 64 + nt * 8 + ec;
            *(float2*)(C + (size_t)row * N + col) =
                make_float2(acc[mt][nt][0], acc[mt][nt][1]);
            *(float2*)(C + (size_t)(row + 8) * N + col) =
                make_float2(acc[mt][nt][2], acc[mt][nt][3]);
        }
    }
}

// ---------------------------------------------------------------------------
// L2-normalize q and k head rows of g_qkv in place. One warp per 64-elem row.
// ---------------------------------------------------------------------------
__global__ __launch_bounds__(256) void normalize_qk(float* __restrict__ qkv) {
    const int gw   = (blockIdx.x * blockDim.x + threadIdx.x) >> 5;
    const int lane = threadIdx.x & 31;
    const int h    = gw & 15;
    const int bt   = (gw >> 4) & (BQ * TQ - 1);
    const int part = gw >> 16;     // 0 = q, 1 = k

    float* p = qkv + (size_t)bt * ROW3 + part * DQ + h * HDQ;
    float v0 = p[lane];
    float v1 = p[lane + 32];
    float ss = v0 * v0 + v1 * v1;
#pragma unroll
    for (int m = 16; m; m >>= 1) ss += __shfl_xor_sync(0xffffffffu, ss, m);
    const float s = 1.0f / fmaxf(sqrtf(ss), 1e-12f);
    p[lane]      = v0 * s;
    p[lane + 32] = v1 * s;
}

// ---------------------------------------------------------------------------
// Causal yat attention on tensor cores (bf16x3 mma.sync).
// CTA = (q-tile 64, head, batch), 128 threads (4 warps x 16 query rows).
// Q A-fragments live in registers for the whole CTA; K/V bf16 hi/lo tiles in
// smem (144B row stride -> conflict-free ldmatrix). S C-fragments are
// transformed to w in-register and re-packed as A-fragments for w@V; V loaded
// via ldmatrix.x4.trans. den accumulated in fp32 alongside.
// ---------------------------------------------------------------------------
#define VR 144

__global__ __launch_bounds__(128) void yat_attn_tc(const float* __restrict__ qkv,
                                                   float* __restrict__ attn) {
    __shared__ __align__(16) unsigned char sKH[64 * VR];
    __shared__ __align__(16) unsigned char sKL[64 * VR];
    __shared__ __align__(16) unsigned char sVH[64 * VR];
    __shared__ __align__(16) unsigned char sVL[64 * VR];

    const int tid  = threadIdx.x;
    const int wid  = tid >> 5;
    const int lane = tid & 31;

    const int qt = blockIdx.x;
    const int h  = blockIdx.y;
    const int b  = blockIdx.z;
    const int q0 = qt * 64;

    const int lr = (lane & 7) + ((lane >> 3) & 1) * 8;
    const int lk = (lane >> 4) * 16;

    const unsigned kH = su32(sKH), kL = su32(sKL);
    const unsigned vH = su32(sVH), vL = su32(sVL);

    // ---- stage Q through K smem, pull A-fragments into registers ----
    {
        const float* qb = qkv + ((size_t)(b * TQ) + q0) * ROW3 + h * HDQ;
#pragma unroll
        for (int j = 0; j < 8; j++) {
            const int idx = tid + 128 * j;
            const int r = idx >> 4, c = idx & 15;
            float4 f = *(const float4*)(qb + (size_t)r * ROW3 + c * 4);
            uint32_t h0, h1, l0, l1;
            split4(f, h0, h1, l0, l1);
            const unsigned off = (unsigned)(r * VR + c * 8);
            STSV2(kH + off, h0, h1);
            STSV2(kL + off, l0, l1);
        }
    }
    __syncthreads();
    uint32_t qfh[4][4], qfl[4][4];
#pragma unroll
    for (int kc = 0; kc < 4; kc++) {
        const unsigned ro = (unsigned)((wid * 16 + lr) * VR + kc * 32 + lk);
        LDSM_X4(qfh[kc][0], qfh[kc][1], qfh[kc][2], qfh[kc][3], kH + ro);
        LDSM_X4(qfl[kc][0], qfl[kc][1], qfl[kc][2], qfl[kc][3], kL + ro);
    }

    float accO[8][4];
#pragma unroll
    for (int nt = 0; nt < 8; nt++)
#pragma unroll
        for (int e = 0; e < 4; e++) accO[nt][e] = 0.0f;
    float dsum0 = 0.0f, dsum1 = 0.0f;

    const int qg0 = q0 + wid * 16 + (lane >> 2);   // this thread's query row (er)

    for (int kt = 0; kt <= qt; kt++) {
        __syncthreads();   // prior iter LDSM (and Q-frag pull) done
        // ---- load K, V tiles (split bf16 hi/lo) ----
        const float* kb = qkv + ((size_t)(b * TQ) + kt * 64) * ROW3 + DQ + h * HDQ;
#pragma unroll
        for (int j = 0; j < 8; j++) {
            const int idx = tid + 128 * j;
            const int r = idx >> 4, c = idx & 15;
            const unsigned off = (unsigned)(r * VR + c * 8);
            float4 f = *(const float4*)(kb + (size_t)r * ROW3 + c * 4);
            uint32_t h0, h1, l0, l1;
            split4(f, h0, h1, l0, l1);
            STSV2(kH + off, h0, h1);
            STSV2(kL + off, l0, l1);
            float4 fv = *(const float4*)(kb + DQ + (size_t)r * ROW3 + c * 4);
            split4(fv, h0, h1, l0, l1);
            STSV2(vH + off, h0, h1);
            STSV2(vL + off, l0, l1);
        }
        __syncthreads();

        // ---- S = Qn Kn^T (bf16x3) ----
        float sf[8][4];
#pragma unroll
        for (int nt = 0; nt < 8; nt++)
#pragma unroll
            for (int e = 0; e < 4; e++) sf[nt][e] = 0.0f;

#pragma unroll
        for (int kc = 0; kc < 4; kc++) {
#pragma unroll
            for (int g = 0; g < 4; g++) {
                uint32_t khf[4], klf[4];
                const unsigned ro = (unsigned)((g * 16 + lr) * VR + kc * 32 + lk);
                LDSM_X4(khf[0], khf[1], khf[2], khf[3], kH + ro);
                LDSM_X4(klf[0], klf[1], klf[2], klf[3], kL + ro);
                MMA16816(sf[2 * g],     qfh[kc], khf[0], khf[2]);
                MMA16816(sf[2 * g],     qfh[kc], klf[0], klf[2]);
                MMA16816(sf[2 * g],     qfl[kc], khf[0], khf[2]);
                MMA16816(sf[2 * g + 1], qfh[kc], khf[1], khf[3]);
                MMA16816(sf[2 * g + 1], qfh[kc], klf[1], klf[3]);
                MMA16816(sf[2 * g + 1], qfl[kc], khf[1], khf[3]);
            }
        }

        // ---- transform to w, mask, den, repack as A-fragments ----
        const bool diag = (kt == qt);
        uint32_t w01h[8], w01l[8], w23h[8], w23l[8];
#pragma unroll
        for (int nt = 0; nt < 8; nt++) {
            float w[4];
#pragma unroll
            for (int e = 0; e < 4; e++) {
                const float d = sf[nt][e];
                const float den = fmaxf(fmaf(-2.0f, d, 2.01f), 1e-6f);
                float rc; RCPA(rc, den);
                w[e] = d * d * rc;
            }
            if (diag) {
                const int kg = kt * 64 + nt * 8 + 2 * (lane & 3);
                if (kg     > qg0)     w[0] = 0.0f;
                if (kg + 1 > qg0)     w[1] = 0.0f;
                if (kg     > qg0 + 8) w[2] = 0.0f;
                if (kg + 1 > qg0 + 8) w[3] = 0.0f;
            }
            dsum0 += w[0] + w[1];
            dsum1 += w[2] + w[3];
            packsplit2(w[0], w[1], w01h[nt], w01l[nt]);
            packsplit2(w[2], w[3], w23h[nt], w23l[nt]);
        }

        // ---- O += w @ V (bf16x3, V via ldmatrix.trans) ----
#pragma unroll
        for (int kc2 = 0; kc2 < 4; kc2++) {
            uint32_t ah[4] = {w01h[2 * kc2], w23h[2 * kc2],
                              w01h[2 * kc2 + 1], w23h[2 * kc2 + 1]};
            uint32_t al[4] = {w01l[2 * kc2], w23l[2 * kc2],
                              w01l[2 * kc2 + 1], w23l[2 * kc2 + 1]};
#pragma unroll
            for (int g = 0; g < 4; g++) {
                uint32_t vhf[4], vlf[4];
                const unsigned ro = (unsigned)((kc2 * 16 + lr) * VR + g * 32 + lk);
                LDSM_X4_T(vhf[0], vhf[1], vhf[2], vhf[3], vH + ro);
                LDSM_X4_T(vlf[0], vlf[1], vlf[2], vlf[3], vL + ro);
                MMA16816(accO[2 * g],     ah, vhf[0], vhf[1]);
                MMA16816(accO[2 * g],     ah, vlf[0], vlf[1]);
                MMA16816(accO[2 * g],     al, vhf[0], vhf[1]);
                MMA16816(accO[2 * g + 1], ah, vhf[2], vhf[3]);
                MMA16816(accO[2 * g + 1], ah, vlf[2], vlf[3]);
                MMA16816(accO[2 * g + 1], al, vhf[2], vhf[3]);
            }
        }
    }

    // ---- epilogue: den reduce over the 4 lanes of each row group, divide ----
    dsum0 += __shfl_xor_sync(0xffffffffu, dsum0, 1);
    dsum0 += __shfl_xor_sync(0xffffffffu, dsum0, 2);
    dsum1 += __shfl_xor_sync(0xffffffffu, dsum1, 1);
    dsum1 += __shfl_xor_sync(0xffffffffu, dsum1, 2);
    float inv0, inv1;
    RCPA(inv0, dsum0 + 1e-6f);
    RCPA(inv1, dsum1 + 1e-6f);

    const size_t rowg = (size_t)(b * TQ) + q0 + wid * 16 + (lane >> 2);
    const int    colb = h * HDQ + 2 * (lane & 3);
#pragma unroll
    for (int nt = 0; nt < 8; nt++) {
        const int col = colb + nt * 8;
        *(float2*)(attn + rowg * DQ + col) =
            make_float2(accO[nt][0] * inv0, accO[nt][1] * inv0);
        *(float2*)(attn + (rowg + 8) * DQ + col) =
            make_float2(accO[nt][2] * inv1, accO[nt][3] * inv1);
    }
}

// ---------------------------------------------------------------------------
// kernel_launch
// ---------------------------------------------------------------------------
extern "C" void kernel_launch(void* const* d_in, const int* in_sizes, int n_in,
                              void* d_out, int out_size) {
    (void)in_sizes; (void)n_in; (void)out_size;
    const float* x    = (const float*)d_in[0];   // [B,T,D]
    const float* Wqkv = (const float*)d_in[1];   // [3D, D]
    const float* Wout = (const float*)d_in[2];   // [D, D]
    float* out = (float*)d_out;                  // [B,T,D]

    void* p_qkv_v = nullptr;
    void* p_att_v = nullptr;
    cudaGetSymbolAddress(&p_qkv_v, g_qkv);
    cudaGetSymbolAddress(&p_att_v, g_att);
    float* p_qkv = (float*)p_qkv_v;
    float* p_att = (float*)p_att_v;

    const int M = BQ * TQ;  // 4096

    // 1) qkv = x @ Wqkv^T : [4096,3072]  (bf16x3 tensor-core)
    gemm_bf16x3<<<dim3(ROW3 / 128, M / 128), 256>>>(x, Wqkv, p_qkv, M, ROW3, DQ);

    // 2) L2-normalize q,k per head in place
    normalize_qk<<<(2 * M * HQ) / 8, 256>>>(p_qkv);

    // 3) causal yat attention -> g_att [B,T,D]  (bf16x3 tensor-core)
    yat_attn_tc<<<dim3(TQ / 64, HQ, BQ), 128>>>(p_qkv, p_att);

    // 4) out = att @ Wout^T : [4096,1024]  (bf16x3 tensor-core)
    gemm_bf16x3<<<dim3(DQ / 128, M / 128), 256>>>(p_att, Wout, out, M, DQ, DQ);
}

// round 6
// speedup vs baseline: 4.3445x; 1.0447x over previous
#include <cuda_runtime.h>
#include <cstddef>
#include <cstdint>

// Problem constants (fixed by setup_inputs)
#define BQ   2
#define TQ   2048
#define DQ   1024
#define HQ   16
#define HDQ  64
#define ROW3 3072   // 3*DQ

// Scratch (device globals — no allocation allowed). u32 = packed bf16x2.
__device__ float    g_qkv[(size_t)BQ * TQ * ROW3];   // fp32 qkv (normalized in place)
__device__ uint32_t g_xh [(size_t)BQ * TQ * DQ / 2]; // x split hi
__device__ uint32_t g_xl [(size_t)BQ * TQ * DQ / 2]; // x split lo
__device__ uint32_t g_w1h[(size_t)ROW3 * DQ / 2];    // Wqkv hi
__device__ uint32_t g_w1l[(size_t)ROW3 * DQ / 2];    // Wqkv lo
__device__ uint32_t g_w2h[(size_t)DQ * DQ / 2];      // Wout hi
__device__ uint32_t g_w2l[(size_t)DQ * DQ / 2];      // Wout lo
__device__ uint32_t g_ah [(size_t)BQ * TQ * DQ / 2]; // attention out hi
__device__ uint32_t g_al [(size_t)BQ * TQ * DQ / 2]; // attention out lo

typedef unsigned long long ull;

__device__ __forceinline__ unsigned su32(const void* p) {
    return (unsigned)__cvta_generic_to_shared(p);
}

// ---------------------------------------------------------------------------
// Warp-level tensor-core + async-copy primitives (base-target PTX)
// ---------------------------------------------------------------------------
#define LDSM_X4(r0, r1, r2, r3, addr) \
    asm volatile("ldmatrix.sync.aligned.m8n8.x4.shared.b16 {%0,%1,%2,%3}, [%4];" \
        : "=r"(r0), "=r"(r1), "=r"(r2), "=r"(r3) : "r"(addr))

#define LDSM_X4_T(r0, r1, r2, r3, addr) \
    asm volatile("ldmatrix.sync.aligned.m8n8.x4.trans.shared.b16 {%0,%1,%2,%3}, [%4];" \
        : "=r"(r0), "=r"(r1), "=r"(r2), "=r"(r3) : "r"(addr))

#define MMA16816(c, a, b0, b1) \
    asm volatile("mma.sync.aligned.m16n8k16.row.col.f32.bf16.bf16.f32 " \
        "{%0,%1,%2,%3}, {%4,%5,%6,%7}, {%8,%9}, {%0,%1,%2,%3};" \
        : "+f"((c)[0]), "+f"((c)[1]), "+f"((c)[2]), "+f"((c)[3]) \
        : "r"((a)[0]), "r"((a)[1]), "r"((a)[2]), "r"((a)[3]), "r"(b0), "r"(b1))

#define CP16(dst, src) \
    asm volatile("cp.async.cg.shared.global [%0], [%1], 16;" :: "r"(dst), "l"(src))
#define CP_COMMIT() asm volatile("cp.async.commit_group;" ::: "memory")
#define CP_WAIT(n)  asm volatile("cp.async.wait_group %0;" :: "n"(n) : "memory")

// Split a float4 into packed bf16x2 hi and lo (lo = rounded residual)
__device__ __forceinline__ void split4(float4 f, uint32_t& h0, uint32_t& h1,
                                       uint32_t& l0, uint32_t& l1) {
    asm("cvt.rn.bf16x2.f32 %0, %1, %2;" : "=r"(h0) : "f"(f.y), "f"(f.x));
    asm("cvt.rn.bf16x2.f32 %0, %1, %2;" : "=r"(h1) : "f"(f.w), "f"(f.z));
    float fx = __uint_as_float(h0 << 16);
    float fy = __uint_as_float(h0 & 0xffff0000u);
    float fz = __uint_as_float(h1 << 16);
    float fw = __uint_as_float(h1 & 0xffff0000u);
    asm("cvt.rn.bf16x2.f32 %0, %1, %2;" : "=r"(l0) : "f"(f.y - fy), "f"(f.x - fx));
    asm("cvt.rn.bf16x2.f32 %0, %1, %2;" : "=r"(l1) : "f"(f.w - fw), "f"(f.z - fz));
}

// Pack two fp32 into bf16x2 hi + residual lo (low half = first arg)
__device__ __forceinline__ void packsplit2(float w0, float w1, uint32_t& h, uint32_t& l) {
    asm("cvt.rn.bf16x2.f32 %0, %1, %2;" : "=r"(h) : "f"(w1), "f"(w0));
    float r0 = w0 - __uint_as_float(h << 16);
    float r1 = w1 - __uint_as_float(h & 0xffff0000u);
    asm("cvt.rn.bf16x2.f32 %0, %1, %2;" : "=r"(l) : "f"(r1), "f"(r0));
}

#define STSV2(addr, v0, v1) \
    asm volatile("st.shared.v2.b32 [%0], {%1,%2};" :: "r"(addr), "r"(v0), "r"(v1) : "memory")

#define RCPA(d, a) \
    asm("rcp.approx.f32 %0, %1;" : "=f"(d) : "f"(a))

// ---------------------------------------------------------------------------
// Convert: fp32 array -> packed bf16x2 hi/lo arrays (flat, float4 per thread)
// ---------------------------------------------------------------------------
__global__ __launch_bounds__(256) void split_f32(const float* __restrict__ src,
                                                 uint32_t* __restrict__ hi,
                                                 uint32_t* __restrict__ lo, int n4) {
    const int i = blockIdx.x * blockDim.x + threadIdx.x;
    if (i < n4) {
        float4 f = ((const float4*)src)[i];
        uint32_t h0, h1, l0, l1;
        split4(f, h0, h1, l0, l1);
        hi[2 * i] = h0; hi[2 * i + 1] = h1;
        lo[2 * i] = l0; lo[2 * i + 1] = l1;
    }
}

// ---------------------------------------------------------------------------
// Pipelined bf16x3 GEMM: C[M,N] = A[M,K] @ B[N,K]^T, operands pre-split bf16.
// CTA tile 128x128, 8 warps (4x2), BK=32, 3-stage cp.async pipeline,
// 80B-stride smem rows (conflict-free ldmatrix). One syncthreads per chunk.
// ---------------------------------------------------------------------------
#define RSTR 80
#define NSTG 3
#define STG_BYTES 40960         // 4 tiles x 128 rows x 80B
#define OFF_AH 0
#define OFF_AL 10240
#define OFF_BH 20480
#define OFF_BL 30720
#define GEMM_SMEM (NSTG * STG_BYTES)

extern __shared__ unsigned char g_dsm[];

__global__ __launch_bounds__(256) void gemm_bf16_pipe(
    const uint16_t* __restrict__ Ah, const uint16_t* __restrict__ Al,
    const uint16_t* __restrict__ Bh, const uint16_t* __restrict__ Bl,
    float* __restrict__ C, int M, int N, int K) {

    const int tid  = threadIdx.x;
    const int wid  = tid >> 5;
    const int lane = tid & 31;
    const int wm   = wid & 3;
    const int wn   = wid >> 2;

    const int row0 = blockIdx.y * 128;
    const int col0 = blockIdx.x * 128;

    const int lr = (lane & 7) + ((lane >> 3) & 1) * 8;
    const int lk = (lane >> 4) * 16;

    const unsigned sb = su32(g_dsm);

    // producer: 2 segments (16B = 8 bf16) per matrix per thread
    const int r0p = (tid * 2) >> 2,     s0p = (tid * 2) & 3;
    const int r1p = (tid * 2 + 1) >> 2, s1p = (tid * 2 + 1) & 3;

    auto issue = [&](int c) {
        const unsigned base = sb + (unsigned)(c % NSTG) * STG_BYTES;
        const int k0 = c * 32;
        {
            const unsigned d0 = base + (unsigned)(r0p * RSTR + s0p * 16);
            const unsigned d1 = base + (unsigned)(r1p * RSTR + s1p * 16);
            const size_t a0 = (size_t)(row0 + r0p) * K + k0 + s0p * 8;
            const size_t a1 = (size_t)(row0 + r1p) * K + k0 + s1p * 8;
            CP16(d0 + OFF_AH, Ah + a0);
            CP16(d1 + OFF_AH, Ah + a1);
            CP16(d0 + OFF_AL, Al + a0);
            CP16(d1 + OFF_AL, Al + a1);
            const size_t b0 = (size_t)(col0 + r0p) * K + k0 + s0p * 8;
            const size_t b1 = (size_t)(col0 + r1p) * K + k0 + s1p * 8;
            CP16(d0 + OFF_BH, Bh + b0);
            CP16(d1 + OFF_BH, Bh + b1);
            CP16(d0 + OFF_BL, Bl + b0);
            CP16(d1 + OFF_BL, Bl + b1);
        }
    };

    float acc[2][8][4];
#pragma unroll
    for (int mt = 0; mt < 2; mt++)
#pragma unroll
        for (int nt = 0; nt < 8; nt++)
#pragma unroll
            for (int e = 0; e < 4; e++) acc[mt][nt][e] = 0.0f;

    const int nchunks = K / 32;

    // prologue: stages 0..NSTG-2
    issue(0); CP_COMMIT();
    issue(1); CP_COMMIT();

    for (int j = 0; j < nchunks; j++) {
        CP_WAIT(NSTG - 2);     // stage j data arrived (this thread)
        __syncthreads();       // visibility + all threads done computing j-1

        const int nx = j + NSTG - 1;
        if (nx < nchunks) issue(nx);
        CP_COMMIT();           // always commit (keeps group accounting)

        const unsigned base = sb + (unsigned)(j % NSTG) * STG_BYTES;
        const unsigned aH = base + OFF_AH, aL = base + OFF_AL;
        const unsigned bH = base + OFF_BH, bL = base + OFF_BL;

#pragma unroll
        for (int ks = 0; ks < 2; ks++) {
            const unsigned kb = (unsigned)(ks * 32 + lk);
            uint32_t ah[2][4], al[2][4];
#pragma unroll
            for (int mt = 0; mt < 2; mt++) {
                const unsigned ro = (unsigned)((wm * 32 + mt * 16 + lr) * RSTR) + kb;
                LDSM_X4(ah[mt][0], ah[mt][1], ah[mt][2], ah[mt][3], aH + ro);
                LDSM_X4(al[mt][0], al[mt][1], al[mt][2], al[mt][3], aL + ro);
            }
            uint32_t bh[4][4], bl[4][4];
#pragma unroll
            for (int np = 0; np < 4; np++) {
                const unsigned ro = (unsigned)((wn * 64 + np * 16 + lr) * RSTR) + kb;
                LDSM_X4(bh[np][0], bh[np][1], bh[np][2], bh[np][3], bH + ro);
                LDSM_X4(bl[np][0], bl[np][1], bl[np][2], bl[np][3], bL + ro);
            }
#pragma unroll
            for (int mt = 0; mt < 2; mt++)
#pragma unroll
                for (int nt = 0; nt < 8; nt++) {
                    const int np = nt >> 1, sel = nt & 1;
                    MMA16816(acc[mt][nt], ah[mt], bh[np][sel], bh[np][sel + 2]);
                    MMA16816(acc[mt][nt], ah[mt], bl[np][sel], bl[np][sel + 2]);
                    MMA16816(acc[mt][nt], al[mt], bh[np][sel], bh[np][sel + 2]);
                }
        }
    }

    const int er = lane >> 2;
    const int ec = (lane & 3) * 2;
#pragma unroll
    for (int mt = 0; mt < 2; mt++) {
        const int row = row0 + wm * 32 + mt * 16 + er;
#pragma unroll
        for (int nt = 0; nt < 8; nt++) {
            const int col = col0 + wn * 64 + nt * 8 + ec;
            *(float2*)(C + (size_t)row * N + col) =
                make_float2(acc[mt][nt][0], acc[mt][nt][1]);
            *(float2*)(C + (size_t)(row + 8) * N + col) =
                make_float2(acc[mt][nt][2], acc[mt][nt][3]);
        }
    }
}

// ---------------------------------------------------------------------------
// L2-normalize q and k head rows of g_qkv in place. One warp per 64-elem row.
// ---------------------------------------------------------------------------
__global__ __launch_bounds__(256) void normalize_qk(float* __restrict__ qkv) {
    const int gw   = (blockIdx.x * blockDim.x + threadIdx.x) >> 5;
    const int lane = threadIdx.x & 31;
    const int h    = gw & 15;
    const int bt   = (gw >> 4) & (BQ * TQ - 1);
    const int part = gw >> 16;     // 0 = q, 1 = k

    float* p = qkv + (size_t)bt * ROW3 + part * DQ + h * HDQ;
    float v0 = p[lane];
    float v1 = p[lane + 32];
    float ss = v0 * v0 + v1 * v1;
#pragma unroll
    for (int m = 16; m; m >>= 1) ss += __shfl_xor_sync(0xffffffffu, ss, m);
    const float s = 1.0f / fmaxf(sqrtf(ss), 1e-12f);
    p[lane]      = v0 * s;
    p[lane + 32] = v1 * s;
}

// ---------------------------------------------------------------------------
// Causal yat attention on tensor cores (bf16x3 mma.sync). Epilogue writes
// pre-split bf16 hi/lo (feeds the out-proj GEMM directly).
// ---------------------------------------------------------------------------
#define VR 144

__global__ __launch_bounds__(128) void yat_attn_tc(const float* __restrict__ qkv,
                                                   uint32_t* __restrict__ ath,
                                                   uint32_t* __restrict__ atl) {
    __shared__ __align__(16) unsigned char sKH[64 * VR];
    __shared__ __align__(16) unsigned char sKL[64 * VR];
    __shared__ __align__(16) unsigned char sVH[64 * VR];
    __shared__ __align__(16) unsigned char sVL[64 * VR];

    const int tid  = threadIdx.x;
    const int wid  = tid >> 5;
    const int lane = tid & 31;

    const int qt = blockIdx.x;
    const int h  = blockIdx.y;
    const int b  = blockIdx.z;
    const int q0 = qt * 64;

    const int lr = (lane & 7) + ((lane >> 3) & 1) * 8;
    const int lk = (lane >> 4) * 16;

    const unsigned kH = su32(sKH), kL = su32(sKL);
    const unsigned vH = su32(sVH), vL = su32(sVL);

    // ---- stage Q through K smem, pull A-fragments into registers ----
    {
        const float* qb = qkv + ((size_t)(b * TQ) + q0) * ROW3 + h * HDQ;
#pragma unroll
        for (int j = 0; j < 8; j++) {
            const int idx = tid + 128 * j;
            const int r = idx >> 4, c = idx & 15;
            float4 f = *(const float4*)(qb + (size_t)r * ROW3 + c * 4);
            uint32_t h0, h1, l0, l1;
            split4(f, h0, h1, l0, l1);
            const unsigned off = (unsigned)(r * VR + c * 8);
            STSV2(kH + off, h0, h1);
            STSV2(kL + off, l0, l1);
        }
    }
    __syncthreads();
    uint32_t qfh[4][4], qfl[4][4];
#pragma unroll
    for (int kc = 0; kc < 4; kc++) {
        const unsigned ro = (unsigned)((wid * 16 + lr) * VR + kc * 32 + lk);
        LDSM_X4(qfh[kc][0], qfh[kc][1], qfh[kc][2], qfh[kc][3], kH + ro);
        LDSM_X4(qfl[kc][0], qfl[kc][1], qfl[kc][2], qfl[kc][3], kL + ro);
    }

    float accO[8][4];
#pragma unroll
    for (int nt = 0; nt < 8; nt++)
#pragma unroll
        for (int e = 0; e < 4; e++) accO[nt][e] = 0.0f;
    float dsum0 = 0.0f, dsum1 = 0.0f;

    const int qg0 = q0 + wid * 16 + (lane >> 2);

    for (int kt = 0; kt <= qt; kt++) {
        __syncthreads();
        const float* kb = qkv + ((size_t)(b * TQ) + kt * 64) * ROW3 + DQ + h * HDQ;
#pragma unroll
        for (int j = 0; j < 8; j++) {
            const int idx = tid + 128 * j;
            const int r = idx >> 4, c = idx & 15;
            const unsigned off = (unsigned)(r * VR + c * 8);
            float4 f = *(const float4*)(kb + (size_t)r * ROW3 + c * 4);
            uint32_t h0, h1, l0, l1;
            split4(f, h0, h1, l0, l1);
            STSV2(kH + off, h0, h1);
            STSV2(kL + off, l0, l1);
            float4 fv = *(const float4*)(kb + DQ + (size_t)r * ROW3 + c * 4);
            split4(fv, h0, h1, l0, l1);
            STSV2(vH + off, h0, h1);
            STSV2(vL + off, l0, l1);
        }
        __syncthreads();

        // ---- S = Qn Kn^T (bf16x3) ----
        float sf[8][4];
#pragma unroll
        for (int nt = 0; nt < 8; nt++)
#pragma unroll
            for (int e = 0; e < 4; e++) sf[nt][e] = 0.0f;

#pragma unroll
        for (int kc = 0; kc < 4; kc++) {
#pragma unroll
            for (int g = 0; g < 4; g++) {
                uint32_t khf[4], klf[4];
                const unsigned ro = (unsigned)((g * 16 + lr) * VR + kc * 32 + lk);
                LDSM_X4(khf[0], khf[1], khf[2], khf[3], kH + ro);
                LDSM_X4(klf[0], klf[1], klf[2], klf[3], kL + ro);
                MMA16816(sf[2 * g],     qfh[kc], khf[0], khf[2]);
                MMA16816(sf[2 * g],     qfh[kc], klf[0], klf[2]);
                MMA16816(sf[2 * g],     qfl[kc], khf[0], khf[2]);
                MMA16816(sf[2 * g + 1], qfh[kc], khf[1], khf[3]);
                MMA16816(sf[2 * g + 1], qfh[kc], klf[1], klf[3]);
                MMA16816(sf[2 * g + 1], qfl[kc], khf[1], khf[3]);
            }
        }

        // ---- transform to w, mask, den, repack as A-fragments ----
        const bool diag = (kt == qt);
        uint32_t w01h[8], w01l[8], w23h[8], w23l[8];
#pragma unroll
        for (int nt = 0; nt < 8; nt++) {
            float w[4];
#pragma unroll
            for (int e = 0; e < 4; e++) {
                const float d = sf[nt][e];
                const float den = fmaxf(fmaf(-2.0f, d, 2.01f), 1e-6f);
                float rc; RCPA(rc, den);
                w[e] = d * d * rc;
            }
            if (diag) {
                const int kg = kt * 64 + nt * 8 + 2 * (lane & 3);
                if (kg     > qg0)     w[0] = 0.0f;
                if (kg + 1 > qg0)     w[1] = 0.0f;
                if (kg     > qg0 + 8) w[2] = 0.0f;
                if (kg + 1 > qg0 + 8) w[3] = 0.0f;
            }
            dsum0 += w[0] + w[1];
            dsum1 += w[2] + w[3];
            packsplit2(w[0], w[1], w01h[nt], w01l[nt]);
            packsplit2(w[2], w[3], w23h[nt], w23l[nt]);
        }

        // ---- O += w @ V (bf16x3, V via ldmatrix.trans) ----
#pragma unroll
        for (int kc2 = 0; kc2 < 4; kc2++) {
            uint32_t ah[4] = {w01h[2 * kc2], w23h[2 * kc2],
                              w01h[2 * kc2 + 1], w23h[2 * kc2 + 1]};
            uint32_t al[4] = {w01l[2 * kc2], w23l[2 * kc2],
                              w01l[2 * kc2 + 1], w23l[2 * kc2 + 1]};
#pragma unroll
            for (int g = 0; g < 4; g++) {
                uint32_t vhf[4], vlf[4];
                const unsigned ro = (unsigned)((kc2 * 16 + lr) * VR + g * 32 + lk);
                LDSM_X4_T(vhf[0], vhf[1], vhf[2], vhf[3], vH + ro);
                LDSM_X4_T(vlf[0], vlf[1], vlf[2], vlf[3], vL + ro);
                MMA16816(accO[2 * g],     ah, vhf[0], vhf[1]);
                MMA16816(accO[2 * g],     ah, vlf[0], vlf[1]);
                MMA16816(accO[2 * g],     al, vhf[0], vhf[1]);
                MMA16816(accO[2 * g + 1], ah, vhf[2], vhf[3]);
                MMA16816(accO[2 * g + 1], ah, vlf[2], vlf[3]);
                MMA16816(accO[2 * g + 1], al, vhf[2], vhf[3]);
            }
        }
    }

    // ---- epilogue: reduce den, divide, write SPLIT bf16 ----
    dsum0 += __shfl_xor_sync(0xffffffffu, dsum0, 1);
    dsum0 += __shfl_xor_sync(0xffffffffu, dsum0, 2);
    dsum1 += __shfl_xor_sync(0xffffffffu, dsum1, 1);
    dsum1 += __shfl_xor_sync(0xffffffffu, dsum1, 2);
    float inv0, inv1;
    RCPA(inv0, dsum0 + 1e-6f);
    RCPA(inv1, dsum1 + 1e-6f);

    const size_t rowg  = (size_t)(b * TQ) + q0 + wid * 16 + (lane >> 2);
    const int    colb2 = h * (HDQ / 2) + (lane & 3);  // u32 (bf16-pair) index
#pragma unroll
    for (int nt = 0; nt < 8; nt++) {
        uint32_t hh, ll;
        packsplit2(accO[nt][0] * inv0, accO[nt][1] * inv0, hh, ll);
        ath[rowg * (DQ / 2) + colb2 + nt * 4] = hh;
        atl[rowg * (DQ / 2) + colb2 + nt * 4] = ll;
        packsplit2(accO[nt][2] * inv1, accO[nt][3] * inv1, hh, ll);
        ath[(rowg + 8) * (DQ / 2) + colb2 + nt * 4] = hh;
        atl[(rowg + 8) * (DQ / 2) + colb2 + nt * 4] = ll;
    }
}

// ---------------------------------------------------------------------------
// kernel_launch
// ---------------------------------------------------------------------------
extern "C" void kernel_launch(void* const* d_in, const int* in_sizes, int n_in,
                              void* d_out, int out_size) {
    (void)in_sizes; (void)n_in; (void)out_size;
    const float* x    = (const float*)d_in[0];   // [B,T,D]
    const float* Wqkv = (const float*)d_in[1];   // [3D, D]
    const float* Wout = (const float*)d_in[2];   // [D, D]
    float* out = (float*)d_out;                  // [B,T,D]

    void *p_qkv, *p_xh, *p_xl, *p_w1h, *p_w1l, *p_w2h, *p_w2l, *p_ah, *p_al;
    cudaGetSymbolAddress(&p_qkv, g_qkv);
    cudaGetSymbolAddress(&p_xh, g_xh);   cudaGetSymbolAddress(&p_xl, g_xl);
    cudaGetSymbolAddress(&p_w1h, g_w1h); cudaGetSymbolAddress(&p_w1l, g_w1l);
    cudaGetSymbolAddress(&p_w2h, g_w2h); cudaGetSymbolAddress(&p_w2l, g_w2l);
    cudaGetSymbolAddress(&p_ah, g_ah);   cudaGetSymbolAddress(&p_al, g_al);

    static bool attr_done = false;
    if (!attr_done) {
        cudaFuncSetAttribute(gemm_bf16_pipe,
                             cudaFuncAttributeMaxDynamicSharedMemorySize, GEMM_SMEM);
        attr_done = true;
    }

    const int M = BQ * TQ;  // 4096

    // 0) split inputs to bf16 hi/lo
    split_f32<<<(M * DQ / 4) / 256, 256>>>(x, (uint32_t*)p_xh, (uint32_t*)p_xl, M * DQ / 4);
    split_f32<<<(ROW3 * DQ / 4) / 256, 256>>>(Wqkv, (uint32_t*)p_w1h, (uint32_t*)p_w1l, ROW3 * DQ / 4);
    split_f32<<<(DQ * DQ / 4) / 256, 256>>>(Wout, (uint32_t*)p_w2h, (uint32_t*)p_w2l, DQ * DQ / 4);

    // 1) qkv = x @ Wqkv^T : [4096,3072]  (pipelined bf16x3)
    gemm_bf16_pipe<<<dim3(ROW3 / 128, M / 128), 256, GEMM_SMEM>>>(
        (const uint16_t*)p_xh, (const uint16_t*)p_xl,
        (const uint16_t*)p_w1h, (const uint16_t*)p_w1l,
        (float*)p_qkv, M, ROW3, DQ);

    // 2) L2-normalize q,k per head in place
    normalize_qk<<<(2 * M * HQ) / 8, 256>>>((float*)p_qkv);

    // 3) causal yat attention -> split bf16 att (feeds out-proj directly)
    yat_attn_tc<<<dim3(TQ / 64, HQ, BQ), 128>>>((const float*)p_qkv,
                                                (uint32_t*)p_ah, (uint32_t*)p_al);

    // 4) out = att @ Wout^T : [4096,1024]  (pipelined bf16x3)
    gemm_bf16_pipe<<<dim3(DQ / 128, M / 128), 256, GEMM_SMEM>>>(
        (const uint16_t*)p_ah, (const uint16_t*)p_al,
        (const uint16_t*)p_w2h, (const uint16_t*)p_w2l,
        out, M, DQ, DQ);
}

// round 7
// speedup vs baseline: 4.4913x; 1.0338x over previous
#include <cuda_runtime.h>
#include <cstddef>
#include <cstdint>

// Problem constants (fixed by setup_inputs)
#define BQ   2
#define TQ   2048
#define DQ   1024
#define HQ   16
#define HDQ  64
#define ROW3 3072   // 3*DQ

// Scratch (device globals — no allocation allowed). u32 = packed bf16x2.
__device__ float    g_qkv[(size_t)BQ * TQ * ROW3];   // fp32 qkv (normalized in place)
__device__ uint32_t g_xh [(size_t)BQ * TQ * DQ / 2]; // x split hi
__device__ uint32_t g_xl [(size_t)BQ * TQ * DQ / 2]; // x split lo
__device__ uint32_t g_w1h[(size_t)ROW3 * DQ / 2];    // Wqkv hi
__device__ uint32_t g_w1l[(size_t)ROW3 * DQ / 2];    // Wqkv lo
__device__ uint32_t g_w2h[(size_t)DQ * DQ / 2];      // Wout hi
__device__ uint32_t g_w2l[(size_t)DQ * DQ / 2];      // Wout lo
__device__ uint32_t g_ah [(size_t)BQ * TQ * DQ / 2]; // attention out hi
__device__ uint32_t g_al [(size_t)BQ * TQ * DQ / 2]; // attention out lo

typedef unsigned long long ull;

__device__ __forceinline__ unsigned su32(const void* p) {
    return (unsigned)__cvta_generic_to_shared(p);
}

// ---------------------------------------------------------------------------
// Warp-level tensor-core + async-copy primitives (base-target PTX)
// ---------------------------------------------------------------------------
#define LDSM_X4(r0, r1, r2, r3, addr) \
    asm volatile("ldmatrix.sync.aligned.m8n8.x4.shared.b16 {%0,%1,%2,%3}, [%4];" \
        : "=r"(r0), "=r"(r1), "=r"(r2), "=r"(r3) : "r"(addr))

#define LDSM_X4_T(r0, r1, r2, r3, addr) \
    asm volatile("ldmatrix.sync.aligned.m8n8.x4.trans.shared.b16 {%0,%1,%2,%3}, [%4];" \
        : "=r"(r0), "=r"(r1), "=r"(r2), "=r"(r3) : "r"(addr))

#define MMA16816(c, a, b0, b1) \
    asm volatile("mma.sync.aligned.m16n8k16.row.col.f32.bf16.bf16.f32 " \
        "{%0,%1,%2,%3}, {%4,%5,%6,%7}, {%8,%9}, {%0,%1,%2,%3};" \
        : "+f"((c)[0]), "+f"((c)[1]), "+f"((c)[2]), "+f"((c)[3]) \
        : "r"((a)[0]), "r"((a)[1]), "r"((a)[2]), "r"((a)[3]), "r"(b0), "r"(b1))

#define CP16(dst, src) \
    asm volatile("cp.async.cg.shared.global [%0], [%1], 16;" :: "r"(dst), "l"(src))
#define CP_COMMIT() asm volatile("cp.async.commit_group;" ::: "memory")
#define CP_WAIT(n)  asm volatile("cp.async.wait_group %0;" :: "n"(n) : "memory")

// Split a float4 into packed bf16x2 hi and lo (lo = rounded residual)
__device__ __forceinline__ void split4(float4 f, uint32_t& h0, uint32_t& h1,
                                       uint32_t& l0, uint32_t& l1) {
    asm("cvt.rn.bf16x2.f32 %0, %1, %2;" : "=r"(h0) : "f"(f.y), "f"(f.x));
    asm("cvt.rn.bf16x2.f32 %0, %1, %2;" : "=r"(h1) : "f"(f.w), "f"(f.z));
    float fx = __uint_as_float(h0 << 16);
    float fy = __uint_as_float(h0 & 0xffff0000u);
    float fz = __uint_as_float(h1 << 16);
    float fw = __uint_as_float(h1 & 0xffff0000u);
    asm("cvt.rn.bf16x2.f32 %0, %1, %2;" : "=r"(l0) : "f"(f.y - fy), "f"(f.x - fx));
    asm("cvt.rn.bf16x2.f32 %0, %1, %2;" : "=r"(l1) : "f"(f.w - fw), "f"(f.z - fz));
}

// Pack two fp32 into bf16x2 hi + residual lo (low half = first arg)
__device__ __forceinline__ void packsplit2(float w0, float w1, uint32_t& h, uint32_t& l) {
    asm("cvt.rn.bf16x2.f32 %0, %1, %2;" : "=r"(h) : "f"(w1), "f"(w0));
    float r0 = w0 - __uint_as_float(h << 16);
    float r1 = w1 - __uint_as_float(h & 0xffff0000u);
    asm("cvt.rn.bf16x2.f32 %0, %1, %2;" : "=r"(l) : "f"(r1), "f"(r0));
}

#define STSV2(addr, v0, v1) \
    asm volatile("st.shared.v2.b32 [%0], {%1,%2};" :: "r"(addr), "r"(v0), "r"(v1) : "memory")

#define RCPA(d, a) \
    asm("rcp.approx.f32 %0, %1;" : "=f"(d) : "f"(a))

// ---------------------------------------------------------------------------
// Convert: fp32 array -> packed bf16x2 hi/lo arrays (flat, float4 per thread)
// ---------------------------------------------------------------------------
__global__ __launch_bounds__(256) void split_f32(const float* __restrict__ src,
                                                 uint32_t* __restrict__ hi,
                                                 uint32_t* __restrict__ lo, int n4) {
    const int i = blockIdx.x * blockDim.x + threadIdx.x;
    if (i < n4) {
        float4 f = ((const float4*)src)[i];
        uint32_t h0, h1, l0, l1;
        split4(f, h0, h1, l0, l1);
        hi[2 * i] = h0; hi[2 * i + 1] = h1;
        lo[2 * i] = l0; lo[2 * i + 1] = l1;
    }
}

// ---------------------------------------------------------------------------
// Pipelined bf16x3 GEMM: C[M,N] = A[M,K] @ B[N,K]^T, operands pre-split bf16.
// CTA tile 128x128, 8 warps (4x2), BK=32, 2-stage cp.async double buffer
// (80 KB smem -> 2 CTAs/SM = 16 warps for latency hiding).
// Loop: wait stage j -> syncthreads -> issue j+1 -> compute j.
// ---------------------------------------------------------------------------
#define RSTR 80
#define NSTG 2
#define STG_BYTES 40960         // 4 tiles x 128 rows x 80B
#define OFF_AH 0
#define OFF_AL 10240
#define OFF_BH 20480
#define OFF_BL 30720
#define GEMM_SMEM (NSTG * STG_BYTES)

extern __shared__ unsigned char g_dsm[];

__global__ __launch_bounds__(256, 2) void gemm_bf16_pipe(
    const uint16_t* __restrict__ Ah, const uint16_t* __restrict__ Al,
    const uint16_t* __restrict__ Bh, const uint16_t* __restrict__ Bl,
    float* __restrict__ C, int M, int N, int K) {

    const int tid  = threadIdx.x;
    const int wid  = tid >> 5;
    const int lane = tid & 31;
    const int wm   = wid & 3;
    const int wn   = wid >> 2;

    const int row0 = blockIdx.y * 128;
    const int col0 = blockIdx.x * 128;

    const int lr = (lane & 7) + ((lane >> 3) & 1) * 8;
    const int lk = (lane >> 4) * 16;

    const unsigned sb = su32(g_dsm);

    // producer: 2 segments (16B = 8 bf16) per matrix per thread
    const int r0p = (tid * 2) >> 2,     s0p = (tid * 2) & 3;
    const int r1p = (tid * 2 + 1) >> 2, s1p = (tid * 2 + 1) & 3;

    auto issue = [&](int c) {
        const unsigned base = sb + (unsigned)(c & 1) * STG_BYTES;
        const int k0 = c * 32;
        const unsigned d0 = base + (unsigned)(r0p * RSTR + s0p * 16);
        const unsigned d1 = base + (unsigned)(r1p * RSTR + s1p * 16);
        const size_t a0 = (size_t)(row0 + r0p) * K + k0 + s0p * 8;
        const size_t a1 = (size_t)(row0 + r1p) * K + k0 + s1p * 8;
        CP16(d0 + OFF_AH, Ah + a0);
        CP16(d1 + OFF_AH, Ah + a1);
        CP16(d0 + OFF_AL, Al + a0);
        CP16(d1 + OFF_AL, Al + a1);
        const size_t b0 = (size_t)(col0 + r0p) * K + k0 + s0p * 8;
        const size_t b1 = (size_t)(col0 + r1p) * K + k0 + s1p * 8;
        CP16(d0 + OFF_BH, Bh + b0);
        CP16(d1 + OFF_BH, Bh + b1);
        CP16(d0 + OFF_BL, Bl + b0);
        CP16(d1 + OFF_BL, Bl + b1);
    };

    float acc[2][8][4];
#pragma unroll
    for (int mt = 0; mt < 2; mt++)
#pragma unroll
        for (int nt = 0; nt < 8; nt++)
#pragma unroll
            for (int e = 0; e < 4; e++) acc[mt][nt][e] = 0.0f;

    const int nchunks = K / 32;

    issue(0); CP_COMMIT();

    for (int j = 0; j < nchunks; j++) {
        CP_WAIT(0);            // stage j data arrived (this thread's view)
        __syncthreads();       // all threads done computing j-1 AND see stage j

        if (j + 1 < nchunks) { issue(j + 1); CP_COMMIT(); }

        const unsigned base = sb + (unsigned)(j & 1) * STG_BYTES;
        const unsigned aH = base + OFF_AH, aL = base + OFF_AL;
        const unsigned bH = base + OFF_BH, bL = base + OFF_BL;

#pragma unroll
        for (int ks = 0; ks < 2; ks++) {
            const unsigned kb = (unsigned)(ks * 32 + lk);
            uint32_t ah[2][4], al[2][4];
#pragma unroll
            for (int mt = 0; mt < 2; mt++) {
                const unsigned ro = (unsigned)((wm * 32 + mt * 16 + lr) * RSTR) + kb;
                LDSM_X4(ah[mt][0], ah[mt][1], ah[mt][2], ah[mt][3], aH + ro);
                LDSM_X4(al[mt][0], al[mt][1], al[mt][2], al[mt][3], aL + ro);
            }
            uint32_t bh[4][4], bl[4][4];
#pragma unroll
            for (int np = 0; np < 4; np++) {
                const unsigned ro = (unsigned)((wn * 64 + np * 16 + lr) * RSTR) + kb;
                LDSM_X4(bh[np][0], bh[np][1], bh[np][2], bh[np][3], bH + ro);
                LDSM_X4(bl[np][0], bl[np][1], bl[np][2], bl[np][3], bL + ro);
            }
#pragma unroll
            for (int mt = 0; mt < 2; mt++)
#pragma unroll
                for (int nt = 0; nt < 8; nt++) {
                    const int np = nt >> 1, sel = nt & 1;
                    MMA16816(acc[mt][nt], ah[mt], bh[np][sel], bh[np][sel + 2]);
                    MMA16816(acc[mt][nt], ah[mt], bl[np][sel], bl[np][sel + 2]);
                    MMA16816(acc[mt][nt], al[mt], bh[np][sel], bh[np][sel + 2]);
                }
        }
    }

    const int er = lane >> 2;
    const int ec = (lane & 3) * 2;
#pragma unroll
    for (int mt = 0; mt < 2; mt++) {
        const int row = row0 + wm * 32 + mt * 16 + er;
#pragma unroll
        for (int nt = 0; nt < 8; nt++) {
            const int col = col0 + wn * 64 + nt * 8 + ec;
            *(float2*)(C + (size_t)row * N + col) =
                make_float2(acc[mt][nt][0], acc[mt][nt][1]);
            *(float2*)(C + (size_t)(row + 8) * N + col) =
                make_float2(acc[mt][nt][2], acc[mt][nt][3]);
        }
    }
}

// ---------------------------------------------------------------------------
// L2-normalize q and k head rows of g_qkv in place. One warp per 64-elem row.
// ---------------------------------------------------------------------------
__global__ __launch_bounds__(256) void normalize_qk(float* __restrict__ qkv) {
    const int gw   = (blockIdx.x * blockDim.x + threadIdx.x) >> 5;
    const int lane = threadIdx.x & 31;
    const int h    = gw & 15;
    const int bt   = (gw >> 4) & (BQ * TQ - 1);
    const int part = gw >> 16;     // 0 = q, 1 = k

    float* p = qkv + (size_t)bt * ROW3 + part * DQ + h * HDQ;
    float v0 = p[lane];
    float v1 = p[lane + 32];
    float ss = v0 * v0 + v1 * v1;
#pragma unroll
    for (int m = 16; m; m >>= 1) ss += __shfl_xor_sync(0xffffffffu, ss, m);
    const float s = 1.0f / fmaxf(sqrtf(ss), 1e-12f);
    p[lane]      = v0 * s;
    p[lane + 32] = v1 * s;
}

// ---------------------------------------------------------------------------
// Causal yat attention on tensor cores (bf16x3 mma.sync). Epilogue writes
// pre-split bf16 hi/lo (feeds the out-proj GEMM directly).
// ---------------------------------------------------------------------------
#define VR 144

__global__ __launch_bounds__(128) void yat_attn_tc(const float* __restrict__ qkv,
                                                   uint32_t* __restrict__ ath,
                                                   uint32_t* __restrict__ atl) {
    __shared__ __align__(16) unsigned char sKH[64 * VR];
    __shared__ __align__(16) unsigned char sKL[64 * VR];
    __shared__ __align__(16) unsigned char sVH[64 * VR];
    __shared__ __align__(16) unsigned char sVL[64 * VR];

    const int tid  = threadIdx.x;
    const int wid  = tid >> 5;
    const int lane = tid & 31;

    const int qt = blockIdx.x;
    const int h  = blockIdx.y;
    const int b  = blockIdx.z;
    const int q0 = qt * 64;

    const int lr = (lane & 7) + ((lane >> 3) & 1) * 8;
    const int lk = (lane >> 4) * 16;

    const unsigned kH = su32(sKH), kL = su32(sKL);
    const unsigned vH = su32(sVH), vL = su32(sVL);

    // ---- stage Q through K smem, pull A-fragments into registers ----
    {
        const float* qb = qkv + ((size_t)(b * TQ) + q0) * ROW3 + h * HDQ;
#pragma unroll
        for (int j = 0; j < 8; j++) {
            const int idx = tid + 128 * j;
            const int r = idx >> 4, c = idx & 15;
            float4 f = *(const float4*)(qb + (size_t)r * ROW3 + c * 4);
            uint32_t h0, h1, l0, l1;
            split4(f, h0, h1, l0, l1);
            const unsigned off = (unsigned)(r * VR + c * 8);
            STSV2(kH + off, h0, h1);
            STSV2(kL + off, l0, l1);
        }
    }
    __syncthreads();
    uint32_t qfh[4][4], qfl[4][4];
#pragma unroll
    for (int kc = 0; kc < 4; kc++) {
        const unsigned ro = (unsigned)((wid * 16 + lr) * VR + kc * 32 + lk);
        LDSM_X4(qfh[kc][0], qfh[kc][1], qfh[kc][2], qfh[kc][3], kH + ro);
        LDSM_X4(qfl[kc][0], qfl[kc][1], qfl[kc][2], qfl[kc][3], kL + ro);
    }

    float accO[8][4];
#pragma unroll
    for (int nt = 0; nt < 8; nt++)
#pragma unroll
        for (int e = 0; e < 4; e++) accO[nt][e] = 0.0f;
    float dsum0 = 0.0f, dsum1 = 0.0f;

    const int qg0 = q0 + wid * 16 + (lane >> 2);

    for (int kt = 0; kt <= qt; kt++) {
        __syncthreads();
        const float* kb = qkv + ((size_t)(b * TQ) + kt * 64) * ROW3 + DQ + h * HDQ;
#pragma unroll
        for (int j = 0; j < 8; j++) {
            const int idx = tid + 128 * j;
            const int r = idx >> 4, c = idx & 15;
            const unsigned off = (unsigned)(r * VR + c * 8);
            float4 f = *(const float4*)(kb + (size_t)r * ROW3 + c * 4);
            uint32_t h0, h1, l0, l1;
            split4(f, h0, h1, l0, l1);
            STSV2(kH + off, h0, h1);
            STSV2(kL + off, l0, l1);
            float4 fv = *(const float4*)(kb + DQ + (size_t)r * ROW3 + c * 4);
            split4(fv, h0, h1, l0, l1);
            STSV2(vH + off, h0, h1);
            STSV2(vL + off, l0, l1);
        }
        __syncthreads();

        // ---- S = Qn Kn^T (bf16x3) ----
        float sf[8][4];
#pragma unroll
        for (int nt = 0; nt < 8; nt++)
#pragma unroll
            for (int e = 0; e < 4; e++) sf[nt][e] = 0.0f;

#pragma unroll
        for (int kc = 0; kc < 4; kc++) {
#pragma unroll
            for (int g = 0; g < 4; g++) {
                uint32_t khf[4], klf[4];
                const unsigned ro = (unsigned)((g * 16 + lr) * VR + kc * 32 + lk);
                LDSM_X4(khf[0], khf[1], khf[2], khf[3], kH + ro);
                LDSM_X4(klf[0], klf[1], klf[2], klf[3], kL + ro);
                MMA16816(sf[2 * g],     qfh[kc], khf[0], khf[2]);
                MMA16816(sf[2 * g],     qfh[kc], klf[0], klf[2]);
                MMA16816(sf[2 * g],     qfl[kc], khf[0], khf[2]);
                MMA16816(sf[2 * g + 1], qfh[kc], khf[1], khf[3]);
                MMA16816(sf[2 * g + 1], qfh[kc], klf[1], klf[3]);
                MMA16816(sf[2 * g + 1], qfl[kc], khf[1], khf[3]);
            }
        }

        // ---- transform to w, mask, den, repack as A-fragments ----
        const bool diag = (kt == qt);
        uint32_t w01h[8], w01l[8], w23h[8], w23l[8];
#pragma unroll
        for (int nt = 0; nt < 8; nt++) {
            float w[4];
#pragma unroll
            for (int e = 0; e < 4; e++) {
                const float d = sf[nt][e];
                const float den = fmaxf(fmaf(-2.0f, d, 2.01f), 1e-6f);
                float rc; RCPA(rc, den);
                w[e] = d * d * rc;
            }
            if (diag) {
                const int kg = kt * 64 + nt * 8 + 2 * (lane & 3);
                if (kg     > qg0)     w[0] = 0.0f;
                if (kg + 1 > qg0)     w[1] = 0.0f;
                if (kg     > qg0 + 8) w[2] = 0.0f;
                if (kg + 1 > qg0 + 8) w[3] = 0.0f;
            }
            dsum0 += w[0] + w[1];
            dsum1 += w[2] + w[3];
            packsplit2(w[0], w[1], w01h[nt], w01l[nt]);
            packsplit2(w[2], w[3], w23h[nt], w23l[nt]);
        }

        // ---- O += w @ V (bf16x3, V via ldmatrix.trans) ----
#pragma unroll
        for (int kc2 = 0; kc2 < 4; kc2++) {
            uint32_t ah[4] = {w01h[2 * kc2], w23h[2 * kc2],
                              w01h[2 * kc2 + 1], w23h[2 * kc2 + 1]};
            uint32_t al[4] = {w01l[2 * kc2], w23l[2 * kc2],
                              w01l[2 * kc2 + 1], w23l[2 * kc2 + 1]};
#pragma unroll
            for (int g = 0; g < 4; g++) {
                uint32_t vhf[4], vlf[4];
                const unsigned ro = (unsigned)((kc2 * 16 + lr) * VR + g * 32 + lk);
                LDSM_X4_T(vhf[0], vhf[1], vhf[2], vhf[3], vH + ro);
                LDSM_X4_T(vlf[0], vlf[1], vlf[2], vlf[3], vL + ro);
                MMA16816(accO[2 * g],     ah, vhf[0], vhf[1]);
                MMA16816(accO[2 * g],     ah, vlf[0], vlf[1]);
                MMA16816(accO[2 * g],     al, vhf[0], vhf[1]);
                MMA16816(accO[2 * g + 1], ah, vhf[2], vhf[3]);
                MMA16816(accO[2 * g + 1], ah, vlf[2], vlf[3]);
                MMA16816(accO[2 * g + 1], al, vhf[2], vhf[3]);
            }
        }
    }

    // ---- epilogue: reduce den, divide, write SPLIT bf16 ----
    dsum0 += __shfl_xor_sync(0xffffffffu, dsum0, 1);
    dsum0 += __shfl_xor_sync(0xffffffffu, dsum0, 2);
    dsum1 += __shfl_xor_sync(0xffffffffu, dsum1, 1);
    dsum1 += __shfl_xor_sync(0xffffffffu, dsum1, 2);
    float inv0, inv1;
    RCPA(inv0, dsum0 + 1e-6f);
    RCPA(inv1, dsum1 + 1e-6f);

    const size_t rowg  = (size_t)(b * TQ) + q0 + wid * 16 + (lane >> 2);
    const int    colb2 = h * (HDQ / 2) + (lane & 3);  // u32 (bf16-pair) index
#pragma unroll
    for (int nt = 0; nt < 8; nt++) {
        uint32_t hh, ll;
        packsplit2(accO[nt][0] * inv0, accO[nt][1] * inv0, hh, ll);
        ath[rowg * (DQ / 2) + colb2 + nt * 4] = hh;
        atl[rowg * (DQ / 2) + colb2 + nt * 4] = ll;
        packsplit2(accO[nt][2] * inv1, accO[nt][3] * inv1, hh, ll);
        ath[(rowg + 8) * (DQ / 2) + colb2 + nt * 4] = hh;
        atl[(rowg + 8) * (DQ / 2) + colb2 + nt * 4] = ll;
    }
}

// ---------------------------------------------------------------------------
// kernel_launch
// ---------------------------------------------------------------------------
extern "C" void kernel_launch(void* const* d_in, const int* in_sizes, int n_in,
                              void* d_out, int out_size) {
    (void)in_sizes; (void)n_in; (void)out_size;
    const float* x    = (const float*)d_in[0];   // [B,T,D]
    const float* Wqkv = (const float*)d_in[1];   // [3D, D]
    const float* Wout = (const float*)d_in[2];   // [D, D]
    float* out = (float*)d_out;                  // [B,T,D]

    void *p_qkv, *p_xh, *p_xl, *p_w1h, *p_w1l, *p_w2h, *p_w2l, *p_ah, *p_al;
    cudaGetSymbolAddress(&p_qkv, g_qkv);
    cudaGetSymbolAddress(&p_xh, g_xh);   cudaGetSymbolAddress(&p_xl, g_xl);
    cudaGetSymbolAddress(&p_w1h, g_w1h); cudaGetSymbolAddress(&p_w1l, g_w1l);
    cudaGetSymbolAddress(&p_w2h, g_w2h); cudaGetSymbolAddress(&p_w2l, g_w2l);
    cudaGetSymbolAddress(&p_ah, g_ah);   cudaGetSymbolAddress(&p_al, g_al);

    static bool attr_done = false;
    if (!attr_done) {
        cudaFuncSetAttribute(gemm_bf16_pipe,
                             cudaFuncAttributeMaxDynamicSharedMemorySize, GEMM_SMEM);
        attr_done = true;
    }

    const int M = BQ * TQ;  // 4096

    // 0) split inputs to bf16 hi/lo
    split_f32<<<(M * DQ / 4) / 256, 256>>>(x, (uint32_t*)p_xh, (uint32_t*)p_xl, M * DQ / 4);
    split_f32<<<(ROW3 * DQ / 4) / 256, 256>>>(Wqkv, (uint32_t*)p_w1h, (uint32_t*)p_w1l, ROW3 * DQ / 4);
    split_f32<<<(DQ * DQ / 4) / 256, 256>>>(Wout, (uint32_t*)p_w2h, (uint32_t*)p_w2l, DQ * DQ / 4);

    // 1) qkv = x @ Wqkv^T : [4096,3072]  (pipelined bf16x3, 2 CTAs/SM)
    gemm_bf16_pipe<<<dim3(ROW3 / 128, M / 128), 256, GEMM_SMEM>>>(
        (const uint16_t*)p_xh, (const uint16_t*)p_xl,
        (const uint16_t*)p_w1h, (const uint16_t*)p_w1l,
        (float*)p_qkv, M, ROW3, DQ);

    // 2) L2-normalize q,k per head in place
    normalize_qk<<<(2 * M * HQ) / 8, 256>>>((float*)p_qkv);

    // 3) causal yat attention -> split bf16 att (feeds out-proj directly)
    yat_attn_tc<<<dim3(TQ / 64, HQ, BQ), 128>>>((const float*)p_qkv,
                                                (uint32_t*)p_ah, (uint32_t*)p_al);

    // 4) out = att @ Wout^T : [4096,1024]  (pipelined bf16x3, 2 CTAs/SM)
    gemm_bf16_pipe<<<dim3(DQ / 128, M / 128), 256, GEMM_SMEM>>>(
        (const uint16_t*)p_ah, (const uint16_t*)p_al,
        (const uint16_t*)p_w2h, (const uint16_t*)p_w2l,
        out, M, DQ, DQ);
}

// round 8
// speedup vs baseline: 4.6307x; 1.0310x over previous
#include <cuda_runtime.h>
#include <cstddef>
#include <cstdint>

// Problem constants (fixed by setup_inputs)
#define BQ   2
#define TQ   2048
#define DQ   1024
#define HQ   16
#define HDQ  64
#define ROW3 3072   // 3*DQ

// Scratch (device globals — no allocation allowed). u32 = packed bf16x2.
__device__ float    g_qkv[(size_t)BQ * TQ * ROW3];   // fp32 qkv (normalized in place)
__device__ uint32_t g_xh [(size_t)BQ * TQ * DQ / 2]; // x split hi
__device__ uint32_t g_xl [(size_t)BQ * TQ * DQ / 2]; // x split lo
__device__ uint32_t g_w1h[(size_t)ROW3 * DQ / 2];    // Wqkv hi
__device__ uint32_t g_w1l[(size_t)ROW3 * DQ / 2];    // Wqkv lo
__device__ uint32_t g_w2h[(size_t)DQ * DQ / 2];      // Wout hi
__device__ uint32_t g_w2l[(size_t)DQ * DQ / 2];      // Wout lo
__device__ uint32_t g_ah [(size_t)BQ * TQ * DQ / 2]; // attention out hi
__device__ uint32_t g_al [(size_t)BQ * TQ * DQ / 2]; // attention out lo

typedef unsigned long long ull;

__device__ __forceinline__ unsigned su32(const void* p) {
    return (unsigned)__cvta_generic_to_shared(p);
}

// ---------------------------------------------------------------------------
// Warp-level tensor-core + async-copy primitives (base-target PTX)
// ---------------------------------------------------------------------------
#define LDSM_X4(r0, r1, r2, r3, addr) \
    asm volatile("ldmatrix.sync.aligned.m8n8.x4.shared.b16 {%0,%1,%2,%3}, [%4];" \
        : "=r"(r0), "=r"(r1), "=r"(r2), "=r"(r3) : "r"(addr))

#define LDSM_X4_T(r0, r1, r2, r3, addr) \
    asm volatile("ldmatrix.sync.aligned.m8n8.x4.trans.shared.b16 {%0,%1,%2,%3}, [%4];" \
        : "=r"(r0), "=r"(r1), "=r"(r2), "=r"(r3) : "r"(addr))

#define MMA16816(c, a, b0, b1) \
    asm volatile("mma.sync.aligned.m16n8k16.row.col.f32.bf16.bf16.f32 " \
        "{%0,%1,%2,%3}, {%4,%5,%6,%7}, {%8,%9}, {%0,%1,%2,%3};" \
        : "+f"((c)[0]), "+f"((c)[1]), "+f"((c)[2]), "+f"((c)[3]) \
        : "r"((a)[0]), "r"((a)[1]), "r"((a)[2]), "r"((a)[3]), "r"(b0), "r"(b1))

#define CP16(dst, src) \
    asm volatile("cp.async.cg.shared.global [%0], [%1], 16;" :: "r"(dst), "l"(src))
#define CP_COMMIT() asm volatile("cp.async.commit_group;" ::: "memory")
#define CP_WAIT(n)  asm volatile("cp.async.wait_group %0;" :: "n"(n) : "memory")

// Split a float4 into packed bf16x2 hi and lo (lo = rounded residual)
__device__ __forceinline__ void split4(float4 f, uint32_t& h0, uint32_t& h1,
                                       uint32_t& l0, uint32_t& l1) {
    asm("cvt.rn.bf16x2.f32 %0, %1, %2;" : "=r"(h0) : "f"(f.y), "f"(f.x));
    asm("cvt.rn.bf16x2.f32 %0, %1, %2;" : "=r"(h1) : "f"(f.w), "f"(f.z));
    float fx = __uint_as_float(h0 << 16);
    float fy = __uint_as_float(h0 & 0xffff0000u);
    float fz = __uint_as_float(h1 << 16);
    float fw = __uint_as_float(h1 & 0xffff0000u);
    asm("cvt.rn.bf16x2.f32 %0, %1, %2;" : "=r"(l0) : "f"(f.y - fy), "f"(f.x - fx));
    asm("cvt.rn.bf16x2.f32 %0, %1, %2;" : "=r"(l1) : "f"(f.w - fw), "f"(f.z - fz));
}

// Pack two fp32 into bf16x2 hi + residual lo (low half = first arg)
__device__ __forceinline__ void packsplit2(float w0, float w1, uint32_t& h, uint32_t& l) {
    asm("cvt.rn.bf16x2.f32 %0, %1, %2;" : "=r"(h) : "f"(w1), "f"(w0));
    float r0 = w0 - __uint_as_float(h << 16);
    float r1 = w1 - __uint_as_float(h & 0xffff0000u);
    asm("cvt.rn.bf16x2.f32 %0, %1, %2;" : "=r"(l) : "f"(r1), "f"(r0));
}

#define STSV2(addr, v0, v1) \
    asm volatile("st.shared.v2.b32 [%0], {%1,%2};" :: "r"(addr), "r"(v0), "r"(v1) : "memory")

#define RCPA(d, a) \
    asm("rcp.approx.f32 %0, %1;" : "=f"(d) : "f"(a))

// ---------------------------------------------------------------------------
// Convert: fp32 array -> packed bf16x2 hi/lo arrays (flat, float4 per thread)
// ---------------------------------------------------------------------------
__global__ __launch_bounds__(256) void split_f32(const float* __restrict__ src,
                                                 uint32_t* __restrict__ hi,
                                                 uint32_t* __restrict__ lo, int n4) {
    const int i = blockIdx.x * blockDim.x + threadIdx.x;
    if (i < n4) {
        float4 f = ((const float4*)src)[i];
        uint32_t h0, h1, l0, l1;
        split4(f, h0, h1, l0, l1);
        hi[2 * i] = h0; hi[2 * i + 1] = h1;
        lo[2 * i] = l0; lo[2 * i + 1] = l1;
    }
}

// ---------------------------------------------------------------------------
// Pipelined bf16x3 GEMM: C[M,N] = A[M,K] @ B[N,K]^T, operands pre-split bf16.
// CTA tile 128x128, 8 warps (4x2), BK=32, 2-stage cp.async double buffer,
// 2 CTAs/SM. MMAs issued in 3 passes of 16 independent HMMAs (no acc RAW
// chains inside a pass).
// ---------------------------------------------------------------------------
#define RSTR 80
#define NSTG 2
#define STG_BYTES 40960         // 4 tiles x 128 rows x 80B
#define OFF_AH 0
#define OFF_AL 10240
#define OFF_BH 20480
#define OFF_BL 30720
#define GEMM_SMEM (NSTG * STG_BYTES)

extern __shared__ unsigned char g_dsm[];

__global__ __launch_bounds__(256, 2) void gemm_bf16_pipe(
    const uint16_t* __restrict__ Ah, const uint16_t* __restrict__ Al,
    const uint16_t* __restrict__ Bh, const uint16_t* __restrict__ Bl,
    float* __restrict__ C, int M, int N, int K) {

    const int tid  = threadIdx.x;
    const int wid  = tid >> 5;
    const int lane = tid & 31;
    const int wm   = wid & 3;
    const int wn   = wid >> 2;

    const int row0 = blockIdx.y * 128;
    const int col0 = blockIdx.x * 128;

    const int lr = (lane & 7) + ((lane >> 3) & 1) * 8;
    const int lk = (lane >> 4) * 16;

    const unsigned sb = su32(g_dsm);

    // producer: 2 segments (16B = 8 bf16) per matrix per thread
    const int r0p = (tid * 2) >> 2,     s0p = (tid * 2) & 3;
    const int r1p = (tid * 2 + 1) >> 2, s1p = (tid * 2 + 1) & 3;

    auto issue = [&](int c) {
        const unsigned base = sb + (unsigned)(c & 1) * STG_BYTES;
        const int k0 = c * 32;
        const unsigned d0 = base + (unsigned)(r0p * RSTR + s0p * 16);
        const unsigned d1 = base + (unsigned)(r1p * RSTR + s1p * 16);
        const size_t a0 = (size_t)(row0 + r0p) * K + k0 + s0p * 8;
        const size_t a1 = (size_t)(row0 + r1p) * K + k0 + s1p * 8;
        CP16(d0 + OFF_AH, Ah + a0);
        CP16(d1 + OFF_AH, Ah + a1);
        CP16(d0 + OFF_AL, Al + a0);
        CP16(d1 + OFF_AL, Al + a1);
        const size_t b0 = (size_t)(col0 + r0p) * K + k0 + s0p * 8;
        const size_t b1 = (size_t)(col0 + r1p) * K + k0 + s1p * 8;
        CP16(d0 + OFF_BH, Bh + b0);
        CP16(d1 + OFF_BH, Bh + b1);
        CP16(d0 + OFF_BL, Bl + b0);
        CP16(d1 + OFF_BL, Bl + b1);
    };

    float acc[2][8][4];
#pragma unroll
    for (int mt = 0; mt < 2; mt++)
#pragma unroll
        for (int nt = 0; nt < 8; nt++)
#pragma unroll
            for (int e = 0; e < 4; e++) acc[mt][nt][e] = 0.0f;

    const int nchunks = K / 32;

    issue(0); CP_COMMIT();

    for (int j = 0; j < nchunks; j++) {
        CP_WAIT(0);            // stage j data arrived (this thread's view)
        __syncthreads();       // all threads done computing j-1 AND see stage j

        if (j + 1 < nchunks) { issue(j + 1); CP_COMMIT(); }

        const unsigned base = sb + (unsigned)(j & 1) * STG_BYTES;
        const unsigned aH = base + OFF_AH, aL = base + OFF_AL;
        const unsigned bH = base + OFF_BH, bL = base + OFF_BL;

#pragma unroll
        for (int ks = 0; ks < 2; ks++) {
            const unsigned kb = (unsigned)(ks * 32 + lk);
            uint32_t ah[2][4], al[2][4];
#pragma unroll
            for (int mt = 0; mt < 2; mt++) {
                const unsigned ro = (unsigned)((wm * 32 + mt * 16 + lr) * RSTR) + kb;
                LDSM_X4(ah[mt][0], ah[mt][1], ah[mt][2], ah[mt][3], aH + ro);
                LDSM_X4(al[mt][0], al[mt][1], al[mt][2], al[mt][3], aL + ro);
            }
            uint32_t bh[4][4], bl[4][4];
#pragma unroll
            for (int np = 0; np < 4; np++) {
                const unsigned ro = (unsigned)((wn * 64 + np * 16 + lr) * RSTR) + kb;
                LDSM_X4(bh[np][0], bh[np][1], bh[np][2], bh[np][3], bH + ro);
                LDSM_X4(bl[np][0], bl[np][1], bl[np][2], bl[np][3], bL + ro);
            }
            // Pass 1: hi*hi — 16 independent HMMAs
#pragma unroll
            for (int mt = 0; mt < 2; mt++)
#pragma unroll
                for (int nt = 0; nt < 8; nt++) {
                    const int np = nt >> 1, sel = nt & 1;
                    MMA16816(acc[mt][nt], ah[mt], bh[np][sel], bh[np][sel + 2]);
                }
            // Pass 2: hi*lo
#pragma unroll
            for (int mt = 0; mt < 2; mt++)
#pragma unroll
                for (int nt = 0; nt < 8; nt++) {
                    const int np = nt >> 1, sel = nt & 1;
                    MMA16816(acc[mt][nt], ah[mt], bl[np][sel], bl[np][sel + 2]);
                }
            // Pass 3: lo*hi
#pragma unroll
            for (int mt = 0; mt < 2; mt++)
#pragma unroll
                for (int nt = 0; nt < 8; nt++) {
                    const int np = nt >> 1, sel = nt & 1;
                    MMA16816(acc[mt][nt], al[mt], bh[np][sel], bh[np][sel + 2]);
                }
        }
    }

    const int er = lane >> 2;
    const int ec = (lane & 3) * 2;
#pragma unroll
    for (int mt = 0; mt < 2; mt++) {
        const int row = row0 + wm * 32 + mt * 16 + er;
#pragma unroll
        for (int nt = 0; nt < 8; nt++) {
            const int col = col0 + wn * 64 + nt * 8 + ec;
            *(float2*)(C + (size_t)row * N + col) =
                make_float2(acc[mt][nt][0], acc[mt][nt][1]);
            *(float2*)(C + (size_t)(row + 8) * N + col) =
                make_float2(acc[mt][nt][2], acc[mt][nt][3]);
        }
    }
}

// ---------------------------------------------------------------------------
// L2-normalize q and k head rows of g_qkv in place. One warp per 64-elem row.
// ---------------------------------------------------------------------------
__global__ __launch_bounds__(256) void normalize_qk(float* __restrict__ qkv) {
    const int gw   = (blockIdx.x * blockDim.x + threadIdx.x) >> 5;
    const int lane = threadIdx.x & 31;
    const int h    = gw & 15;
    const int bt   = (gw >> 4) & (BQ * TQ - 1);
    const int part = gw >> 16;     // 0 = q, 1 = k

    float* p = qkv + (size_t)bt * ROW3 + part * DQ + h * HDQ;
    float v0 = p[lane];
    float v1 = p[lane + 32];
    float ss = v0 * v0 + v1 * v1;
#pragma unroll
    for (int m = 16; m; m >>= 1) ss += __shfl_xor_sync(0xffffffffu, ss, m);
    const float s = 1.0f / fmaxf(sqrtf(ss), 1e-12f);
    p[lane]      = v0 * s;
    p[lane + 32] = v1 * s;
}

// ---------------------------------------------------------------------------
// Causal yat attention on tensor cores (bf16x3 mma.sync). Epilogue writes
// pre-split bf16 hi/lo (feeds the out-proj GEMM directly). MMA chains per
// accumulator interleaved to cut RAW stalls.
// ---------------------------------------------------------------------------
#define VR 144

__global__ __launch_bounds__(128) void yat_attn_tc(const float* __restrict__ qkv,
                                                   uint32_t* __restrict__ ath,
                                                   uint32_t* __restrict__ atl) {
    __shared__ __align__(16) unsigned char sKH[64 * VR];
    __shared__ __align__(16) unsigned char sKL[64 * VR];
    __shared__ __align__(16) unsigned char sVH[64 * VR];
    __shared__ __align__(16) unsigned char sVL[64 * VR];

    const int tid  = threadIdx.x;
    const int wid  = tid >> 5;
    const int lane = tid & 31;

    const int qt = blockIdx.x;
    const int h  = blockIdx.y;
    const int b  = blockIdx.z;
    const int q0 = qt * 64;

    const int lr = (lane & 7) + ((lane >> 3) & 1) * 8;
    const int lk = (lane >> 4) * 16;

    const unsigned kH = su32(sKH), kL = su32(sKL);
    const unsigned vH = su32(sVH), vL = su32(sVL);

    // ---- stage Q through K smem, pull A-fragments into registers ----
    {
        const float* qb = qkv + ((size_t)(b * TQ) + q0) * ROW3 + h * HDQ;
#pragma unroll
        for (int j = 0; j < 8; j++) {
            const int idx = tid + 128 * j;
            const int r = idx >> 4, c = idx & 15;
            float4 f = *(const float4*)(qb + (size_t)r * ROW3 + c * 4);
            uint32_t h0, h1, l0, l1;
            split4(f, h0, h1, l0, l1);
            const unsigned off = (unsigned)(r * VR + c * 8);
            STSV2(kH + off, h0, h1);
            STSV2(kL + off, l0, l1);
        }
    }
    __syncthreads();
    uint32_t qfh[4][4], qfl[4][4];
#pragma unroll
    for (int kc = 0; kc < 4; kc++) {
        const unsigned ro = (unsigned)((wid * 16 + lr) * VR + kc * 32 + lk);
        LDSM_X4(qfh[kc][0], qfh[kc][1], qfh[kc][2], qfh[kc][3], kH + ro);
        LDSM_X4(qfl[kc][0], qfl[kc][1], qfl[kc][2], qfl[kc][3], kL + ro);
    }

    float accO[8][4];
#pragma unroll
    for (int nt = 0; nt < 8; nt++)
#pragma unroll
        for (int e = 0; e < 4; e++) accO[nt][e] = 0.0f;
    float dsum0 = 0.0f, dsum1 = 0.0f;

    const int qg0 = q0 + wid * 16 + (lane >> 2);

    for (int kt = 0; kt <= qt; kt++) {
        __syncthreads();
        const float* kb = qkv + ((size_t)(b * TQ) + kt * 64) * ROW3 + DQ + h * HDQ;
#pragma unroll
        for (int j = 0; j < 8; j++) {
            const int idx = tid + 128 * j;
            const int r = idx >> 4, c = idx & 15;
            const unsigned off = (unsigned)(r * VR + c * 8);
            float4 f = *(const float4*)(kb + (size_t)r * ROW3 + c * 4);
            uint32_t h0, h1, l0, l1;
            split4(f, h0, h1, l0, l1);
            STSV2(kH + off, h0, h1);
            STSV2(kL + off, l0, l1);
            float4 fv = *(const float4*)(kb + DQ + (size_t)r * ROW3 + c * 4);
            split4(fv, h0, h1, l0, l1);
            STSV2(vH + off, h0, h1);
            STSV2(vL + off, l0, l1);
        }
        __syncthreads();

        // ---- S = Qn Kn^T (bf16x3), interleaved chains ----
        float sf[8][4];
#pragma unroll
        for (int nt = 0; nt < 8; nt++)
#pragma unroll
            for (int e = 0; e < 4; e++) sf[nt][e] = 0.0f;

#pragma unroll
        for (int kc = 0; kc < 4; kc++) {
#pragma unroll
            for (int g = 0; g < 4; g++) {
                uint32_t khf[4], klf[4];
                const unsigned ro = (unsigned)((g * 16 + lr) * VR + kc * 32 + lk);
                LDSM_X4(khf[0], khf[1], khf[2], khf[3], kH + ro);
                LDSM_X4(klf[0], klf[1], klf[2], klf[3], kL + ro);
                MMA16816(sf[2 * g],     qfh[kc], khf[0], khf[2]);
                MMA16816(sf[2 * g + 1], qfh[kc], khf[1], khf[3]);
                MMA16816(sf[2 * g],     qfh[kc], klf[0], klf[2]);
                MMA16816(sf[2 * g + 1], qfh[kc], klf[1], klf[3]);
                MMA16816(sf[2 * g],     qfl[kc], khf[0], khf[2]);
                MMA16816(sf[2 * g + 1], qfl[kc], khf[1], khf[3]);
            }
        }

        // ---- transform to w, mask, den, repack as A-fragments ----
        const bool diag = (kt == qt);
        uint32_t w01h[8], w01l[8], w23h[8], w23l[8];
#pragma unroll
        for (int nt = 0; nt < 8; nt++) {
            float w[4];
#pragma unroll
            for (int e = 0; e < 4; e++) {
                const float d = sf[nt][e];
                const float den = fmaxf(fmaf(-2.0f, d, 2.01f), 1e-6f);
                float rc; RCPA(rc, den);
                w[e] = d * d * rc;
            }
            if (diag) {
                const int kg = kt * 64 + nt * 8 + 2 * (lane & 3);
                if (kg     > qg0)     w[0] = 0.0f;
                if (kg + 1 > qg0)     w[1] = 0.0f;
                if (kg     > qg0 + 8) w[2] = 0.0f;
                if (kg + 1 > qg0 + 8) w[3] = 0.0f;
            }
            dsum0 += w[0] + w[1];
            dsum1 += w[2] + w[3];
            packsplit2(w[0], w[1], w01h[nt], w01l[nt]);
            packsplit2(w[2], w[3], w23h[nt], w23l[nt]);
        }

        // ---- O += w @ V (bf16x3, V via ldmatrix.trans), interleaved ----
#pragma unroll
        for (int kc2 = 0; kc2 < 4; kc2++) {
            uint32_t ah[4] = {w01h[2 * kc2], w23h[2 * kc2],
                              w01h[2 * kc2 + 1], w23h[2 * kc2 + 1]};
            uint32_t al[4] = {w01l[2 * kc2], w23l[2 * kc2],
                              w01l[2 * kc2 + 1], w23l[2 * kc2 + 1]};
#pragma unroll
            for (int g = 0; g < 4; g++) {
                uint32_t vhf[4], vlf[4];
                const unsigned ro = (unsigned)((kc2 * 16 + lr) * VR + g * 32 + lk);
                LDSM_X4_T(vhf[0], vhf[1], vhf[2], vhf[3], vH + ro);
                LDSM_X4_T(vlf[0], vlf[1], vlf[2], vlf[3], vL + ro);
                MMA16816(accO[2 * g],     ah, vhf[0], vhf[1]);
                MMA16816(accO[2 * g + 1], ah, vhf[2], vhf[3]);
                MMA16816(accO[2 * g],     ah, vlf[0], vlf[1]);
                MMA16816(accO[2 * g + 1], ah, vlf[2], vlf[3]);
                MMA16816(accO[2 * g],     al, vhf[0], vhf[1]);
                MMA16816(accO[2 * g + 1], al, vhf[2], vhf[3]);
            }
        }
    }

    // ---- epilogue: reduce den, divide, write SPLIT bf16 ----
    dsum0 += __shfl_xor_sync(0xffffffffu, dsum0, 1);
    dsum0 += __shfl_xor_sync(0xffffffffu, dsum0, 2);
    dsum1 += __shfl_xor_sync(0xffffffffu, dsum1, 1);
    dsum1 += __shfl_xor_sync(0xffffffffu, dsum1, 2);
    float inv0, inv1;
    RCPA(inv0, dsum0 + 1e-6f);
    RCPA(inv1, dsum1 + 1e-6f);

    const size_t rowg  = (size_t)(b * TQ) + q0 + wid * 16 + (lane >> 2);
    const int    colb2 = h * (HDQ / 2) + (lane & 3);  // u32 (bf16-pair) index
#pragma unroll
    for (int nt = 0; nt < 8; nt++) {
        uint32_t hh, ll;
        packsplit2(accO[nt][0] * inv0, accO[nt][1] * inv0, hh, ll);
        ath[rowg * (DQ / 2) + colb2 + nt * 4] = hh;
        atl[rowg * (DQ / 2) + colb2 + nt * 4] = ll;
        packsplit2(accO[nt][2] * inv1, accO[nt][3] * inv1, hh, ll);
        ath[(rowg + 8) * (DQ / 2) + colb2 + nt * 4] = hh;
        atl[(rowg + 8) * (DQ / 2) + colb2 + nt * 4] = ll;
    }
}

// ---------------------------------------------------------------------------
// kernel_launch
// ---------------------------------------------------------------------------
extern "C" void kernel_launch(void* const* d_in, const int* in_sizes, int n_in,
                              void* d_out, int out_size) {
    (void)in_sizes; (void)n_in; (void)out_size;
    const float* x    = (const float*)d_in[0];   // [B,T,D]
    const float* Wqkv = (const float*)d_in[1];   // [3D, D]
    const float* Wout = (const float*)d_in[2];   // [D, D]
    float* out = (float*)d_out;                  // [B,T,D]

    void *p_qkv, *p_xh, *p_xl, *p_w1h, *p_w1l, *p_w2h, *p_w2l, *p_ah, *p_al;
    cudaGetSymbolAddress(&p_qkv, g_qkv);
    cudaGetSymbolAddress(&p_xh, g_xh);   cudaGetSymbolAddress(&p_xl, g_xl);
    cudaGetSymbolAddress(&p_w1h, g_w1h); cudaGetSymbolAddress(&p_w1l, g_w1l);
    cudaGetSymbolAddress(&p_w2h, g_w2h); cudaGetSymbolAddress(&p_w2l, g_w2l);
    cudaGetSymbolAddress(&p_ah, g_ah);   cudaGetSymbolAddress(&p_al, g_al);

    static bool attr_done = false;
    if (!attr_done) {
        cudaFuncSetAttribute(gemm_bf16_pipe,
                             cudaFuncAttributeMaxDynamicSharedMemorySize, GEMM_SMEM);
        attr_done = true;
    }

    const int M = BQ * TQ;  // 4096

    // 0) split inputs to bf16 hi/lo
    split_f32<<<(M * DQ / 4) / 256, 256>>>(x, (uint32_t*)p_xh, (uint32_t*)p_xl, M * DQ / 4);
    split_f32<<<(ROW3 * DQ / 4) / 256, 256>>>(Wqkv, (uint32_t*)p_w1h, (uint32_t*)p_w1l, ROW3 * DQ / 4);
    split_f32<<<(DQ * DQ / 4) / 256, 256>>>(Wout, (uint32_t*)p_w2h, (uint32_t*)p_w2l, DQ * DQ / 4);

    // 1) qkv = x @ Wqkv^T : [4096,3072]  (pipelined bf16x3, 2 CTAs/SM)
    gemm_bf16_pipe<<<dim3(ROW3 / 128, M / 128), 256, GEMM_SMEM>>>(
        (const uint16_t*)p_xh, (const uint16_t*)p_xl,
        (const uint16_t*)p_w1h, (const uint16_t*)p_w1l,
        (float*)p_qkv, M, ROW3, DQ);

    // 2) L2-normalize q,k per head in place
    normalize_qk<<<(2 * M * HQ) / 8, 256>>>((float*)p_qkv);

    // 3) causal yat attention -> split bf16 att (feeds out-proj directly)
    yat_attn_tc<<<dim3(TQ / 64, HQ, BQ), 128>>>((const float*)p_qkv,
                                                (uint32_t*)p_ah, (uint32_t*)p_al);

    // 4) out = att @ Wout^T : [4096,1024]  (pipelined bf16x3, 2 CTAs/SM)
    gemm_bf16_pipe<<<dim3(DQ / 128, M / 128), 256, GEMM_SMEM>>>(
        (const uint16_t*)p_ah, (const uint16_t*)p_al,
        (const uint16_t*)p_w2h, (const uint16_t*)p_w2l,
        out, M, DQ, DQ);
}

// round 9
// speedup vs baseline: 5.7357x; 1.2386x over previous
#include <cuda_runtime.h>
#include <cuda_fp16.h>
#include <cstddef>
#include <cstdint>

// Problem constants (fixed by setup_inputs)
#define BQ   2
#define TQ   2048
#define DQ   1024
#define HQ   16
#define HDQ  64
#define ROW3 3072   // 3*DQ

// Scratch (device globals — no allocation allowed). u32 = packed fp16x2.
__device__ float    g_qkv[(size_t)BQ * TQ * ROW3];   // fp32 qkv (normalized in place)
__device__ uint32_t g_xh [(size_t)BQ * TQ * DQ / 2]; // x split hi
__device__ uint32_t g_xl [(size_t)BQ * TQ * DQ / 2]; // x split lo
__device__ uint32_t g_w1h[(size_t)ROW3 * DQ / 2];    // Wqkv hi (lo not needed)
__device__ uint32_t g_w2h[(size_t)DQ * DQ / 2];      // Wout hi (lo not needed)
__device__ uint32_t g_ah [(size_t)BQ * TQ * DQ / 2]; // attention out hi
__device__ uint32_t g_al [(size_t)BQ * TQ * DQ / 2]; // attention out lo

typedef unsigned long long ull;

__device__ __forceinline__ unsigned su32(const void* p) {
    return (unsigned)__cvta_generic_to_shared(p);
}

// ---------------------------------------------------------------------------
// Warp-level tensor-core + async-copy primitives (base-target PTX)
// ---------------------------------------------------------------------------
#define LDSM_X4(r0, r1, r2, r3, addr) \
    asm volatile("ldmatrix.sync.aligned.m8n8.x4.shared.b16 {%0,%1,%2,%3}, [%4];" \
        : "=r"(r0), "=r"(r1), "=r"(r2), "=r"(r3) : "r"(addr))

#define LDSM_X4_T(r0, r1, r2, r3, addr) \
    asm volatile("ldmatrix.sync.aligned.m8n8.x4.trans.shared.b16 {%0,%1,%2,%3}, [%4];" \
        : "=r"(r0), "=r"(r1), "=r"(r2), "=r"(r3) : "r"(addr))

#define MMAH(c, a, b0, b1) \
    asm volatile("mma.sync.aligned.m16n8k16.row.col.f32.f16.f16.f32 " \
        "{%0,%1,%2,%3}, {%4,%5,%6,%7}, {%8,%9}, {%0,%1,%2,%3};" \
        : "+f"((c)[0]), "+f"((c)[1]), "+f"((c)[2]), "+f"((c)[3]) \
        : "r"((a)[0]), "r"((a)[1]), "r"((a)[2]), "r"((a)[3]), "r"(b0), "r"(b1))

#define CP16(dst, src) \
    asm volatile("cp.async.cg.shared.global [%0], [%1], 16;" :: "r"(dst), "l"(src))
#define CP_COMMIT() asm volatile("cp.async.commit_group;" ::: "memory")
#define CP_WAIT(n)  asm volatile("cp.async.wait_group %0;" :: "n"(n) : "memory")

// pack two fp16 (from floats) into one u32 (lo = first arg)
__device__ __forceinline__ uint32_t packh2(float lo, float hi) {
    __half2 t = __halves2half2(__float2half_rn(lo), __float2half_rn(hi));
    return *reinterpret_cast<uint32_t*>(&t);
}

// Split a float4 into packed fp16x2 hi and lo (lo = rounded residual)
__device__ __forceinline__ void split4h(float4 f, uint32_t& h0, uint32_t& h1,
                                        uint32_t& l0, uint32_t& l1) {
    const __half hx = __float2half_rn(f.x), hy = __float2half_rn(f.y);
    const __half hz = __float2half_rn(f.z), hw = __float2half_rn(f.w);
    {
        __half2 t = __halves2half2(hx, hy);
        h0 = *reinterpret_cast<uint32_t*>(&t);
        __half2 u = __halves2half2(hz, hw);
        h1 = *reinterpret_cast<uint32_t*>(&u);
    }
    l0 = packh2(f.x - __half2float(hx), f.y - __half2float(hy));
    l1 = packh2(f.z - __half2float(hz), f.w - __half2float(hw));
}

// Pack two fp32 into fp16x2 hi + residual lo
__device__ __forceinline__ void packsplit2h(float w0, float w1,
                                            uint32_t& h, uint32_t& l) {
    const __half h0 = __float2half_rn(w0), h1 = __float2half_rn(w1);
    __half2 t = __halves2half2(h0, h1);
    h = *reinterpret_cast<uint32_t*>(&t);
    l = packh2(w0 - __half2float(h0), w1 - __half2float(h1));
}

#define STSV2(addr, v0, v1) \
    asm volatile("st.shared.v2.b32 [%0], {%1,%2};" :: "r"(addr), "r"(v0), "r"(v1) : "memory")

#define RCPA(d, a) \
    asm("rcp.approx.f32 %0, %1;" : "=f"(d) : "f"(a))

// ---------------------------------------------------------------------------
// Converts: fp32 -> packed fp16x2 hi/lo (or hi only, for weights)
// ---------------------------------------------------------------------------
__global__ __launch_bounds__(256) void split_f16(const float* __restrict__ src,
                                                 uint32_t* __restrict__ hi,
                                                 uint32_t* __restrict__ lo, int n4) {
    const int i = blockIdx.x * blockDim.x + threadIdx.x;
    if (i < n4) {
        float4 f = ((const float4*)src)[i];
        uint32_t h0, h1, l0, l1;
        split4h(f, h0, h1, l0, l1);
        hi[2 * i] = h0; hi[2 * i + 1] = h1;
        lo[2 * i] = l0; lo[2 * i + 1] = l1;
    }
}

__global__ __launch_bounds__(256) void conv_f16(const float* __restrict__ src,
                                                uint32_t* __restrict__ hi, int n4) {
    const int i = blockIdx.x * blockDim.x + threadIdx.x;
    if (i < n4) {
        float4 f = ((const float4*)src)[i];
        hi[2 * i]     = packh2(f.x, f.y);
        hi[2 * i + 1] = packh2(f.z, f.w);
    }
}

// ---------------------------------------------------------------------------
// Pipelined fp16x2 GEMM: C[M,N] = (Ah+Al)[M,K] @ Bh[N,K]^T   (A corrected,
// B hi-only; error ~2^-12 rel). CTA tile 128x128, 8 warps, BK=32,
// 3-stage cp.async pipeline, 2 CTAs/SM (92KB smem).
// ---------------------------------------------------------------------------
#define RSTR 80
#define NSTG 3
#define STG_BYTES 30720         // 3 tiles x 128 rows x 80B
#define OFF_AH 0
#define OFF_AL 10240
#define OFF_BH 20480
#define GEMM_SMEM (NSTG * STG_BYTES)

extern __shared__ unsigned char g_dsm[];

__global__ __launch_bounds__(256, 2) void gemm_f16_2p(
    const uint16_t* __restrict__ Ah, const uint16_t* __restrict__ Al,
    const uint16_t* __restrict__ Bh,
    float* __restrict__ C, int M, int N, int K) {

    const int tid  = threadIdx.x;
    const int wid  = tid >> 5;
    const int lane = tid & 31;
    const int wm   = wid & 3;
    const int wn   = wid >> 2;

    const int row0 = blockIdx.y * 128;
    const int col0 = blockIdx.x * 128;

    const int lr = (lane & 7) + ((lane >> 3) & 1) * 8;
    const int lk = (lane >> 4) * 16;

    const unsigned sb = su32(g_dsm);

    // producer: 2 segments (16B = 8 fp16) per tile per thread
    const int r0p = (tid * 2) >> 2,     s0p = (tid * 2) & 3;
    const int r1p = (tid * 2 + 1) >> 2, s1p = (tid * 2 + 1) & 3;

    auto issue = [&](int c) {
        const unsigned base = sb + (unsigned)(c % NSTG) * STG_BYTES;
        const int k0 = c * 32;
        const unsigned d0 = base + (unsigned)(r0p * RSTR + s0p * 16);
        const unsigned d1 = base + (unsigned)(r1p * RSTR + s1p * 16);
        const size_t a0 = (size_t)(row0 + r0p) * K + k0 + s0p * 8;
        const size_t a1 = (size_t)(row0 + r1p) * K + k0 + s1p * 8;
        CP16(d0 + OFF_AH, Ah + a0);
        CP16(d1 + OFF_AH, Ah + a1);
        CP16(d0 + OFF_AL, Al + a0);
        CP16(d1 + OFF_AL, Al + a1);
        const size_t b0 = (size_t)(col0 + r0p) * K + k0 + s0p * 8;
        const size_t b1 = (size_t)(col0 + r1p) * K + k0 + s1p * 8;
        CP16(d0 + OFF_BH, Bh + b0);
        CP16(d1 + OFF_BH, Bh + b1);
    };

    float acc[2][8][4];
#pragma unroll
    for (int mt = 0; mt < 2; mt++)
#pragma unroll
        for (int nt = 0; nt < 8; nt++)
#pragma unroll
            for (int e = 0; e < 4; e++) acc[mt][nt][e] = 0.0f;

    const int nchunks = K / 32;

    issue(0); CP_COMMIT();
    issue(1); CP_COMMIT();

    for (int j = 0; j < nchunks; j++) {
        CP_WAIT(1);            // stage j's group complete (<=1 outstanding)
        __syncthreads();       // all threads done with buffer being overwritten

        if (j + 2 < nchunks) issue(j + 2);
        CP_COMMIT();

        const unsigned base = sb + (unsigned)(j % NSTG) * STG_BYTES;
        const unsigned aH = base + OFF_AH, aL = base + OFF_AL;
        const unsigned bH = base + OFF_BH;

#pragma unroll
        for (int ks = 0; ks < 2; ks++) {
            const unsigned kb = (unsigned)(ks * 32 + lk);
            uint32_t ah[2][4], al[2][4];
#pragma unroll
            for (int mt = 0; mt < 2; mt++) {
                const unsigned ro = (unsigned)((wm * 32 + mt * 16 + lr) * RSTR) + kb;
                LDSM_X4(ah[mt][0], ah[mt][1], ah[mt][2], ah[mt][3], aH + ro);
                LDSM_X4(al[mt][0], al[mt][1], al[mt][2], al[mt][3], aL + ro);
            }
            uint32_t bh[4][4];
#pragma unroll
            for (int np = 0; np < 4; np++) {
                const unsigned ro = (unsigned)((wn * 64 + np * 16 + lr) * RSTR) + kb;
                LDSM_X4(bh[np][0], bh[np][1], bh[np][2], bh[np][3], bH + ro);
            }
            // Pass 1: ah*bh — 16 independent HMMAs
#pragma unroll
            for (int mt = 0; mt < 2; mt++)
#pragma unroll
                for (int nt = 0; nt < 8; nt++) {
                    const int np = nt >> 1, sel = nt & 1;
                    MMAH(acc[mt][nt], ah[mt], bh[np][sel], bh[np][sel + 2]);
                }
            // Pass 2: al*bh
#pragma unroll
            for (int mt = 0; mt < 2; mt++)
#pragma unroll
                for (int nt = 0; nt < 8; nt++) {
                    const int np = nt >> 1, sel = nt & 1;
                    MMAH(acc[mt][nt], al[mt], bh[np][sel], bh[np][sel + 2]);
                }
        }
    }

    const int er = lane >> 2;
    const int ec = (lane & 3) * 2;
#pragma unroll
    for (int mt = 0; mt < 2; mt++) {
        const int row = row0 + wm * 32 + mt * 16 + er;
#pragma unroll
        for (int nt = 0; nt < 8; nt++) {
            const int col = col0 + wn * 64 + nt * 8 + ec;
            *(float2*)(C + (size_t)row * N + col) =
                make_float2(acc[mt][nt][0], acc[mt][nt][1]);
            *(float2*)(C + (size_t)(row + 8) * N + col) =
                make_float2(acc[mt][nt][2], acc[mt][nt][3]);
        }
    }
}

// ---------------------------------------------------------------------------
// L2-normalize q and k head rows of g_qkv in place. One warp per 64-elem row.
// ---------------------------------------------------------------------------
__global__ __launch_bounds__(256) void normalize_qk(float* __restrict__ qkv) {
    const int gw   = (blockIdx.x * blockDim.x + threadIdx.x) >> 5;
    const int lane = threadIdx.x & 31;
    const int h    = gw & 15;
    const int bt   = (gw >> 4) & (BQ * TQ - 1);
    const int part = gw >> 16;     // 0 = q, 1 = k

    float* p = qkv + (size_t)bt * ROW3 + part * DQ + h * HDQ;
    float v0 = p[lane];
    float v1 = p[lane + 32];
    float ss = v0 * v0 + v1 * v1;
#pragma unroll
    for (int m = 16; m; m >>= 1) ss += __shfl_xor_sync(0xffffffffu, ss, m);
    const float s = 1.0f / fmaxf(sqrtf(ss), 1e-12f);
    p[lane]      = v0 * s;
    p[lane + 32] = v1 * s;
}

// ---------------------------------------------------------------------------
// Causal yat attention on tensor cores (fp16x3 mma.sync, ~2^-22 accurate).
// Epilogue writes pre-split fp16 hi/lo for the out-proj GEMM.
// qt reversed (longest CTAs scheduled first).
// ---------------------------------------------------------------------------
#define VR 144

__global__ __launch_bounds__(128) void yat_attn_tc(const float* __restrict__ qkv,
                                                   uint32_t* __restrict__ ath,
                                                   uint32_t* __restrict__ atl) {
    __shared__ __align__(16) unsigned char sKH[64 * VR];
    __shared__ __align__(16) unsigned char sKL[64 * VR];
    __shared__ __align__(16) unsigned char sVH[64 * VR];
    __shared__ __align__(16) unsigned char sVL[64 * VR];

    const int tid  = threadIdx.x;
    const int wid  = tid >> 5;
    const int lane = tid & 31;

    const int qt = (int)gridDim.x - 1 - (int)blockIdx.x;  // longest first
    const int h  = blockIdx.y;
    const int b  = blockIdx.z;
    const int q0 = qt * 64;

    const int lr = (lane & 7) + ((lane >> 3) & 1) * 8;
    const int lk = (lane >> 4) * 16;

    const unsigned kH = su32(sKH), kL = su32(sKL);
    const unsigned vH = su32(sVH), vL = su32(sVL);

    // ---- stage Q through K smem, pull A-fragments into registers ----
    {
        const float* qb = qkv + ((size_t)(b * TQ) + q0) * ROW3 + h * HDQ;
#pragma unroll
        for (int j = 0; j < 8; j++) {
            const int idx = tid + 128 * j;
            const int r = idx >> 4, c = idx & 15;
            float4 f = *(const float4*)(qb + (size_t)r * ROW3 + c * 4);
            uint32_t h0, h1, l0, l1;
            split4h(f, h0, h1, l0, l1);
            const unsigned off = (unsigned)(r * VR + c * 8);
            STSV2(kH + off, h0, h1);
            STSV2(kL + off, l0, l1);
        }
    }
    __syncthreads();
    uint32_t qfh[4][4], qfl[4][4];
#pragma unroll
    for (int kc = 0; kc < 4; kc++) {
        const unsigned ro = (unsigned)((wid * 16 + lr) * VR + kc * 32 + lk);
        LDSM_X4(qfh[kc][0], qfh[kc][1], qfh[kc][2], qfh[kc][3], kH + ro);
        LDSM_X4(qfl[kc][0], qfl[kc][1], qfl[kc][2], qfl[kc][3], kL + ro);
    }

    float accO[8][4];
#pragma unroll
    for (int nt = 0; nt < 8; nt++)
#pragma unroll
        for (int e = 0; e < 4; e++) accO[nt][e] = 0.0f;
    float dsum0 = 0.0f, dsum1 = 0.0f;

    const int qg0 = q0 + wid * 16 + (lane >> 2);

    for (int kt = 0; kt <= qt; kt++) {
        __syncthreads();
        const float* kb = qkv + ((size_t)(b * TQ) + kt * 64) * ROW3 + DQ + h * HDQ;
#pragma unroll
        for (int j = 0; j < 8; j++) {
            const int idx = tid + 128 * j;
            const int r = idx >> 4, c = idx & 15;
            const unsigned off = (unsigned)(r * VR + c * 8);
            float4 f = *(const float4*)(kb + (size_t)r * ROW3 + c * 4);
            uint32_t h0, h1, l0, l1;
            split4h(f, h0, h1, l0, l1);
            STSV2(kH + off, h0, h1);
            STSV2(kL + off, l0, l1);
            float4 fv = *(const float4*)(kb + DQ + (size_t)r * ROW3 + c * 4);
            split4h(fv, h0, h1, l0, l1);
            STSV2(vH + off, h0, h1);
            STSV2(vL + off, l0, l1);
        }
        __syncthreads();

        // ---- S = Qn Kn^T (fp16x3), interleaved chains ----
        float sf[8][4];
#pragma unroll
        for (int nt = 0; nt < 8; nt++)
#pragma unroll
            for (int e = 0; e < 4; e++) sf[nt][e] = 0.0f;

#pragma unroll
        for (int kc = 0; kc < 4; kc++) {
#pragma unroll
            for (int g = 0; g < 4; g++) {
                uint32_t khf[4], klf[4];
                const unsigned ro = (unsigned)((g * 16 + lr) * VR + kc * 32 + lk);
                LDSM_X4(khf[0], khf[1], khf[2], khf[3], kH + ro);
                LDSM_X4(klf[0], klf[1], klf[2], klf[3], kL + ro);
                MMAH(sf[2 * g],     qfh[kc], khf[0], khf[2]);
                MMAH(sf[2 * g + 1], qfh[kc], khf[1], khf[3]);
                MMAH(sf[2 * g],     qfh[kc], klf[0], klf[2]);
                MMAH(sf[2 * g + 1], qfh[kc], klf[1], klf[3]);
                MMAH(sf[2 * g],     qfl[kc], khf[0], khf[2]);
                MMAH(sf[2 * g + 1], qfl[kc], khf[1], khf[3]);
            }
        }

        // ---- transform to w, mask, den, repack as A-fragments ----
        const bool diag = (kt == qt);
        uint32_t w01h[8], w01l[8], w23h[8], w23l[8];
#pragma unroll
        for (int nt = 0; nt < 8; nt++) {
            float w[4];
#pragma unroll
            for (int e = 0; e < 4; e++) {
                const float d = sf[nt][e];
                const float den = fmaxf(fmaf(-2.0f, d, 2.01f), 1e-6f);
                float rc; RCPA(rc, den);
                w[e] = d * d * rc;
            }
            if (diag) {
                const int kg = kt * 64 + nt * 8 + 2 * (lane & 3);
                if (kg     > qg0)     w[0] = 0.0f;
                if (kg + 1 > qg0)     w[1] = 0.0f;
                if (kg     > qg0 + 8) w[2] = 0.0f;
                if (kg + 1 > qg0 + 8) w[3] = 0.0f;
            }
            dsum0 += w[0] + w[1];
            dsum1 += w[2] + w[3];
            packsplit2h(w[0], w[1], w01h[nt], w01l[nt]);
            packsplit2h(w[2], w[3], w23h[nt], w23l[nt]);
        }

        // ---- O += w @ V (fp16x3, V via ldmatrix.trans), interleaved ----
#pragma unroll
        for (int kc2 = 0; kc2 < 4; kc2++) {
            uint32_t ah[4] = {w01h[2 * kc2], w23h[2 * kc2],
                              w01h[2 * kc2 + 1], w23h[2 * kc2 + 1]};
            uint32_t al[4] = {w01l[2 * kc2], w23l[2 * kc2],
                              w01l[2 * kc2 + 1], w23l[2 * kc2 + 1]};
#pragma unroll
            for (int g = 0; g < 4; g++) {
                uint32_t vhf[4], vlf[4];
                const unsigned ro = (unsigned)((kc2 * 16 + lr) * VR + g * 32 + lk);
                LDSM_X4_T(vhf[0], vhf[1], vhf[2], vhf[3], vH + ro);
                LDSM_X4_T(vlf[0], vlf[1], vlf[2], vlf[3], vL + ro);
                MMAH(accO[2 * g],     ah, vhf[0], vhf[1]);
                MMAH(accO[2 * g + 1], ah, vhf[2], vhf[3]);
                MMAH(accO[2 * g],     ah, vlf[0], vlf[1]);
                MMAH(accO[2 * g + 1], ah, vlf[2], vlf[3]);
                MMAH(accO[2 * g],     al, vhf[0], vhf[1]);
                MMAH(accO[2 * g + 1], al, vhf[2], vhf[3]);
            }
        }
    }

    // ---- epilogue: reduce den, divide, write SPLIT fp16 ----
    dsum0 += __shfl_xor_sync(0xffffffffu, dsum0, 1);
    dsum0 += __shfl_xor_sync(0xffffffffu, dsum0, 2);
    dsum1 += __shfl_xor_sync(0xffffffffu, dsum1, 1);
    dsum1 += __shfl_xor_sync(0xffffffffu, dsum1, 2);
    float inv0, inv1;
    RCPA(inv0, dsum0 + 1e-6f);
    RCPA(inv1, dsum1 + 1e-6f);

    const size_t rowg  = (size_t)(b * TQ) + q0 + wid * 16 + (lane >> 2);
    const int    colb2 = h * (HDQ / 2) + (lane & 3);  // u32 (fp16-pair) index
#pragma unroll
    for (int nt = 0; nt < 8; nt++) {
        uint32_t hh, ll;
        packsplit2h(accO[nt][0] * inv0, accO[nt][1] * inv0, hh, ll);
        ath[rowg * (DQ / 2) + colb2 + nt * 4] = hh;
        atl[rowg * (DQ / 2) + colb2 + nt * 4] = ll;
        packsplit2h(accO[nt][2] * inv1, accO[nt][3] * inv1, hh, ll);
        ath[(rowg + 8) * (DQ / 2) + colb2 + nt * 4] = hh;
        atl[(rowg + 8) * (DQ / 2) + colb2 + nt * 4] = ll;
    }
}

// ---------------------------------------------------------------------------
// kernel_launch
// ---------------------------------------------------------------------------
extern "C" void kernel_launch(void* const* d_in, const int* in_sizes, int n_in,
                              void* d_out, int out_size) {
    (void)in_sizes; (void)n_in; (void)out_size;
    const float* x    = (const float*)d_in[0];   // [B,T,D]
    const float* Wqkv = (const float*)d_in[1];   // [3D, D]
    const float* Wout = (const float*)d_in[2];   // [D, D]
    float* out = (float*)d_out;                  // [B,T,D]

    void *p_qkv, *p_xh, *p_xl, *p_w1h, *p_w2h, *p_ah, *p_al;
    cudaGetSymbolAddress(&p_qkv, g_qkv);
    cudaGetSymbolAddress(&p_xh, g_xh);   cudaGetSymbolAddress(&p_xl, g_xl);
    cudaGetSymbolAddress(&p_w1h, g_w1h); cudaGetSymbolAddress(&p_w2h, g_w2h);
    cudaGetSymbolAddress(&p_ah, g_ah);   cudaGetSymbolAddress(&p_al, g_al);

    static bool attr_done = false;
    if (!attr_done) {
        cudaFuncSetAttribute(gemm_f16_2p,
                             cudaFuncAttributeMaxDynamicSharedMemorySize, GEMM_SMEM);
        attr_done = true;
    }

    const int M = BQ * TQ;  // 4096

    // 0) convert inputs to fp16 (x: hi+lo, weights: hi only)
    split_f16<<<(M * DQ / 4) / 256, 256>>>(x, (uint32_t*)p_xh, (uint32_t*)p_xl, M * DQ / 4);
    conv_f16<<<(ROW3 * DQ / 4) / 256, 256>>>(Wqkv, (uint32_t*)p_w1h, ROW3 * DQ / 4);
    conv_f16<<<(DQ * DQ / 4) / 256, 256>>>(Wout, (uint32_t*)p_w2h, DQ * DQ / 4);

    // 1) qkv = x @ Wqkv^T : [4096,3072]  (fp16 2-pass, A corrected)
    gemm_f16_2p<<<dim3(ROW3 / 128, M / 128), 256, GEMM_SMEM>>>(
        (const uint16_t*)p_xh, (const uint16_t*)p_xl, (const uint16_t*)p_w1h,
        (float*)p_qkv, M, ROW3, DQ);

    // 2) L2-normalize q,k per head in place
    normalize_qk<<<(2 * M * HQ) / 8, 256>>>((float*)p_qkv);

    // 3) causal yat attention (fp16x3) -> split fp16 att
    yat_attn_tc<<<dim3(TQ / 64, HQ, BQ), 128>>>((const float*)p_qkv,
                                                (uint32_t*)p_ah, (uint32_t*)p_al);

    // 4) out = att @ Wout^T : [4096,1024]  (fp16 2-pass, A corrected)
    gemm_f16_2p<<<dim3(DQ / 128, M / 128), 256, GEMM_SMEM>>>(
        (const uint16_t*)p_ah, (const uint16_t*)p_al, (const uint16_t*)p_w2h,
        out, M, DQ, DQ);
}

// round 10
// speedup vs baseline: 6.0374x; 1.0526x over previous
#include <cuda_runtime.h>
#include <cuda_fp16.h>
#include <cstddef>
#include <cstdint>

// Problem constants (fixed by setup_inputs)
#define BQ   2
#define TQ   2048
#define DQ   1024
#define HQ   16
#define HDQ  64
#define ROW3 3072   // 3*DQ

// Scratch (device globals — no allocation allowed). u32 = packed fp16x2.
__device__ float    g_qkv[(size_t)BQ * TQ * ROW3];   // fp32 qkv
__device__ uint32_t g_xh [(size_t)BQ * TQ * DQ / 2]; // x split hi
__device__ uint32_t g_xl [(size_t)BQ * TQ * DQ / 2]; // x split lo
__device__ uint32_t g_w1h[(size_t)ROW3 * DQ / 2];    // Wqkv hi
__device__ uint32_t g_w2h[(size_t)DQ * DQ / 2];      // Wout hi
__device__ uint32_t g_ah [(size_t)BQ * TQ * DQ / 2]; // attention out hi
__device__ uint32_t g_al [(size_t)BQ * TQ * DQ / 2]; // attention out lo
// head-major [b][h][t][64] fp16 tensors for attention
__device__ __half   g_qnh[(size_t)BQ * HQ * TQ * HDQ];
__device__ __half   g_qnl[(size_t)BQ * HQ * TQ * HDQ];
__device__ __half   g_knh[(size_t)BQ * HQ * TQ * HDQ];
__device__ __half   g_knl[(size_t)BQ * HQ * TQ * HDQ];
__device__ __half   g_vh2[(size_t)BQ * HQ * TQ * HDQ];

typedef unsigned long long ull;

__device__ __forceinline__ unsigned su32(const void* p) {
    return (unsigned)__cvta_generic_to_shared(p);
}

// ---------------------------------------------------------------------------
// Warp-level tensor-core + async-copy primitives (base-target PTX)
// ---------------------------------------------------------------------------
#define LDSM_X4(r0, r1, r2, r3, addr) \
    asm volatile("ldmatrix.sync.aligned.m8n8.x4.shared.b16 {%0,%1,%2,%3}, [%4];" \
        : "=r"(r0), "=r"(r1), "=r"(r2), "=r"(r3) : "r"(addr))

#define LDSM_X4_T(r0, r1, r2, r3, addr) \
    asm volatile("ldmatrix.sync.aligned.m8n8.x4.trans.shared.b16 {%0,%1,%2,%3}, [%4];" \
        : "=r"(r0), "=r"(r1), "=r"(r2), "=r"(r3) : "r"(addr))

#define MMAH(c, a, b0, b1) \
    asm volatile("mma.sync.aligned.m16n8k16.row.col.f32.f16.f16.f32 " \
        "{%0,%1,%2,%3}, {%4,%5,%6,%7}, {%8,%9}, {%0,%1,%2,%3};" \
        : "+f"((c)[0]), "+f"((c)[1]), "+f"((c)[2]), "+f"((c)[3]) \
        : "r"((a)[0]), "r"((a)[1]), "r"((a)[2]), "r"((a)[3]), "r"(b0), "r"(b1))

#define CP16(dst, src) \
    asm volatile("cp.async.cg.shared.global [%0], [%1], 16;" :: "r"(dst), "l"(src))
#define CP_COMMIT() asm volatile("cp.async.commit_group;" ::: "memory")
#define CP_WAIT(n)  asm volatile("cp.async.wait_group %0;" :: "n"(n) : "memory")

// pack two fp16 (from floats) into one u32 (lo = first arg)
__device__ __forceinline__ uint32_t packh2(float lo, float hi) {
    __half2 t = __halves2half2(__float2half_rn(lo), __float2half_rn(hi));
    return *reinterpret_cast<uint32_t*>(&t);
}

// Split a float4 into packed fp16x2 hi and lo (lo = rounded residual)
__device__ __forceinline__ void split4h(float4 f, uint32_t& h0, uint32_t& h1,
                                        uint32_t& l0, uint32_t& l1) {
    const __half hx = __float2half_rn(f.x), hy = __float2half_rn(f.y);
    const __half hz = __float2half_rn(f.z), hw = __float2half_rn(f.w);
    {
        __half2 t = __halves2half2(hx, hy);
        h0 = *reinterpret_cast<uint32_t*>(&t);
        __half2 u = __halves2half2(hz, hw);
        h1 = *reinterpret_cast<uint32_t*>(&u);
    }
    l0 = packh2(f.x - __half2float(hx), f.y - __half2float(hy));
    l1 = packh2(f.z - __half2float(hz), f.w - __half2float(hw));
}

// Pack two fp32 into fp16x2 hi + residual lo
__device__ __forceinline__ void packsplit2h(float w0, float w1,
                                            uint32_t& h, uint32_t& l) {
    const __half h0 = __float2half_rn(w0), h1 = __float2half_rn(w1);
    __half2 t = __halves2half2(h0, h1);
    h = *reinterpret_cast<uint32_t*>(&t);
    l = packh2(w0 - __half2float(h0), w1 - __half2float(h1));
}

#define RCPA(d, a) \
    asm("rcp.approx.f32 %0, %1;" : "=f"(d) : "f"(a))

// ---------------------------------------------------------------------------
// Converts: fp32 -> packed fp16x2 hi/lo (or hi only, for weights)
// ---------------------------------------------------------------------------
__global__ __launch_bounds__(256) void split_f16(const float* __restrict__ src,
                                                 uint32_t* __restrict__ hi,
                                                 uint32_t* __restrict__ lo, int n4) {
    const int i = blockIdx.x * blockDim.x + threadIdx.x;
    if (i < n4) {
        float4 f = ((const float4*)src)[i];
        uint32_t h0, h1, l0, l1;
        split4h(f, h0, h1, l0, l1);
        hi[2 * i] = h0; hi[2 * i + 1] = h1;
        lo[2 * i] = l0; lo[2 * i + 1] = l1;
    }
}

__global__ __launch_bounds__(256) void conv_f16(const float* __restrict__ src,
                                                uint32_t* __restrict__ hi, int n4) {
    const int i = blockIdx.x * blockDim.x + threadIdx.x;
    if (i < n4) {
        float4 f = ((const float4*)src)[i];
        hi[2 * i]     = packh2(f.x, f.y);
        hi[2 * i + 1] = packh2(f.z, f.w);
    }
}

// ---------------------------------------------------------------------------
// prep_qkv: one warp per (part, token, head) 64-elem row of fp32 qkv.
// part 0: q -> L2-normalize -> split fp16 hi/lo -> g_qnh/g_qnl (head-major)
// part 1: k -> same -> g_knh/g_knl
// part 2: v -> fp16 hi only -> g_vh2
// ---------------------------------------------------------------------------
__global__ __launch_bounds__(256) void prep_qkv(const float* __restrict__ qkv,
                                                __half* __restrict__ qnh,
                                                __half* __restrict__ qnl,
                                                __half* __restrict__ knh,
                                                __half* __restrict__ knl,
                                                __half* __restrict__ vh) {
    const int gw   = (blockIdx.x * blockDim.x + threadIdx.x) >> 5;
    const int lane = threadIdx.x & 31;
    const int part = gw >> 16;                 // 0..2
    const int rem  = gw & 65535;
    const int bt   = rem >> 4;                 // token index (b*TQ + t)
    const int h    = rem & 15;

    const float* p = qkv + (size_t)bt * ROW3 + part * DQ + h * HDQ;
    float v0 = p[lane];
    float v1 = p[lane + 32];

    const int b = bt / TQ, t = bt & (TQ - 1);
    const size_t dst = (((size_t)(b * HQ + h)) * TQ + t) * HDQ;

    if (part == 2) {
        vh[dst + lane]      = __float2half_rn(v0);
        vh[dst + lane + 32] = __float2half_rn(v1);
        return;
    }

    float ss = v0 * v0 + v1 * v1;
#pragma unroll
    for (int m = 16; m; m >>= 1) ss += __shfl_xor_sync(0xffffffffu, ss, m);
    const float s = 1.0f / fmaxf(sqrtf(ss), 1e-12f);
    v0 *= s; v1 *= s;

    __half* oh = (part == 0) ? qnh : knh;
    __half* ol = (part == 0) ? qnl : knl;
    const __half h0 = __float2half_rn(v0);
    const __half h1 = __float2half_rn(v1);
    oh[dst + lane]      = h0;
    oh[dst + lane + 32] = h1;
    ol[dst + lane]      = __float2half_rn(v0 - __half2float(h0));
    ol[dst + lane + 32] = __float2half_rn(v1 - __half2float(h1));
}

// ---------------------------------------------------------------------------
// Pipelined fp16x2 GEMM (unchanged from R9): C = (Ah+Al) @ Bh^T.
// ---------------------------------------------------------------------------
#define RSTR 80
#define NSTG 3
#define STG_BYTES 30720
#define OFF_AH 0
#define OFF_AL 10240
#define OFF_BH 20480
#define GEMM_SMEM (NSTG * STG_BYTES)

extern __shared__ unsigned char g_dsm[];

__global__ __launch_bounds__(256, 2) void gemm_f16_2p(
    const uint16_t* __restrict__ Ah, const uint16_t* __restrict__ Al,
    const uint16_t* __restrict__ Bh,
    float* __restrict__ C, int M, int N, int K) {

    const int tid  = threadIdx.x;
    const int wid  = tid >> 5;
    const int lane = tid & 31;
    const int wm   = wid & 3;
    const int wn   = wid >> 2;

    const int row0 = blockIdx.y * 128;
    const int col0 = blockIdx.x * 128;

    const int lr = (lane & 7) + ((lane >> 3) & 1) * 8;
    const int lk = (lane >> 4) * 16;

    const unsigned sb = su32(g_dsm);

    const int r0p = (tid * 2) >> 2,     s0p = (tid * 2) & 3;
    const int r1p = (tid * 2 + 1) >> 2, s1p = (tid * 2 + 1) & 3;

    auto issue = [&](int c) {
        const unsigned base = sb + (unsigned)(c % NSTG) * STG_BYTES;
        const int k0 = c * 32;
        const unsigned d0 = base + (unsigned)(r0p * RSTR + s0p * 16);
        const unsigned d1 = base + (unsigned)(r1p * RSTR + s1p * 16);
        const size_t a0 = (size_t)(row0 + r0p) * K + k0 + s0p * 8;
        const size_t a1 = (size_t)(row0 + r1p) * K + k0 + s1p * 8;
        CP16(d0 + OFF_AH, Ah + a0);
        CP16(d1 + OFF_AH, Ah + a1);
        CP16(d0 + OFF_AL, Al + a0);
        CP16(d1 + OFF_AL, Al + a1);
        const size_t b0 = (size_t)(col0 + r0p) * K + k0 + s0p * 8;
        const size_t b1 = (size_t)(col0 + r1p) * K + k0 + s1p * 8;
        CP16(d0 + OFF_BH, Bh + b0);
        CP16(d1 + OFF_BH, Bh + b1);
    };

    float acc[2][8][4];
#pragma unroll
    for (int mt = 0; mt < 2; mt++)
#pragma unroll
        for (int nt = 0; nt < 8; nt++)
#pragma unroll
            for (int e = 0; e < 4; e++) acc[mt][nt][e] = 0.0f;

    const int nchunks = K / 32;

    issue(0); CP_COMMIT();
    issue(1); CP_COMMIT();

    for (int j = 0; j < nchunks; j++) {
        CP_WAIT(1);
        __syncthreads();

        if (j + 2 < nchunks) issue(j + 2);
        CP_COMMIT();

        const unsigned base = sb + (unsigned)(j % NSTG) * STG_BYTES;
        const unsigned aH = base + OFF_AH, aL = base + OFF_AL;
        const unsigned bH = base + OFF_BH;

#pragma unroll
        for (int ks = 0; ks < 2; ks++) {
            const unsigned kb = (unsigned)(ks * 32 + lk);
            uint32_t ah[2][4], al[2][4];
#pragma unroll
            for (int mt = 0; mt < 2; mt++) {
                const unsigned ro = (unsigned)((wm * 32 + mt * 16 + lr) * RSTR) + kb;
                LDSM_X4(ah[mt][0], ah[mt][1], ah[mt][2], ah[mt][3], aH + ro);
                LDSM_X4(al[mt][0], al[mt][1], al[mt][2], al[mt][3], aL + ro);
            }
            uint32_t bh[4][4];
#pragma unroll
            for (int np = 0; np < 4; np++) {
                const unsigned ro = (unsigned)((wn * 64 + np * 16 + lr) * RSTR) + kb;
                LDSM_X4(bh[np][0], bh[np][1], bh[np][2], bh[np][3], bH + ro);
            }
#pragma unroll
            for (int mt = 0; mt < 2; mt++)
#pragma unroll
                for (int nt = 0; nt < 8; nt++) {
                    const int np = nt >> 1, sel = nt & 1;
                    MMAH(acc[mt][nt], ah[mt], bh[np][sel], bh[np][sel + 2]);
                }
#pragma unroll
            for (int mt = 0; mt < 2; mt++)
#pragma unroll
                for (int nt = 0; nt < 8; nt++) {
                    const int np = nt >> 1, sel = nt & 1;
                    MMAH(acc[mt][nt], al[mt], bh[np][sel], bh[np][sel + 2]);
                }
        }
    }

    const int er = lane >> 2;
    const int ec = (lane & 3) * 2;
#pragma unroll
    for (int mt = 0; mt < 2; mt++) {
        const int row = row0 + wm * 32 + mt * 16 + er;
#pragma unroll
        for (int nt = 0; nt < 8; nt++) {
            const int col = col0 + wn * 64 + nt * 8 + ec;
            *(float2*)(C + (size_t)row * N + col) =
                make_float2(acc[mt][nt][0], acc[mt][nt][1]);
            *(float2*)(C + (size_t)(row + 8) * N + col) =
                make_float2(acc[mt][nt][2], acc[mt][nt][3]);
        }
    }
}

// ---------------------------------------------------------------------------
// Causal yat attention: cp.async double-buffered pre-split fp16 K/V tiles.
// S phase fp16 3-pass (qh*kh + qh*kl + ql*kh); V phase 2-pass ((wh+wl)*vh).
// Stage = KH | KL | VH tiles, 64 rows x 144B each. 2 stages, dynamic smem.
// Epilogue writes pre-split fp16 hi/lo for the out-proj GEMM.
// ---------------------------------------------------------------------------
#define VR 144
#define OFF_KL (64 * VR)
#define OFF_VH (128 * VR)
#define AST (192 * VR)        // 27648 B per stage
#define ATT_SMEM (2 * AST)    // 55296 B

__global__ __launch_bounds__(128) void yat_attn_tc(
    const __half* __restrict__ qnh, const __half* __restrict__ qnl,
    const __half* __restrict__ knh, const __half* __restrict__ knl,
    const __half* __restrict__ vh,
    uint32_t* __restrict__ ath, uint32_t* __restrict__ atl) {

    const int tid  = threadIdx.x;
    const int wid  = tid >> 5;
    const int lane = tid & 31;

    const int qt = (int)gridDim.x - 1 - (int)blockIdx.x;  // longest first
    const int h  = blockIdx.y;
    const int b  = blockIdx.z;
    const int q0 = qt * 64;

    const int lr = (lane & 7) + ((lane >> 3) & 1) * 8;
    const int lk = (lane >> 4) * 16;

    const unsigned sb = su32(g_dsm);
    const size_t headBase = ((size_t)(b * HQ + h)) * TQ;

    // per-thread cp.async mapping: 16B segment seg of rows rb, rb+16, rb+32, rb+48
    const int seg = tid & 7;
    const int rb  = tid >> 3;

    // ---- stage Q (hi/lo) into stage 0, pull A-fragments ----
#pragma unroll
    for (int i = 0; i < 4; i++) {
        const int r = rb + 16 * i;
        const size_t so = (headBase + q0 + r) * HDQ + seg * 8;
        const unsigned dofs = (unsigned)(r * VR + seg * 16);
        CP16(sb + dofs,          qnh + so);
        CP16(sb + OFF_KL + dofs, qnl + so);
    }
    CP_COMMIT();
    CP_WAIT(0);
    __syncthreads();

    uint32_t qfh[4][4], qfl[4][4];
#pragma unroll
    for (int kc = 0; kc < 4; kc++) {
        const unsigned ro = (unsigned)((wid * 16 + lr) * VR + kc * 32 + lk);
        LDSM_X4(qfh[kc][0], qfh[kc][1], qfh[kc][2], qfh[kc][3], sb + ro);
        LDSM_X4(qfl[kc][0], qfl[kc][1], qfl[kc][2], qfl[kc][3], sb + OFF_KL + ro);
    }
    __syncthreads();   // Q frags pulled; stage 0 free

    auto issueKV = [&](int kt) {
        const unsigned base = sb + (unsigned)(kt & 1) * AST;
        const size_t tok = headBase + (size_t)kt * 64;
#pragma unroll
        for (int i = 0; i < 4; i++) {
            const int r = rb + 16 * i;
            const size_t so = (tok + r) * HDQ + seg * 8;
            const unsigned dofs = (unsigned)(r * VR + seg * 16);
            CP16(base + dofs,          knh + so);
            CP16(base + OFF_KL + dofs, knl + so);
            CP16(base + OFF_VH + dofs, vh + so);
        }
    };

    float accO[8][4];
#pragma unroll
    for (int nt = 0; nt < 8; nt++)
#pragma unroll
        for (int e = 0; e < 4; e++) accO[nt][e] = 0.0f;
    float dsum0 = 0.0f, dsum1 = 0.0f;

    const int qg0 = q0 + wid * 16 + (lane >> 2);

    issueKV(0); CP_COMMIT();

    for (int kt = 0; kt <= qt; kt++) {
        CP_WAIT(0);         // tile kt arrived
        __syncthreads();    // + all warps done with the buffer being refilled

        if (kt + 1 <= qt) issueKV(kt + 1);
        CP_COMMIT();

        const unsigned base = sb + (unsigned)(kt & 1) * AST;
        const unsigned kH = base, kL = base + OFF_KL, vHb = base + OFF_VH;

        // ---- S = Qn Kn^T (fp16 3-pass) ----
        float sf[8][4];
#pragma unroll
        for (int nt = 0; nt < 8; nt++)
#pragma unroll
            for (int e = 0; e < 4; e++) sf[nt][e] = 0.0f;

#pragma unroll
        for (int kc = 0; kc < 4; kc++) {
#pragma unroll
            for (int g = 0; g < 4; g++) {
                uint32_t khf[4], klf[4];
                const unsigned ro = (unsigned)((g * 16 + lr) * VR + kc * 32 + lk);
                LDSM_X4(khf[0], khf[1], khf[2], khf[3], kH + ro);
                LDSM_X4(klf[0], klf[1], klf[2], klf[3], kL + ro);
                MMAH(sf[2 * g],     qfh[kc], khf[0], khf[2]);
                MMAH(sf[2 * g + 1], qfh[kc], khf[1], khf[3]);
                MMAH(sf[2 * g],     qfh[kc], klf[0], klf[2]);
                MMAH(sf[2 * g + 1], qfh[kc], klf[1], klf[3]);
                MMAH(sf[2 * g],     qfl[kc], khf[0], khf[2]);
                MMAH(sf[2 * g + 1], qfl[kc], khf[1], khf[3]);
            }
        }

        // ---- transform to w, mask, den, repack ----
        const bool diag = (kt == qt);
        uint32_t w01h[8], w01l[8], w23h[8], w23l[8];
#pragma unroll
        for (int nt = 0; nt < 8; nt++) {
            float w[4];
#pragma unroll
            for (int e = 0; e < 4; e++) {
                const float d = sf[nt][e];
                const float den = fmaxf(fmaf(-2.0f, d, 2.01f), 1e-6f);
                float rc; RCPA(rc, den);
                w[e] = d * d * rc;
            }
            if (diag) {
                const int kg = kt * 64 + nt * 8 + 2 * (lane & 3);
                if (kg     > qg0)     w[0] = 0.0f;
                if (kg + 1 > qg0)     w[1] = 0.0f;
                if (kg     > qg0 + 8) w[2] = 0.0f;
                if (kg + 1 > qg0 + 8) w[3] = 0.0f;
            }
            dsum0 += w[0] + w[1];
            dsum1 += w[2] + w[3];
            packsplit2h(w[0], w[1], w01h[nt], w01l[nt]);
            packsplit2h(w[2], w[3], w23h[nt], w23l[nt]);
        }

        // ---- O += (wh+wl) @ Vh (fp16 2-pass, V via ldmatrix.trans) ----
#pragma unroll
        for (int kc2 = 0; kc2 < 4; kc2++) {
            uint32_t ah[4] = {w01h[2 * kc2], w23h[2 * kc2],
                              w01h[2 * kc2 + 1], w23h[2 * kc2 + 1]};
            uint32_t al[4] = {w01l[2 * kc2], w23l[2 * kc2],
                              w01l[2 * kc2 + 1], w23l[2 * kc2 + 1]};
#pragma unroll
            for (int g = 0; g < 4; g++) {
                uint32_t vhf[4];
                const unsigned ro = (unsigned)((kc2 * 16 + lr) * VR + g * 32 + lk);
                LDSM_X4_T(vhf[0], vhf[1], vhf[2], vhf[3], vHb + ro);
                MMAH(accO[2 * g],     ah, vhf[0], vhf[1]);
                MMAH(accO[2 * g + 1], ah, vhf[2], vhf[3]);
                MMAH(accO[2 * g],     al, vhf[0], vhf[1]);
                MMAH(accO[2 * g + 1], al, vhf[2], vhf[3]);
            }
        }
        __syncthreads();   // done reading buffer (refill of this buf is next iter+1)
    }

    // ---- epilogue: reduce den, divide, write SPLIT fp16 ----
    dsum0 += __shfl_xor_sync(0xffffffffu, dsum0, 1);
    dsum0 += __shfl_xor_sync(0xffffffffu, dsum0, 2);
    dsum1 += __shfl_xor_sync(0xffffffffu, dsum1, 1);
    dsum1 += __shfl_xor_sync(0xffffffffu, dsum1, 2);
    float inv0, inv1;
    RCPA(inv0, dsum0 + 1e-6f);
    RCPA(inv1, dsum1 + 1e-6f);

    const size_t rowg  = (size_t)(b * TQ) + q0 + wid * 16 + (lane >> 2);
    const int    colb2 = h * (HDQ / 2) + (lane & 3);
#pragma unroll
    for (int nt = 0; nt < 8; nt++) {
        uint32_t hh, ll;
        packsplit2h(accO[nt][0] * inv0, accO[nt][1] * inv0, hh, ll);
        ath[rowg * (DQ / 2) + colb2 + nt * 4] = hh;
        atl[rowg * (DQ / 2) + colb2 + nt * 4] = ll;
        packsplit2h(accO[nt][2] * inv1, accO[nt][3] * inv1, hh, ll);
        ath[(rowg + 8) * (DQ / 2) + colb2 + nt * 4] = hh;
        atl[(rowg + 8) * (DQ / 2) + colb2 + nt * 4] = ll;
    }
}

// ---------------------------------------------------------------------------
// kernel_launch
// ---------------------------------------------------------------------------
extern "C" void kernel_launch(void* const* d_in, const int* in_sizes, int n_in,
                              void* d_out, int out_size) {
    (void)in_sizes; (void)n_in; (void)out_size;
    const float* x    = (const float*)d_in[0];   // [B,T,D]
    const float* Wqkv = (const float*)d_in[1];   // [3D, D]
    const float* Wout = (const float*)d_in[2];   // [D, D]
    float* out = (float*)d_out;                  // [B,T,D]

    void *p_qkv, *p_xh, *p_xl, *p_w1h, *p_w2h, *p_ah, *p_al;
    void *p_qnh, *p_qnl, *p_knh, *p_knl, *p_vh;
    cudaGetSymbolAddress(&p_qkv, g_qkv);
    cudaGetSymbolAddress(&p_xh, g_xh);   cudaGetSymbolAddress(&p_xl, g_xl);
    cudaGetSymbolAddress(&p_w1h, g_w1h); cudaGetSymbolAddress(&p_w2h, g_w2h);
    cudaGetSymbolAddress(&p_ah, g_ah);   cudaGetSymbolAddress(&p_al, g_al);
    cudaGetSymbolAddress(&p_qnh, g_qnh); cudaGetSymbolAddress(&p_qnl, g_qnl);
    cudaGetSymbolAddress(&p_knh, g_knh); cudaGetSymbolAddress(&p_knl, g_knl);
    cudaGetSymbolAddress(&p_vh, g_vh2);

    static bool attr_done = false;
    if (!attr_done) {
        cudaFuncSetAttribute(gemm_f16_2p,
                             cudaFuncAttributeMaxDynamicSharedMemorySize, GEMM_SMEM);
        cudaFuncSetAttribute(yat_attn_tc,
                             cudaFuncAttributeMaxDynamicSharedMemorySize, ATT_SMEM);
        attr_done = true;
    }

    const int M = BQ * TQ;  // 4096

    // 0) convert inputs to fp16 (x: hi+lo, weights: hi only)
    split_f16<<<(M * DQ / 4) / 256, 256>>>(x, (uint32_t*)p_xh, (uint32_t*)p_xl, M * DQ / 4);
    conv_f16<<<(ROW3 * DQ / 4) / 256, 256>>>(Wqkv, (uint32_t*)p_w1h, ROW3 * DQ / 4);
    conv_f16<<<(DQ * DQ / 4) / 256, 256>>>(Wout, (uint32_t*)p_w2h, DQ * DQ / 4);

    // 1) qkv = x @ Wqkv^T : [4096,3072]
    gemm_f16_2p<<<dim3(ROW3 / 128, M / 128), 256, GEMM_SMEM>>>(
        (const uint16_t*)p_xh, (const uint16_t*)p_xl, (const uint16_t*)p_w1h,
        (float*)p_qkv, M, ROW3, DQ);

    // 2) normalize q,k + split to fp16 head-major, convert v
    prep_qkv<<<(3 * M * HQ) / 8, 256>>>((const float*)p_qkv,
        (__half*)p_qnh, (__half*)p_qnl, (__half*)p_knh, (__half*)p_knl, (__half*)p_vh);

    // 3) causal yat attention (pipelined, fp16) -> split fp16 att
    yat_attn_tc<<<dim3(TQ / 64, HQ, BQ), 128, ATT_SMEM>>>(
        (const __half*)p_qnh, (const __half*)p_qnl,
        (const __half*)p_knh, (const __half*)p_knl, (const __half*)p_vh,
        (uint32_t*)p_ah, (uint32_t*)p_al);

    // 4) out = att @ Wout^T : [4096,1024]
    gemm_f16_2p<<<dim3(DQ / 128, M / 128), 256, GEMM_SMEM>>>(
        (const uint16_t*)p_ah, (const uint16_t*)p_al, (const uint16_t*)p_w2h,
        out, M, DQ, DQ);
}

// round 11
// speedup vs baseline: 7.4014x; 1.2259x over previous
#include <cuda_runtime.h>
#include <cuda_fp16.h>
#include <cstddef>
#include <cstdint>

// Problem constants (fixed by setup_inputs)
#define BQ   2
#define TQ   2048
#define DQ   1024
#define HQ   16
#define HDQ  64
#define ROW3 3072   // 3*DQ

// Scratch (device globals — no allocation allowed). u32 = packed fp16x2.
__device__ float    g_qkv[(size_t)BQ * TQ * ROW3];   // fp32 qkv
__device__ uint32_t g_xh [(size_t)BQ * TQ * DQ / 2]; // x fp16 (hi only)
__device__ uint32_t g_w1h[(size_t)ROW3 * DQ / 2];    // Wqkv hi
__device__ uint32_t g_w2h[(size_t)DQ * DQ / 2];      // Wout hi
__device__ uint32_t g_ah [(size_t)BQ * TQ * DQ / 2]; // attention out hi
__device__ uint32_t g_al [(size_t)BQ * TQ * DQ / 2]; // attention out lo
// head-major [b][h][t][64] fp16 tensors for attention
__device__ __half   g_qnh[(size_t)BQ * HQ * TQ * HDQ];
__device__ __half   g_qnl[(size_t)BQ * HQ * TQ * HDQ];
__device__ __half   g_knh[(size_t)BQ * HQ * TQ * HDQ];
__device__ __half   g_knl[(size_t)BQ * HQ * TQ * HDQ];
__device__ __half   g_vh2[(size_t)BQ * HQ * TQ * HDQ];

typedef unsigned long long ull;

__device__ __forceinline__ unsigned su32(const void* p) {
    return (unsigned)__cvta_generic_to_shared(p);
}

// ---------------------------------------------------------------------------
// Warp-level tensor-core + async-copy primitives (base-target PTX)
// ---------------------------------------------------------------------------
#define LDSM_X4(r0, r1, r2, r3, addr) \
    asm volatile("ldmatrix.sync.aligned.m8n8.x4.shared.b16 {%0,%1,%2,%3}, [%4];" \
        : "=r"(r0), "=r"(r1), "=r"(r2), "=r"(r3) : "r"(addr))

#define LDSM_X4_T(r0, r1, r2, r3, addr) \
    asm volatile("ldmatrix.sync.aligned.m8n8.x4.trans.shared.b16 {%0,%1,%2,%3}, [%4];" \
        : "=r"(r0), "=r"(r1), "=r"(r2), "=r"(r3) : "r"(addr))

#define MMAH(c, a, b0, b1) \
    asm volatile("mma.sync.aligned.m16n8k16.row.col.f32.f16.f16.f32 " \
        "{%0,%1,%2,%3}, {%4,%5,%6,%7}, {%8,%9}, {%0,%1,%2,%3};" \
        : "+f"((c)[0]), "+f"((c)[1]), "+f"((c)[2]), "+f"((c)[3]) \
        : "r"((a)[0]), "r"((a)[1]), "r"((a)[2]), "r"((a)[3]), "r"(b0), "r"(b1))

#define CP16(dst, src) \
    asm volatile("cp.async.cg.shared.global [%0], [%1], 16;" :: "r"(dst), "l"(src))
#define CP_COMMIT() asm volatile("cp.async.commit_group;" ::: "memory")
#define CP_WAIT(n)  asm volatile("cp.async.wait_group %0;" :: "n"(n) : "memory")

// pack two fp16 (from floats) into one u32 (lo = first arg)
__device__ __forceinline__ uint32_t packh2(float lo, float hi) {
    __half2 t = __halves2half2(__float2half_rn(lo), __float2half_rn(hi));
    return *reinterpret_cast<uint32_t*>(&t);
}

// Pack two fp32 into fp16x2 hi + residual lo
__device__ __forceinline__ void packsplit2h(float w0, float w1,
                                            uint32_t& h, uint32_t& l) {
    const __half h0 = __float2half_rn(w0), h1 = __float2half_rn(w1);
    __half2 t = __halves2half2(h0, h1);
    h = *reinterpret_cast<uint32_t*>(&t);
    l = packh2(w0 - __half2float(h0), w1 - __half2float(h1));
}

#define RCPA(d, a) \
    asm("rcp.approx.f32 %0, %1;" : "=f"(d) : "f"(a))

// ---------------------------------------------------------------------------
// Convert: fp32 -> packed fp16 (hi only)
// ---------------------------------------------------------------------------
__global__ __launch_bounds__(256) void conv_f16(const float* __restrict__ src,
                                                uint32_t* __restrict__ hi, int n4) {
    const int i = blockIdx.x * blockDim.x + threadIdx.x;
    if (i < n4) {
        float4 f = ((const float4*)src)[i];
        hi[2 * i]     = packh2(f.x, f.y);
        hi[2 * i + 1] = packh2(f.z, f.w);
    }
}

// ---------------------------------------------------------------------------
// prep_qkv: one warp per (part, token, head) 64-elem row of fp32 qkv.
// part 0: q -> L2-normalize -> split fp16 hi/lo -> g_qnh/g_qnl (head-major)
// part 1: k -> same -> g_knh/g_knl
// part 2: v -> fp16 hi only -> g_vh2
// ---------------------------------------------------------------------------
__global__ __launch_bounds__(256) void prep_qkv(const float* __restrict__ qkv,
                                                __half* __restrict__ qnh,
                                                __half* __restrict__ qnl,
                                                __half* __restrict__ knh,
                                                __half* __restrict__ knl,
                                                __half* __restrict__ vh) {
    const int gw   = (blockIdx.x * blockDim.x + threadIdx.x) >> 5;
    const int lane = threadIdx.x & 31;
    const int part = gw >> 16;                 // 0..2
    const int rem  = gw & 65535;
    const int bt   = rem >> 4;                 // token index (b*TQ + t)
    const int h    = rem & 15;

    const float* p = qkv + (size_t)bt * ROW3 + part * DQ + h * HDQ;
    float v0 = p[lane];
    float v1 = p[lane + 32];

    const int b = bt / TQ, t = bt & (TQ - 1);
    const size_t dst = (((size_t)(b * HQ + h)) * TQ + t) * HDQ;

    if (part == 2) {
        vh[dst + lane]      = __float2half_rn(v0);
        vh[dst + lane + 32] = __float2half_rn(v1);
        return;
    }

    float ss = v0 * v0 + v1 * v1;
#pragma unroll
    for (int m = 16; m; m >>= 1) ss += __shfl_xor_sync(0xffffffffu, ss, m);
    const float s = 1.0f / fmaxf(sqrtf(ss), 1e-12f);
    v0 *= s; v1 *= s;

    __half* oh = (part == 0) ? qnh : knh;
    __half* ol = (part == 0) ? qnl : knl;
    const __half h0 = __float2half_rn(v0);
    const __half h1 = __float2half_rn(v1);
    oh[dst + lane]      = h0;
    oh[dst + lane + 32] = h1;
    ol[dst + lane]      = __float2half_rn(v0 - __half2float(h0));
    ol[dst + lane + 32] = __float2half_rn(v1 - __half2float(h1));
}

// ---------------------------------------------------------------------------
// GEMM smem layout constants
// ---------------------------------------------------------------------------
#define RSTR 80
#define NSTG 3
// 2-pass variant (A hi/lo + B hi)
#define STG2 30720
#define OFF_AH 0
#define OFF_AL 10240
#define OFF_BH 20480
#define GEMM2_SMEM (NSTG * STG2)
// 1-pass variant (A hi + B hi)
#define STG1 20480
#define OFF1_BH 10240
#define GEMM1_SMEM (NSTG * STG1)

extern __shared__ unsigned char g_dsm[];

// ---------------------------------------------------------------------------
// 1-pass fp16 GEMM: C[M,N] = Ah[M,K] @ Bh[N,K]^T  (both hi-only)
// ---------------------------------------------------------------------------
__global__ __launch_bounds__(256, 2) void gemm_f16_1p(
    const uint16_t* __restrict__ Ah, const uint16_t* __restrict__ Bh,
    float* __restrict__ C, int M, int N, int K) {

    const int tid  = threadIdx.x;
    const int wid  = tid >> 5;
    const int lane = tid & 31;
    const int wm   = wid & 3;
    const int wn   = wid >> 2;

    const int row0 = blockIdx.y * 128;
    const int col0 = blockIdx.x * 128;

    const int lr = (lane & 7) + ((lane >> 3) & 1) * 8;
    const int lk = (lane >> 4) * 16;

    const unsigned sb = su32(g_dsm);

    const int r0p = (tid * 2) >> 2,     s0p = (tid * 2) & 3;
    const int r1p = (tid * 2 + 1) >> 2, s1p = (tid * 2 + 1) & 3;

    auto issue = [&](int c) {
        const unsigned base = sb + (unsigned)(c % NSTG) * STG1;
        const int k0 = c * 32;
        const unsigned d0 = base + (unsigned)(r0p * RSTR + s0p * 16);
        const unsigned d1 = base + (unsigned)(r1p * RSTR + s1p * 16);
        const size_t a0 = (size_t)(row0 + r0p) * K + k0 + s0p * 8;
        const size_t a1 = (size_t)(row0 + r1p) * K + k0 + s1p * 8;
        CP16(d0, Ah + a0);
        CP16(d1, Ah + a1);
        const size_t b0 = (size_t)(col0 + r0p) * K + k0 + s0p * 8;
        const size_t b1 = (size_t)(col0 + r1p) * K + k0 + s1p * 8;
        CP16(d0 + OFF1_BH, Bh + b0);
        CP16(d1 + OFF1_BH, Bh + b1);
    };

    float acc[2][8][4];
#pragma unroll
    for (int mt = 0; mt < 2; mt++)
#pragma unroll
        for (int nt = 0; nt < 8; nt++)
#pragma unroll
            for (int e = 0; e < 4; e++) acc[mt][nt][e] = 0.0f;

    const int nchunks = K / 32;

    issue(0); CP_COMMIT();
    issue(1); CP_COMMIT();

    for (int j = 0; j < nchunks; j++) {
        CP_WAIT(1);
        __syncthreads();

        if (j + 2 < nchunks) issue(j + 2);
        CP_COMMIT();

        const unsigned base = sb + (unsigned)(j % NSTG) * STG1;
        const unsigned aH = base, bH = base + OFF1_BH;

#pragma unroll
        for (int ks = 0; ks < 2; ks++) {
            const unsigned kb = (unsigned)(ks * 32 + lk);
            uint32_t ah[2][4];
#pragma unroll
            for (int mt = 0; mt < 2; mt++) {
                const unsigned ro = (unsigned)((wm * 32 + mt * 16 + lr) * RSTR) + kb;
                LDSM_X4(ah[mt][0], ah[mt][1], ah[mt][2], ah[mt][3], aH + ro);
            }
            uint32_t bh[4][4];
#pragma unroll
            for (int np = 0; np < 4; np++) {
                const unsigned ro = (unsigned)((wn * 64 + np * 16 + lr) * RSTR) + kb;
                LDSM_X4(bh[np][0], bh[np][1], bh[np][2], bh[np][3], bH + ro);
            }
#pragma unroll
            for (int mt = 0; mt < 2; mt++)
#pragma unroll
                for (int nt = 0; nt < 8; nt++) {
                    const int np = nt >> 1, sel = nt & 1;
                    MMAH(acc[mt][nt], ah[mt], bh[np][sel], bh[np][sel + 2]);
                }
        }
    }

    const int er = lane >> 2;
    const int ec = (lane & 3) * 2;
#pragma unroll
    for (int mt = 0; mt < 2; mt++) {
        const int row = row0 + wm * 32 + mt * 16 + er;
#pragma unroll
        for (int nt = 0; nt < 8; nt++) {
            const int col = col0 + wn * 64 + nt * 8 + ec;
            *(float2*)(C + (size_t)row * N + col) =
                make_float2(acc[mt][nt][0], acc[mt][nt][1]);
            *(float2*)(C + (size_t)(row + 8) * N + col) =
                make_float2(acc[mt][nt][2], acc[mt][nt][3]);
        }
    }
}

// ---------------------------------------------------------------------------
// 2-pass fp16 GEMM: C = (Ah+Al) @ Bh^T  (A corrected; used for out-proj)
// ---------------------------------------------------------------------------
__global__ __launch_bounds__(256, 2) void gemm_f16_2p(
    const uint16_t* __restrict__ Ah, const uint16_t* __restrict__ Al,
    const uint16_t* __restrict__ Bh,
    float* __restrict__ C, int M, int N, int K) {

    const int tid  = threadIdx.x;
    const int wid  = tid >> 5;
    const int lane = tid & 31;
    const int wm   = wid & 3;
    const int wn   = wid >> 2;

    const int row0 = blockIdx.y * 128;
    const int col0 = blockIdx.x * 128;

    const int lr = (lane & 7) + ((lane >> 3) & 1) * 8;
    const int lk = (lane >> 4) * 16;

    const unsigned sb = su32(g_dsm);

    const int r0p = (tid * 2) >> 2,     s0p = (tid * 2) & 3;
    const int r1p = (tid * 2 + 1) >> 2, s1p = (tid * 2 + 1) & 3;

    auto issue = [&](int c) {
        const unsigned base = sb + (unsigned)(c % NSTG) * STG2;
        const int k0 = c * 32;
        const unsigned d0 = base + (unsigned)(r0p * RSTR + s0p * 16);
        const unsigned d1 = base + (unsigned)(r1p * RSTR + s1p * 16);
        const size_t a0 = (size_t)(row0 + r0p) * K + k0 + s0p * 8;
        const size_t a1 = (size_t)(row0 + r1p) * K + k0 + s1p * 8;
        CP16(d0 + OFF_AH, Ah + a0);
        CP16(d1 + OFF_AH, Ah + a1);
        CP16(d0 + OFF_AL, Al + a0);
        CP16(d1 + OFF_AL, Al + a1);
        const size_t b0 = (size_t)(col0 + r0p) * K + k0 + s0p * 8;
        const size_t b1 = (size_t)(col0 + r1p) * K + k0 + s1p * 8;
        CP16(d0 + OFF_BH, Bh + b0);
        CP16(d1 + OFF_BH, Bh + b1);
    };

    float acc[2][8][4];
#pragma unroll
    for (int mt = 0; mt < 2; mt++)
#pragma unroll
        for (int nt = 0; nt < 8; nt++)
#pragma unroll
            for (int e = 0; e < 4; e++) acc[mt][nt][e] = 0.0f;

    const int nchunks = K / 32;

    issue(0); CP_COMMIT();
    issue(1); CP_COMMIT();

    for (int j = 0; j < nchunks; j++) {
        CP_WAIT(1);
        __syncthreads();

        if (j + 2 < nchunks) issue(j + 2);
        CP_COMMIT();

        const unsigned base = sb + (unsigned)(j % NSTG) * STG2;
        const unsigned aH = base + OFF_AH, aL = base + OFF_AL;
        const unsigned bH = base + OFF_BH;

#pragma unroll
        for (int ks = 0; ks < 2; ks++) {
            const unsigned kb = (unsigned)(ks * 32 + lk);
            uint32_t ah[2][4], al[2][4];
#pragma unroll
            for (int mt = 0; mt < 2; mt++) {
                const unsigned ro = (unsigned)((wm * 32 + mt * 16 + lr) * RSTR) + kb;
                LDSM_X4(ah[mt][0], ah[mt][1], ah[mt][2], ah[mt][3], aH + ro);
                LDSM_X4(al[mt][0], al[mt][1], al[mt][2], al[mt][3], aL + ro);
            }
            uint32_t bh[4][4];
#pragma unroll
            for (int np = 0; np < 4; np++) {
                const unsigned ro = (unsigned)((wn * 64 + np * 16 + lr) * RSTR) + kb;
                LDSM_X4(bh[np][0], bh[np][1], bh[np][2], bh[np][3], bH + ro);
            }
#pragma unroll
            for (int mt = 0; mt < 2; mt++)
#pragma unroll
                for (int nt = 0; nt < 8; nt++) {
                    const int np = nt >> 1, sel = nt & 1;
                    MMAH(acc[mt][nt], ah[mt], bh[np][sel], bh[np][sel + 2]);
                }
#pragma unroll
            for (int mt = 0; mt < 2; mt++)
#pragma unroll
                for (int nt = 0; nt < 8; nt++) {
                    const int np = nt >> 1, sel = nt & 1;
                    MMAH(acc[mt][nt], al[mt], bh[np][sel], bh[np][sel + 2]);
                }
        }
    }

    const int er = lane >> 2;
    const int ec = (lane & 3) * 2;
#pragma unroll
    for (int mt = 0; mt < 2; mt++) {
        const int row = row0 + wm * 32 + mt * 16 + er;
#pragma unroll
        for (int nt = 0; nt < 8; nt++) {
            const int col = col0 + wn * 64 + nt * 8 + ec;
            *(float2*)(C + (size_t)row * N + col) =
                make_float2(acc[mt][nt][0], acc[mt][nt][1]);
            *(float2*)(C + (size_t)(row + 8) * N + col) =
                make_float2(acc[mt][nt][2], acc[mt][nt][3]);
        }
    }
}

// ---------------------------------------------------------------------------
// Causal yat attention (unchanged from R10): cp.async double-buffered fp16
// K/V tiles; S fp16 3-pass; V 2-pass. Epilogue writes split fp16 hi/lo.
// ---------------------------------------------------------------------------
#define VR 144
#define OFF_KL (64 * VR)
#define OFF_VH (128 * VR)
#define AST (192 * VR)
#define ATT_SMEM (2 * AST)

__global__ __launch_bounds__(128) void yat_attn_tc(
    const __half* __restrict__ qnh, const __half* __restrict__ qnl,
    const __half* __restrict__ knh, const __half* __restrict__ knl,
    const __half* __restrict__ vh,
    uint32_t* __restrict__ ath, uint32_t* __restrict__ atl) {

    const int tid  = threadIdx.x;
    const int wid  = tid >> 5;
    const int lane = tid & 31;

    const int qt = (int)gridDim.x - 1 - (int)blockIdx.x;  // longest first
    const int h  = blockIdx.y;
    const int b  = blockIdx.z;
    const int q0 = qt * 64;

    const int lr = (lane & 7) + ((lane >> 3) & 1) * 8;
    const int lk = (lane >> 4) * 16;

    const unsigned sb = su32(g_dsm);
    const size_t headBase = ((size_t)(b * HQ + h)) * TQ;

    const int seg = tid & 7;
    const int rb  = tid >> 3;

    // ---- stage Q (hi/lo) into stage 0, pull A-fragments ----
#pragma unroll
    for (int i = 0; i < 4; i++) {
        const int r = rb + 16 * i;
        const size_t so = (headBase + q0 + r) * HDQ + seg * 8;
        const unsigned dofs = (unsigned)(r * VR + seg * 16);
        CP16(sb + dofs,          qnh + so);
        CP16(sb + OFF_KL + dofs, qnl + so);
    }
    CP_COMMIT();
    CP_WAIT(0);
    __syncthreads();

    uint32_t qfh[4][4], qfl[4][4];
#pragma unroll
    for (int kc = 0; kc < 4; kc++) {
        const unsigned ro = (unsigned)((wid * 16 + lr) * VR + kc * 32 + lk);
        LDSM_X4(qfh[kc][0], qfh[kc][1], qfh[kc][2], qfh[kc][3], sb + ro);
        LDSM_X4(qfl[kc][0], qfl[kc][1], qfl[kc][2], qfl[kc][3], sb + OFF_KL + ro);
    }
    __syncthreads();

    auto issueKV = [&](int kt) {
        const unsigned base = sb + (unsigned)(kt & 1) * AST;
        const size_t tok = headBase + (size_t)kt * 64;
#pragma unroll
        for (int i = 0; i < 4; i++) {
            const int r = rb + 16 * i;
            const size_t so = (tok + r) * HDQ + seg * 8;
            const unsigned dofs = (unsigned)(r * VR + seg * 16);
            CP16(base + dofs,          knh + so);
            CP16(base + OFF_KL + dofs, knl + so);
            CP16(base + OFF_VH + dofs, vh + so);
        }
    };

    float accO[8][4];
#pragma unroll
    for (int nt = 0; nt < 8; nt++)
#pragma unroll
        for (int e = 0; e < 4; e++) accO[nt][e] = 0.0f;
    float dsum0 = 0.0f, dsum1 = 0.0f;

    const int qg0 = q0 + wid * 16 + (lane >> 2);

    issueKV(0); CP_COMMIT();

    for (int kt = 0; kt <= qt; kt++) {
        CP_WAIT(0);
        __syncthreads();

        if (kt + 1 <= qt) issueKV(kt + 1);
        CP_COMMIT();

        const unsigned base = sb + (unsigned)(kt & 1) * AST;
        const unsigned kH = base, kL = base + OFF_KL, vHb = base + OFF_VH;

        // ---- S = Qn Kn^T (fp16 3-pass) ----
        float sf[8][4];
#pragma unroll
        for (int nt = 0; nt < 8; nt++)
#pragma unroll
            for (int e = 0; e < 4; e++) sf[nt][e] = 0.0f;

#pragma unroll
        for (int kc = 0; kc < 4; kc++) {
#pragma unroll
            for (int g = 0; g < 4; g++) {
                uint32_t khf[4], klf[4];
                const unsigned ro = (unsigned)((g * 16 + lr) * VR + kc * 32 + lk);
                LDSM_X4(khf[0], khf[1], khf[2], khf[3], kH + ro);
                LDSM_X4(klf[0], klf[1], klf[2], klf[3], kL + ro);
                MMAH(sf[2 * g],     qfh[kc], khf[0], khf[2]);
                MMAH(sf[2 * g + 1], qfh[kc], khf[1], khf[3]);
                MMAH(sf[2 * g],     qfh[kc], klf[0], klf[2]);
                MMAH(sf[2 * g + 1], qfh[kc], klf[1], klf[3]);
                MMAH(sf[2 * g],     qfl[kc], khf[0], khf[2]);
                MMAH(sf[2 * g + 1], qfl[kc], khf[1], khf[3]);
            }
        }

        // ---- transform to w, mask, den, repack ----
        const bool diag = (kt == qt);
        uint32_t w01h[8], w01l[8], w23h[8], w23l[8];
#pragma unroll
        for (int nt = 0; nt < 8; nt++) {
            float w[4];
#pragma unroll
            for (int e = 0; e < 4; e++) {
                const float d = sf[nt][e];
                const float den = fmaxf(fmaf(-2.0f, d, 2.01f), 1e-6f);
                float rc; RCPA(rc, den);
                w[e] = d * d * rc;
            }
            if (diag) {
                const int kg = kt * 64 + nt * 8 + 2 * (lane & 3);
                if (kg     > qg0)     w[0] = 0.0f;
                if (kg + 1 > qg0)     w[1] = 0.0f;
                if (kg     > qg0 + 8) w[2] = 0.0f;
                if (kg + 1 > qg0 + 8) w[3] = 0.0f;
            }
            dsum0 += w[0] + w[1];
            dsum1 += w[2] + w[3];
            packsplit2h(w[0], w[1], w01h[nt], w01l[nt]);
            packsplit2h(w[2], w[3], w23h[nt], w23l[nt]);
        }

        // ---- O += (wh+wl) @ Vh (fp16 2-pass, V via ldmatrix.trans) ----
#pragma unroll
        for (int kc2 = 0; kc2 < 4; kc2++) {
            uint32_t ah[4] = {w01h[2 * kc2], w23h[2 * kc2],
                              w01h[2 * kc2 + 1], w23h[2 * kc2 + 1]};
            uint32_t al[4] = {w01l[2 * kc2], w23l[2 * kc2],
                              w01l[2 * kc2 + 1], w23l[2 * kc2 + 1]};
#pragma unroll
            for (int g = 0; g < 4; g++) {
                uint32_t vhf[4];
                const unsigned ro = (unsigned)((kc2 * 16 + lr) * VR + g * 32 + lk);
                LDSM_X4_T(vhf[0], vhf[1], vhf[2], vhf[3], vHb + ro);
                MMAH(accO[2 * g],     ah, vhf[0], vhf[1]);
                MMAH(accO[2 * g + 1], ah, vhf[2], vhf[3]);
                MMAH(accO[2 * g],     al, vhf[0], vhf[1]);
                MMAH(accO[2 * g + 1], al, vhf[2], vhf[3]);
            }
        }
        __syncthreads();
    }

    // ---- epilogue: reduce den, divide, write SPLIT fp16 ----
    dsum0 += __shfl_xor_sync(0xffffffffu, dsum0, 1);
    dsum0 += __shfl_xor_sync(0xffffffffu, dsum0, 2);
    dsum1 += __shfl_xor_sync(0xffffffffu, dsum1, 1);
    dsum1 += __shfl_xor_sync(0xffffffffu, dsum1, 2);
    float inv0, inv1;
    RCPA(inv0, dsum0 + 1e-6f);
    RCPA(inv1, dsum1 + 1e-6f);

    const size_t rowg  = (size_t)(b * TQ) + q0 + wid * 16 + (lane >> 2);
    const int    colb2 = h * (HDQ / 2) + (lane & 3);
#pragma unroll
    for (int nt = 0; nt < 8; nt++) {
        uint32_t hh, ll;
        packsplit2h(accO[nt][0] * inv0, accO[nt][1] * inv0, hh, ll);
        ath[rowg * (DQ / 2) + colb2 + nt * 4] = hh;
        atl[rowg * (DQ / 2) + colb2 + nt * 4] = ll;
        packsplit2h(accO[nt][2] * inv1, accO[nt][3] * inv1, hh, ll);
        ath[(rowg + 8) * (DQ / 2) + colb2 + nt * 4] = hh;
        atl[(rowg + 8) * (DQ / 2) + colb2 + nt * 4] = ll;
    }
}

// ---------------------------------------------------------------------------
// kernel_launch
// ---------------------------------------------------------------------------
extern "C" void kernel_launch(void* const* d_in, const int* in_sizes, int n_in,
                              void* d_out, int out_size) {
    (void)in_sizes; (void)n_in; (void)out_size;
    const float* x    = (const float*)d_in[0];   // [B,T,D]
    const float* Wqkv = (const float*)d_in[1];   // [3D, D]
    const float* Wout = (const float*)d_in[2];   // [D, D]
    float* out = (float*)d_out;                  // [B,T,D]

    void *p_qkv, *p_xh, *p_w1h, *p_w2h, *p_ah, *p_al;
    void *p_qnh, *p_qnl, *p_knh, *p_knl, *p_vh;
    cudaGetSymbolAddress(&p_qkv, g_qkv);
    cudaGetSymbolAddress(&p_xh, g_xh);
    cudaGetSymbolAddress(&p_w1h, g_w1h); cudaGetSymbolAddress(&p_w2h, g_w2h);
    cudaGetSymbolAddress(&p_ah, g_ah);   cudaGetSymbolAddress(&p_al, g_al);
    cudaGetSymbolAddress(&p_qnh, g_qnh); cudaGetSymbolAddress(&p_qnl, g_qnl);
    cudaGetSymbolAddress(&p_knh, g_knh); cudaGetSymbolAddress(&p_knl, g_knl);
    cudaGetSymbolAddress(&p_vh, g_vh2);

    static bool attr_done = false;
    if (!attr_done) {
        cudaFuncSetAttribute(gemm_f16_1p,
                             cudaFuncAttributeMaxDynamicSharedMemorySize, GEMM1_SMEM);
        cudaFuncSetAttribute(gemm_f16_2p,
                             cudaFuncAttributeMaxDynamicSharedMemorySize, GEMM2_SMEM);
        cudaFuncSetAttribute(yat_attn_tc,
                             cudaFuncAttributeMaxDynamicSharedMemorySize, ATT_SMEM);
        attr_done = true;
    }

    const int M = BQ * TQ;  // 4096

    // 0) convert inputs to fp16 (hi only)
    conv_f16<<<(M * DQ / 4) / 256, 256>>>(x, (uint32_t*)p_xh, M * DQ / 4);
    conv_f16<<<(ROW3 * DQ / 4) / 256, 256>>>(Wqkv, (uint32_t*)p_w1h, ROW3 * DQ / 4);
    conv_f16<<<(DQ * DQ / 4) / 256, 256>>>(Wout, (uint32_t*)p_w2h, DQ * DQ / 4);

    // 1) qkv = x @ Wqkv^T : [4096,3072]  (fp16 1-pass)
    gemm_f16_1p<<<dim3(ROW3 / 128, M / 128), 256, GEMM1_SMEM>>>(
        (const uint16_t*)p_xh, (const uint16_t*)p_w1h,
        (float*)p_qkv, M, ROW3, DQ);

    // 2) normalize q,k + split to fp16 head-major, convert v
    prep_qkv<<<(3 * M * HQ) / 8, 256>>>((const float*)p_qkv,
        (__half*)p_qnh, (__half*)p_qnl, (__half*)p_knh, (__half*)p_knl, (__half*)p_vh);

    // 3) causal yat attention (pipelined, fp16) -> split fp16 att
    yat_attn_tc<<<dim3(TQ / 64, HQ, BQ), 128, ATT_SMEM>>>(
        (const __half*)p_qnh, (const __half*)p_qnl,
        (const __half*)p_knh, (const __half*)p_knl, (const __half*)p_vh,
        (uint32_t*)p_ah, (uint32_t*)p_al);

    // 4) out = att @ Wout^T : [4096,1024]  (fp16 2-pass, A corrected)
    gemm_f16_2p<<<dim3(DQ / 128, M / 128), 256, GEMM2_SMEM>>>(
        (const uint16_t*)p_ah, (const uint16_t*)p_al, (const uint16_t*)p_w2h,
        out, M, DQ, DQ);
}

// round 12
// speedup vs baseline: 9.0086x; 1.2171x over previous
#include <cuda_runtime.h>
#include <cuda_fp16.h>
#include <cstddef>
#include <cstdint>

// Problem constants (fixed by setup_inputs)
#define BQ   2
#define TQ   2048
#define DQ   1024
#define HQ   16
#define HDQ  64
#define ROW3 3072   // 3*DQ

// Scratch (device globals — no allocation allowed). u32 = packed fp16x2.
__device__ float    g_qkv[(size_t)BQ * TQ * ROW3];   // fp32 qkv
__device__ uint32_t g_xh [(size_t)BQ * TQ * DQ / 2]; // x fp16 (hi only)
__device__ uint32_t g_w1h[(size_t)ROW3 * DQ / 2];    // Wqkv hi
__device__ uint32_t g_w2h[(size_t)DQ * DQ / 2];      // Wout hi
__device__ uint32_t g_ah [(size_t)BQ * TQ * DQ / 2]; // attention out (fp16 hi)
// head-major [b][h][t][64] fp16 tensors for attention
__device__ __half   g_qnh[(size_t)BQ * HQ * TQ * HDQ];
__device__ __half   g_knh[(size_t)BQ * HQ * TQ * HDQ];
__device__ __half   g_knl[(size_t)BQ * HQ * TQ * HDQ];
__device__ __half   g_vh2[(size_t)BQ * HQ * TQ * HDQ];

typedef unsigned long long ull;

__device__ __forceinline__ unsigned su32(const void* p) {
    return (unsigned)__cvta_generic_to_shared(p);
}

// ---------------------------------------------------------------------------
// Warp-level tensor-core + async-copy primitives (base-target PTX)
// ---------------------------------------------------------------------------
#define LDSM_X4(r0, r1, r2, r3, addr) \
    asm volatile("ldmatrix.sync.aligned.m8n8.x4.shared.b16 {%0,%1,%2,%3}, [%4];" \
        : "=r"(r0), "=r"(r1), "=r"(r2), "=r"(r3) : "r"(addr))

#define LDSM_X4_T(r0, r1, r2, r3, addr) \
    asm volatile("ldmatrix.sync.aligned.m8n8.x4.trans.shared.b16 {%0,%1,%2,%3}, [%4];" \
        : "=r"(r0), "=r"(r1), "=r"(r2), "=r"(r3) : "r"(addr))

#define MMAH(c, a, b0, b1) \
    asm volatile("mma.sync.aligned.m16n8k16.row.col.f32.f16.f16.f32 " \
        "{%0,%1,%2,%3}, {%4,%5,%6,%7}, {%8,%9}, {%0,%1,%2,%3};" \
        : "+f"((c)[0]), "+f"((c)[1]), "+f"((c)[2]), "+f"((c)[3]) \
        : "r"((a)[0]), "r"((a)[1]), "r"((a)[2]), "r"((a)[3]), "r"(b0), "r"(b1))

#define CP16(dst, src) \
    asm volatile("cp.async.cg.shared.global [%0], [%1], 16;" :: "r"(dst), "l"(src))
#define CP_COMMIT() asm volatile("cp.async.commit_group;" ::: "memory")
#define CP_WAIT(n)  asm volatile("cp.async.wait_group %0;" :: "n"(n) : "memory")

// pack two fp16 (from floats) into one u32 (lo = first arg)
__device__ __forceinline__ uint32_t packh2(float lo, float hi) {
    __half2 t = __halves2half2(__float2half_rn(lo), __float2half_rn(hi));
    return *reinterpret_cast<uint32_t*>(&t);
}

// Pack two fp32 into fp16x2 hi + residual lo
__device__ __forceinline__ void packsplit2h(float w0, float w1,
                                            uint32_t& h, uint32_t& l) {
    const __half h0 = __float2half_rn(w0), h1 = __float2half_rn(w1);
    __half2 t = __halves2half2(h0, h1);
    h = *reinterpret_cast<uint32_t*>(&t);
    l = packh2(w0 - __half2float(h0), w1 - __half2float(h1));
}

#define RCPA(d, a) \
    asm("rcp.approx.f32 %0, %1;" : "=f"(d) : "f"(a))

// ---------------------------------------------------------------------------
// Convert: fp32 -> packed fp16 (hi only)
// ---------------------------------------------------------------------------
__global__ __launch_bounds__(256) void conv_f16(const float* __restrict__ src,
                                                uint32_t* __restrict__ hi, int n4) {
    const int i = blockIdx.x * blockDim.x + threadIdx.x;
    if (i < n4) {
        float4 f = ((const float4*)src)[i];
        hi[2 * i]     = packh2(f.x, f.y);
        hi[2 * i + 1] = packh2(f.z, f.w);
    }
}

// ---------------------------------------------------------------------------
// prep_qkv: one warp per (part, token, head) 64-elem row of fp32 qkv.
// part 0: q -> L2-normalize -> fp16 hi -> g_qnh (head-major)
// part 1: k -> L2-normalize -> split fp16 hi/lo -> g_knh/g_knl
// part 2: v -> fp16 hi -> g_vh2
// ---------------------------------------------------------------------------
__global__ __launch_bounds__(256) void prep_qkv(const float* __restrict__ qkv,
                                                __half* __restrict__ qnh,
                                                __half* __restrict__ knh,
                                                __half* __restrict__ knl,
                                                __half* __restrict__ vh) {
    const int gw   = (blockIdx.x * blockDim.x + threadIdx.x) >> 5;
    const int lane = threadIdx.x & 31;
    const int part = gw >> 16;                 // 0..2
    const int rem  = gw & 65535;
    const int bt   = rem >> 4;                 // token index (b*TQ + t)
    const int h    = rem & 15;

    const float* p = qkv + (size_t)bt * ROW3 + part * DQ + h * HDQ;
    float v0 = p[lane];
    float v1 = p[lane + 32];

    const int b = bt / TQ, t = bt & (TQ - 1);
    const size_t dst = (((size_t)(b * HQ + h)) * TQ + t) * HDQ;

    if (part == 2) {
        vh[dst + lane]      = __float2half_rn(v0);
        vh[dst + lane + 32] = __float2half_rn(v1);
        return;
    }

    float ss = v0 * v0 + v1 * v1;
#pragma unroll
    for (int m = 16; m; m >>= 1) ss += __shfl_xor_sync(0xffffffffu, ss, m);
    const float s = 1.0f / fmaxf(sqrtf(ss), 1e-12f);
    v0 *= s; v1 *= s;

    const __half h0 = __float2half_rn(v0);
    const __half h1 = __float2half_rn(v1);
    if (part == 0) {
        qnh[dst + lane]      = h0;
        qnh[dst + lane + 32] = h1;
    } else {
        knh[dst + lane]      = h0;
        knh[dst + lane + 32] = h1;
        knl[dst + lane]      = __float2half_rn(v0 - __half2float(h0));
        knl[dst + lane + 32] = __float2half_rn(v1 - __half2float(h1));
    }
}

// ---------------------------------------------------------------------------
// 1-pass fp16 GEMM: C[M,N] = Ah[M,K] @ Bh[N,K]^T  (both hi-only)
// CTA tile 128x128, 8 warps, BK=32, 3-stage cp.async pipeline, 2 CTAs/SM.
// ---------------------------------------------------------------------------
#define RSTR 80
#define NSTG 3
#define STG1 20480
#define OFF1_BH 10240
#define GEMM1_SMEM (NSTG * STG1)

extern __shared__ unsigned char g_dsm[];

__global__ __launch_bounds__(256, 2) void gemm_f16_1p(
    const uint16_t* __restrict__ Ah, const uint16_t* __restrict__ Bh,
    float* __restrict__ C, int M, int N, int K) {

    const int tid  = threadIdx.x;
    const int wid  = tid >> 5;
    const int lane = tid & 31;
    const int wm   = wid & 3;
    const int wn   = wid >> 2;

    const int row0 = blockIdx.y * 128;
    const int col0 = blockIdx.x * 128;

    const int lr = (lane & 7) + ((lane >> 3) & 1) * 8;
    const int lk = (lane >> 4) * 16;

    const unsigned sb = su32(g_dsm);

    const int r0p = (tid * 2) >> 2,     s0p = (tid * 2) & 3;
    const int r1p = (tid * 2 + 1) >> 2, s1p = (tid * 2 + 1) & 3;

    auto issue = [&](int c) {
        const unsigned base = sb + (unsigned)(c % NSTG) * STG1;
        const int k0 = c * 32;
        const unsigned d0 = base + (unsigned)(r0p * RSTR + s0p * 16);
        const unsigned d1 = base + (unsigned)(r1p * RSTR + s1p * 16);
        const size_t a0 = (size_t)(row0 + r0p) * K + k0 + s0p * 8;
        const size_t a1 = (size_t)(row0 + r1p) * K + k0 + s1p * 8;
        CP16(d0, Ah + a0);
        CP16(d1, Ah + a1);
        const size_t b0 = (size_t)(col0 + r0p) * K + k0 + s0p * 8;
        const size_t b1 = (size_t)(col0 + r1p) * K + k0 + s1p * 8;
        CP16(d0 + OFF1_BH, Bh + b0);
        CP16(d1 + OFF1_BH, Bh + b1);
    };

    float acc[2][8][4];
#pragma unroll
    for (int mt = 0; mt < 2; mt++)
#pragma unroll
        for (int nt = 0; nt < 8; nt++)
#pragma unroll
            for (int e = 0; e < 4; e++) acc[mt][nt][e] = 0.0f;

    const int nchunks = K / 32;

    issue(0); CP_COMMIT();
    issue(1); CP_COMMIT();

    for (int j = 0; j < nchunks; j++) {
        CP_WAIT(1);
        __syncthreads();

        if (j + 2 < nchunks) issue(j + 2);
        CP_COMMIT();

        const unsigned base = sb + (unsigned)(j % NSTG) * STG1;
        const unsigned aH = base, bH = base + OFF1_BH;

#pragma unroll
        for (int ks = 0; ks < 2; ks++) {
            const unsigned kb = (unsigned)(ks * 32 + lk);
            uint32_t ah[2][4];
#pragma unroll
            for (int mt = 0; mt < 2; mt++) {
                const unsigned ro = (unsigned)((wm * 32 + mt * 16 + lr) * RSTR) + kb;
                LDSM_X4(ah[mt][0], ah[mt][1], ah[mt][2], ah[mt][3], aH + ro);
            }
            uint32_t bh[4][4];
#pragma unroll
            for (int np = 0; np < 4; np++) {
                const unsigned ro = (unsigned)((wn * 64 + np * 16 + lr) * RSTR) + kb;
                LDSM_X4(bh[np][0], bh[np][1], bh[np][2], bh[np][3], bH + ro);
            }
#pragma unroll
            for (int mt = 0; mt < 2; mt++)
#pragma unroll
                for (int nt = 0; nt < 8; nt++) {
                    const int np = nt >> 1, sel = nt & 1;
                    MMAH(acc[mt][nt], ah[mt], bh[np][sel], bh[np][sel + 2]);
                }
        }
    }

    const int er = lane >> 2;
    const int ec = (lane & 3) * 2;
#pragma unroll
    for (int mt = 0; mt < 2; mt++) {
        const int row = row0 + wm * 32 + mt * 16 + er;
#pragma unroll
        for (int nt = 0; nt < 8; nt++) {
            const int col = col0 + wn * 64 + nt * 8 + ec;
            *(float2*)(C + (size_t)row * N + col) =
                make_float2(acc[mt][nt][0], acc[mt][nt][1]);
            *(float2*)(C + (size_t)(row + 8) * N + col) =
                make_float2(acc[mt][nt][2], acc[mt][nt][3]);
        }
    }
}

// ---------------------------------------------------------------------------
// Causal yat attention: cp.async double-buffered fp16 K/V tiles.
// S phase fp16 2-pass (qh*kh + qh*kl, k corrected); V 2-pass ((wh+wl)*vh).
// Stage = KH | KL | VH tiles, 64 rows x 144B each. Epilogue writes fp16 hi.
// ---------------------------------------------------------------------------
#define VR 144
#define OFF_KL (64 * VR)
#define OFF_VH (128 * VR)
#define AST (192 * VR)
#define ATT_SMEM (2 * AST)

__global__ __launch_bounds__(128) void yat_attn_tc(
    const __half* __restrict__ qnh,
    const __half* __restrict__ knh, const __half* __restrict__ knl,
    const __half* __restrict__ vh,
    uint32_t* __restrict__ ath) {

    const int tid  = threadIdx.x;
    const int wid  = tid >> 5;
    const int lane = tid & 31;

    const int qt = (int)gridDim.x - 1 - (int)blockIdx.x;  // longest first
    const int h  = blockIdx.y;
    const int b  = blockIdx.z;
    const int q0 = qt * 64;

    const int lr = (lane & 7) + ((lane >> 3) & 1) * 8;
    const int lk = (lane >> 4) * 16;

    const unsigned sb = su32(g_dsm);
    const size_t headBase = ((size_t)(b * HQ + h)) * TQ;

    const int seg = tid & 7;
    const int rb  = tid >> 3;

    // ---- stage Q (hi) into stage 0, pull A-fragments ----
#pragma unroll
    for (int i = 0; i < 4; i++) {
        const int r = rb + 16 * i;
        const size_t so = (headBase + q0 + r) * HDQ + seg * 8;
        CP16(sb + (unsigned)(r * VR + seg * 16), qnh + so);
    }
    CP_COMMIT();
    CP_WAIT(0);
    __syncthreads();

    uint32_t qfh[4][4];
#pragma unroll
    for (int kc = 0; kc < 4; kc++) {
        const unsigned ro = (unsigned)((wid * 16 + lr) * VR + kc * 32 + lk);
        LDSM_X4(qfh[kc][0], qfh[kc][1], qfh[kc][2], qfh[kc][3], sb + ro);
    }
    __syncthreads();

    auto issueKV = [&](int kt) {
        const unsigned base = sb + (unsigned)(kt & 1) * AST;
        const size_t tok = headBase + (size_t)kt * 64;
#pragma unroll
        for (int i = 0; i < 4; i++) {
            const int r = rb + 16 * i;
            const size_t so = (tok + r) * HDQ + seg * 8;
            const unsigned dofs = (unsigned)(r * VR + seg * 16);
            CP16(base + dofs,          knh + so);
            CP16(base + OFF_KL + dofs, knl + so);
            CP16(base + OFF_VH + dofs, vh + so);
        }
    };

    float accO[8][4];
#pragma unroll
    for (int nt = 0; nt < 8; nt++)
#pragma unroll
        for (int e = 0; e < 4; e++) accO[nt][e] = 0.0f;
    float dsum0 = 0.0f, dsum1 = 0.0f;

    const int qg0 = q0 + wid * 16 + (lane >> 2);

    issueKV(0); CP_COMMIT();

    for (int kt = 0; kt <= qt; kt++) {
        CP_WAIT(0);
        __syncthreads();

        if (kt + 1 <= qt) issueKV(kt + 1);
        CP_COMMIT();

        const unsigned base = sb + (unsigned)(kt & 1) * AST;
        const unsigned kH = base, kL = base + OFF_KL, vHb = base + OFF_VH;

        // ---- S = Qn Kn^T (fp16 2-pass: qh*kh + qh*kl) ----
        float sf[8][4];
#pragma unroll
        for (int nt = 0; nt < 8; nt++)
#pragma unroll
            for (int e = 0; e < 4; e++) sf[nt][e] = 0.0f;

#pragma unroll
        for (int kc = 0; kc < 4; kc++) {
#pragma unroll
            for (int g = 0; g < 4; g++) {
                uint32_t khf[4], klf[4];
                const unsigned ro = (unsigned)((g * 16 + lr) * VR + kc * 32 + lk);
                LDSM_X4(khf[0], khf[1], khf[2], khf[3], kH + ro);
                LDSM_X4(klf[0], klf[1], klf[2], klf[3], kL + ro);
                MMAH(sf[2 * g],     qfh[kc], khf[0], khf[2]);
                MMAH(sf[2 * g + 1], qfh[kc], khf[1], khf[3]);
                MMAH(sf[2 * g],     qfh[kc], klf[0], klf[2]);
                MMAH(sf[2 * g + 1], qfh[kc], klf[1], klf[3]);
            }
        }

        // ---- transform to w, mask, den, repack ----
        const bool diag = (kt == qt);
        uint32_t w01h[8], w01l[8], w23h[8], w23l[8];
#pragma unroll
        for (int nt = 0; nt < 8; nt++) {
            float w[4];
#pragma unroll
            for (int e = 0; e < 4; e++) {
                const float d = sf[nt][e];
                const float den = fmaxf(fmaf(-2.0f, d, 2.01f), 1e-6f);
                float rc; RCPA(rc, den);
                w[e] = d * d * rc;
            }
            if (diag) {
                const int kg = kt * 64 + nt * 8 + 2 * (lane & 3);
                if (kg     > qg0)     w[0] = 0.0f;
                if (kg + 1 > qg0)     w[1] = 0.0f;
                if (kg     > qg0 + 8) w[2] = 0.0f;
                if (kg + 1 > qg0 + 8) w[3] = 0.0f;
            }
            dsum0 += w[0] + w[1];
            dsum1 += w[2] + w[3];
            packsplit2h(w[0], w[1], w01h[nt], w01l[nt]);
            packsplit2h(w[2], w[3], w23h[nt], w23l[nt]);
        }

        // ---- O += (wh+wl) @ Vh (fp16 2-pass, V via ldmatrix.trans) ----
#pragma unroll
        for (int kc2 = 0; kc2 < 4; kc2++) {
            uint32_t ah[4] = {w01h[2 * kc2], w23h[2 * kc2],
                              w01h[2 * kc2 + 1], w23h[2 * kc2 + 1]};
            uint32_t al[4] = {w01l[2 * kc2], w23l[2 * kc2],
                              w01l[2 * kc2 + 1], w23l[2 * kc2 + 1]};
#pragma unroll
            for (int g = 0; g < 4; g++) {
                uint32_t vhf[4];
                const unsigned ro = (unsigned)((kc2 * 16 + lr) * VR + g * 32 + lk);
                LDSM_X4_T(vhf[0], vhf[1], vhf[2], vhf[3], vHb + ro);
                MMAH(accO[2 * g],     ah, vhf[0], vhf[1]);
                MMAH(accO[2 * g + 1], ah, vhf[2], vhf[3]);
                MMAH(accO[2 * g],     al, vhf[0], vhf[1]);
                MMAH(accO[2 * g + 1], al, vhf[2], vhf[3]);
            }
        }
        __syncthreads();
    }

    // ---- epilogue: reduce den, divide, write fp16 hi ----
    dsum0 += __shfl_xor_sync(0xffffffffu, dsum0, 1);
    dsum0 += __shfl_xor_sync(0xffffffffu, dsum0, 2);
    dsum1 += __shfl_xor_sync(0xffffffffu, dsum1, 1);
    dsum1 += __shfl_xor_sync(0xffffffffu, dsum1, 2);
    float inv0, inv1;
    RCPA(inv0, dsum0 + 1e-6f);
    RCPA(inv1, dsum1 + 1e-6f);

    const size_t rowg  = (size_t)(b * TQ) + q0 + wid * 16 + (lane >> 2);
    const int    colb2 = h * (HDQ / 2) + (lane & 3);
#pragma unroll
    for (int nt = 0; nt < 8; nt++) {
        ath[rowg * (DQ / 2) + colb2 + nt * 4] =
            packh2(accO[nt][0] * inv0, accO[nt][1] * inv0);
        ath[(rowg + 8) * (DQ / 2) + colb2 + nt * 4] =
            packh2(accO[nt][2] * inv1, accO[nt][3] * inv1);
    }
}

// ---------------------------------------------------------------------------
// kernel_launch
// ---------------------------------------------------------------------------
extern "C" void kernel_launch(void* const* d_in, const int* in_sizes, int n_in,
                              void* d_out, int out_size) {
    (void)in_sizes; (void)n_in; (void)out_size;
    const float* x    = (const float*)d_in[0];   // [B,T,D]
    const float* Wqkv = (const float*)d_in[1];   // [3D, D]
    const float* Wout = (const float*)d_in[2];   // [D, D]
    float* out = (float*)d_out;                  // [B,T,D]

    void *p_qkv, *p_xh, *p_w1h, *p_w2h, *p_ah;
    void *p_qnh, *p_knh, *p_knl, *p_vh;
    cudaGetSymbolAddress(&p_qkv, g_qkv);
    cudaGetSymbolAddress(&p_xh, g_xh);
    cudaGetSymbolAddress(&p_w1h, g_w1h); cudaGetSymbolAddress(&p_w2h, g_w2h);
    cudaGetSymbolAddress(&p_ah, g_ah);
    cudaGetSymbolAddress(&p_qnh, g_qnh);
    cudaGetSymbolAddress(&p_knh, g_knh); cudaGetSymbolAddress(&p_knl, g_knl);
    cudaGetSymbolAddress(&p_vh, g_vh2);

    static bool attr_done = false;
    if (!attr_done) {
        cudaFuncSetAttribute(gemm_f16_1p,
                             cudaFuncAttributeMaxDynamicSharedMemorySize, GEMM1_SMEM);
        cudaFuncSetAttribute(yat_attn_tc,
                             cudaFuncAttributeMaxDynamicSharedMemorySize, ATT_SMEM);
        attr_done = true;
    }

    const int M = BQ * TQ;  // 4096

    // 0) convert inputs to fp16 (hi only)
    conv_f16<<<(M * DQ / 4) / 256, 256>>>(x, (uint32_t*)p_xh, M * DQ / 4);
    conv_f16<<<(ROW3 * DQ / 4) / 256, 256>>>(Wqkv, (uint32_t*)p_w1h, ROW3 * DQ / 4);
    conv_f16<<<(DQ * DQ / 4) / 256, 256>>>(Wout, (uint32_t*)p_w2h, DQ * DQ / 4);

    // 1) qkv = x @ Wqkv^T : [4096,3072]  (fp16 1-pass)
    gemm_f16_1p<<<dim3(ROW3 / 128, M / 128), 256, GEMM1_SMEM>>>(
        (const uint16_t*)p_xh, (const uint16_t*)p_w1h,
        (float*)p_qkv, M, ROW3, DQ);

    // 2) normalize q,k; q fp16 hi, k fp16 hi/lo, v fp16 hi (head-major)
    prep_qkv<<<(3 * M * HQ) / 8, 256>>>((const float*)p_qkv,
        (__half*)p_qnh, (__half*)p_knh, (__half*)p_knl, (__half*)p_vh);

    // 3) causal yat attention (S 2-pass, V 2-pass) -> fp16 hi att
    yat_attn_tc<<<dim3(TQ / 64, HQ, BQ), 128, ATT_SMEM>>>(
        (const __half*)p_qnh, (const __half*)p_knh, (const __half*)p_knl,
        (const __half*)p_vh, (uint32_t*)p_ah);

    // 4) out = att @ Wout^T : [4096,1024]  (fp16 1-pass)
    gemm_f16_1p<<<dim3(DQ / 128, M / 128), 256, GEMM1_SMEM>>>(
        (const uint16_t*)p_ah, (const uint16_t*)p_w2h,
        out, M, DQ, DQ);
}

// round 13
// speedup vs baseline: 10.2781x; 1.1409x over previous
#include <cuda_runtime.h>
#include <cuda_fp16.h>
#include <cstddef>
#include <cstdint>

// Problem constants (fixed by setup_inputs)
#define BQ   2
#define TQ   2048
#define DQ   1024
#define HQ   16
#define HDQ  64
#define ROW3 3072   // 3*DQ

// Scratch (device globals — no allocation allowed). u32 = packed fp16x2.
__device__ float    g_qkv[(size_t)BQ * TQ * ROW3];   // fp32 qkv
__device__ uint32_t g_xh [(size_t)BQ * TQ * DQ / 2]; // x fp16 (hi only)
__device__ uint32_t g_w1h[(size_t)ROW3 * DQ / 2];    // Wqkv hi
__device__ uint32_t g_w2h[(size_t)DQ * DQ / 2];      // Wout hi
__device__ uint32_t g_ah [(size_t)BQ * TQ * DQ / 2]; // attention out (fp16 hi)
// head-major [b][h][t][64] fp16 tensors for attention
__device__ __half   g_qnh[(size_t)BQ * HQ * TQ * HDQ];
__device__ __half   g_knh[(size_t)BQ * HQ * TQ * HDQ];
__device__ __half   g_vh2[(size_t)BQ * HQ * TQ * HDQ];

typedef unsigned long long ull;

__device__ __forceinline__ unsigned su32(const void* p) {
    return (unsigned)__cvta_generic_to_shared(p);
}

// ---------------------------------------------------------------------------
// Warp-level tensor-core + async-copy primitives (base-target PTX)
// ---------------------------------------------------------------------------
#define LDSM_X4(r0, r1, r2, r3, addr) \
    asm volatile("ldmatrix.sync.aligned.m8n8.x4.shared.b16 {%0,%1,%2,%3}, [%4];" \
        : "=r"(r0), "=r"(r1), "=r"(r2), "=r"(r3) : "r"(addr))

#define LDSM_X4_T(r0, r1, r2, r3, addr) \
    asm volatile("ldmatrix.sync.aligned.m8n8.x4.trans.shared.b16 {%0,%1,%2,%3}, [%4];" \
        : "=r"(r0), "=r"(r1), "=r"(r2), "=r"(r3) : "r"(addr))

#define MMAH(c, a, b0, b1) \
    asm volatile("mma.sync.aligned.m16n8k16.row.col.f32.f16.f16.f32 " \
        "{%0,%1,%2,%3}, {%4,%5,%6,%7}, {%8,%9}, {%0,%1,%2,%3};" \
        : "+f"((c)[0]), "+f"((c)[1]), "+f"((c)[2]), "+f"((c)[3]) \
        : "r"((a)[0]), "r"((a)[1]), "r"((a)[2]), "r"((a)[3]), "r"(b0), "r"(b1))

#define CP16(dst, src) \
    asm volatile("cp.async.cg.shared.global [%0], [%1], 16;" :: "r"(dst), "l"(src))
#define CP_COMMIT() asm volatile("cp.async.commit_group;" ::: "memory")
#define CP_WAIT(n)  asm volatile("cp.async.wait_group %0;" :: "n"(n) : "memory")

// pack two fp16 (from floats) into one u32 (lo = first arg)
__device__ __forceinline__ uint32_t packh2(float lo, float hi) {
    __half2 t = __halves2half2(__float2half_rn(lo), __float2half_rn(hi));
    return *reinterpret_cast<uint32_t*>(&t);
}

#define RCPA(d, a) \
    asm("rcp.approx.f32 %0, %1;" : "=f"(d) : "f"(a))

// ---------------------------------------------------------------------------
// Convert: fp32 -> packed fp16 (hi only)
// ---------------------------------------------------------------------------
__global__ __launch_bounds__(256) void conv_f16(const float* __restrict__ src,
                                                uint32_t* __restrict__ hi, int n4) {
    const int i = blockIdx.x * blockDim.x + threadIdx.x;
    if (i < n4) {
        float4 f = ((const float4*)src)[i];
        hi[2 * i]     = packh2(f.x, f.y);
        hi[2 * i + 1] = packh2(f.z, f.w);
    }
}

// ---------------------------------------------------------------------------
// prep_qkv: one warp per (part, token, head) 64-elem row of fp32 qkv.
// part 0: q -> L2-normalize -> fp16 hi -> g_qnh (head-major)
// part 1: k -> L2-normalize -> fp16 hi -> g_knh
// part 2: v -> fp16 hi -> g_vh2
// ---------------------------------------------------------------------------
__global__ __launch_bounds__(256) void prep_qkv(const float* __restrict__ qkv,
                                                __half* __restrict__ qnh,
                                                __half* __restrict__ knh,
                                                __half* __restrict__ vh) {
    const int gw   = (blockIdx.x * blockDim.x + threadIdx.x) >> 5;
    const int lane = threadIdx.x & 31;
    const int part = gw >> 16;                 // 0..2
    const int rem  = gw & 65535;
    const int bt   = rem >> 4;                 // token index (b*TQ + t)
    const int h    = rem & 15;

    const float* p = qkv + (size_t)bt * ROW3 + part * DQ + h * HDQ;
    float v0 = p[lane];
    float v1 = p[lane + 32];

    const int b = bt / TQ, t = bt & (TQ - 1);
    const size_t dst = (((size_t)(b * HQ + h)) * TQ + t) * HDQ;

    if (part == 2) {
        vh[dst + lane]      = __float2half_rn(v0);
        vh[dst + lane + 32] = __float2half_rn(v1);
        return;
    }

    float ss = v0 * v0 + v1 * v1;
#pragma unroll
    for (int m = 16; m; m >>= 1) ss += __shfl_xor_sync(0xffffffffu, ss, m);
    const float s = 1.0f / fmaxf(sqrtf(ss), 1e-12f);
    v0 *= s; v1 *= s;

    __half* o = (part == 0) ? qnh : knh;
    o[dst + lane]      = __float2half_rn(v0);
    o[dst + lane + 32] = __float2half_rn(v1);
}

// ---------------------------------------------------------------------------
// 1-pass fp16 GEMM: C[M,N] = Ah[M,K] @ Bh[N,K]^T  (both hi-only)
// CTA tile 128x128, 8 warps, BK=32, 3-stage cp.async pipeline, 2 CTAs/SM.
// ---------------------------------------------------------------------------
#define RSTR 80
#define NSTG 3
#define STG1 20480
#define OFF1_BH 10240
#define GEMM1_SMEM (NSTG * STG1)

extern __shared__ unsigned char g_dsm[];

__global__ __launch_bounds__(256, 2) void gemm_f16_1p(
    const uint16_t* __restrict__ Ah, const uint16_t* __restrict__ Bh,
    float* __restrict__ C, int M, int N, int K) {

    const int tid  = threadIdx.x;
    const int wid  = tid >> 5;
    const int lane = tid & 31;
    const int wm   = wid & 3;
    const int wn   = wid >> 2;

    const int row0 = blockIdx.y * 128;
    const int col0 = blockIdx.x * 128;

    const int lr = (lane & 7) + ((lane >> 3) & 1) * 8;
    const int lk = (lane >> 4) * 16;

    const unsigned sb = su32(g_dsm);

    const int r0p = (tid * 2) >> 2,     s0p = (tid * 2) & 3;
    const int r1p = (tid * 2 + 1) >> 2, s1p = (tid * 2 + 1) & 3;

    auto issue = [&](int c) {
        const unsigned base = sb + (unsigned)(c % NSTG) * STG1;
        const int k0 = c * 32;
        const unsigned d0 = base + (unsigned)(r0p * RSTR + s0p * 16);
        const unsigned d1 = base + (unsigned)(r1p * RSTR + s1p * 16);
        const size_t a0 = (size_t)(row0 + r0p) * K + k0 + s0p * 8;
        const size_t a1 = (size_t)(row0 + r1p) * K + k0 + s1p * 8;
        CP16(d0, Ah + a0);
        CP16(d1, Ah + a1);
        const size_t b0 = (size_t)(col0 + r0p) * K + k0 + s0p * 8;
        const size_t b1 = (size_t)(col0 + r1p) * K + k0 + s1p * 8;
        CP16(d0 + OFF1_BH, Bh + b0);
        CP16(d1 + OFF1_BH, Bh + b1);
    };

    float acc[2][8][4];
#pragma unroll
    for (int mt = 0; mt < 2; mt++)
#pragma unroll
        for (int nt = 0; nt < 8; nt++)
#pragma unroll
            for (int e = 0; e < 4; e++) acc[mt][nt][e] = 0.0f;

    const int nchunks = K / 32;

    issue(0); CP_COMMIT();
    issue(1); CP_COMMIT();

    for (int j = 0; j < nchunks; j++) {
        CP_WAIT(1);
        __syncthreads();

        if (j + 2 < nchunks) issue(j + 2);
        CP_COMMIT();

        const unsigned base = sb + (unsigned)(j % NSTG) * STG1;
        const unsigned aH = base, bH = base + OFF1_BH;

#pragma unroll
        for (int ks = 0; ks < 2; ks++) {
            const unsigned kb = (unsigned)(ks * 32 + lk);
            uint32_t ah[2][4];
#pragma unroll
            for (int mt = 0; mt < 2; mt++) {
                const unsigned ro = (unsigned)((wm * 32 + mt * 16 + lr) * RSTR) + kb;
                LDSM_X4(ah[mt][0], ah[mt][1], ah[mt][2], ah[mt][3], aH + ro);
            }
            uint32_t bh[4][4];
#pragma unroll
            for (int np = 0; np < 4; np++) {
                const unsigned ro = (unsigned)((wn * 64 + np * 16 + lr) * RSTR) + kb;
                LDSM_X4(bh[np][0], bh[np][1], bh[np][2], bh[np][3], bH + ro);
            }
#pragma unroll
            for (int mt = 0; mt < 2; mt++)
#pragma unroll
                for (int nt = 0; nt < 8; nt++) {
                    const int np = nt >> 1, sel = nt & 1;
                    MMAH(acc[mt][nt], ah[mt], bh[np][sel], bh[np][sel + 2]);
                }
        }
    }

    const int er = lane >> 2;
    const int ec = (lane & 3) * 2;
#pragma unroll
    for (int mt = 0; mt < 2; mt++) {
        const int row = row0 + wm * 32 + mt * 16 + er;
#pragma unroll
        for (int nt = 0; nt < 8; nt++) {
            const int col = col0 + wn * 64 + nt * 8 + ec;
            *(float2*)(C + (size_t)row * N + col) =
                make_float2(acc[mt][nt][0], acc[mt][nt][1]);
            *(float2*)(C + (size_t)(row + 8) * N + col) =
                make_float2(acc[mt][nt][2], acc[mt][nt][3]);
        }
    }
}

// ---------------------------------------------------------------------------
// Causal yat attention: cp.async double-buffered fp16 K/V tiles.
// S phase fp16 1-pass (qh*kh); V phase 1-pass (wh*vh); den in fp32.
// Stage = KH | VH tiles, 64 rows x 144B each. Epilogue writes fp16 hi.
// ---------------------------------------------------------------------------
#define VR 144
#define OFF_VH (64 * VR)
#define AST (128 * VR)        // 18432 B per stage
#define ATT_SMEM (2 * AST)    // 36864 B

__global__ __launch_bounds__(128) void yat_attn_tc(
    const __half* __restrict__ qnh,
    const __half* __restrict__ knh,
    const __half* __restrict__ vh,
    uint32_t* __restrict__ ath) {

    const int tid  = threadIdx.x;
    const int wid  = tid >> 5;
    const int lane = tid & 31;

    const int qt = (int)gridDim.x - 1 - (int)blockIdx.x;  // longest first
    const int h  = blockIdx.y;
    const int b  = blockIdx.z;
    const int q0 = qt * 64;

    const int lr = (lane & 7) + ((lane >> 3) & 1) * 8;
    const int lk = (lane >> 4) * 16;

    const unsigned sb = su32(g_dsm);
    const size_t headBase = ((size_t)(b * HQ + h)) * TQ;

    const int seg = tid & 7;
    const int rb  = tid >> 3;

    // ---- stage Q (hi) into stage 0, pull A-fragments ----
#pragma unroll
    for (int i = 0; i < 4; i++) {
        const int r = rb + 16 * i;
        const size_t so = (headBase + q0 + r) * HDQ + seg * 8;
        CP16(sb + (unsigned)(r * VR + seg * 16), qnh + so);
    }
    CP_COMMIT();
    CP_WAIT(0);
    __syncthreads();

    uint32_t qfh[4][4];
#pragma unroll
    for (int kc = 0; kc < 4; kc++) {
        const unsigned ro = (unsigned)((wid * 16 + lr) * VR + kc * 32 + lk);
        LDSM_X4(qfh[kc][0], qfh[kc][1], qfh[kc][2], qfh[kc][3], sb + ro);
    }
    __syncthreads();

    auto issueKV = [&](int kt) {
        const unsigned base = sb + (unsigned)(kt & 1) * AST;
        const size_t tok = headBase + (size_t)kt * 64;
#pragma unroll
        for (int i = 0; i < 4; i++) {
            const int r = rb + 16 * i;
            const size_t so = (tok + r) * HDQ + seg * 8;
            const unsigned dofs = (unsigned)(r * VR + seg * 16);
            CP16(base + dofs,          knh + so);
            CP16(base + OFF_VH + dofs, vh + so);
        }
    };

    float accO[8][4];
#pragma unroll
    for (int nt = 0; nt < 8; nt++)
#pragma unroll
        for (int e = 0; e < 4; e++) accO[nt][e] = 0.0f;
    float dsum0 = 0.0f, dsum1 = 0.0f;

    const int qg0 = q0 + wid * 16 + (lane >> 2);

    issueKV(0); CP_COMMIT();

    for (int kt = 0; kt <= qt; kt++) {
        CP_WAIT(0);
        __syncthreads();

        if (kt + 1 <= qt) issueKV(kt + 1);
        CP_COMMIT();

        const unsigned base = sb + (unsigned)(kt & 1) * AST;
        const unsigned kH = base, vHb = base + OFF_VH;

        // ---- S = Qn Kn^T (fp16 1-pass) ----
        float sf[8][4];
#pragma unroll
        for (int nt = 0; nt < 8; nt++)
#pragma unroll
            for (int e = 0; e < 4; e++) sf[nt][e] = 0.0f;

#pragma unroll
        for (int kc = 0; kc < 4; kc++) {
#pragma unroll
            for (int g = 0; g < 4; g++) {
                uint32_t khf[4];
                const unsigned ro = (unsigned)((g * 16 + lr) * VR + kc * 32 + lk);
                LDSM_X4(khf[0], khf[1], khf[2], khf[3], kH + ro);
                MMAH(sf[2 * g],     qfh[kc], khf[0], khf[2]);
                MMAH(sf[2 * g + 1], qfh[kc], khf[1], khf[3]);
            }
        }

        // ---- transform to w, mask, den, pack fp16 A-fragments ----
        const bool diag = (kt == qt);
        uint32_t w01[8], w23[8];
#pragma unroll
        for (int nt = 0; nt < 8; nt++) {
            float w[4];
#pragma unroll
            for (int e = 0; e < 4; e++) {
                const float d = sf[nt][e];
                const float den = fmaxf(fmaf(-2.0f, d, 2.01f), 1e-6f);
                float rc; RCPA(rc, den);
                w[e] = d * d * rc;
            }
            if (diag) {
                const int kg = kt * 64 + nt * 8 + 2 * (lane & 3);
                if (kg     > qg0)     w[0] = 0.0f;
                if (kg + 1 > qg0)     w[1] = 0.0f;
                if (kg     > qg0 + 8) w[2] = 0.0f;
                if (kg + 1 > qg0 + 8) w[3] = 0.0f;
            }
            dsum0 += w[0] + w[1];
            dsum1 += w[2] + w[3];
            w01[nt] = packh2(w[0], w[1]);
            w23[nt] = packh2(w[2], w[3]);
        }

        // ---- O += wh @ Vh (fp16 1-pass, V via ldmatrix.trans) ----
#pragma unroll
        for (int kc2 = 0; kc2 < 4; kc2++) {
            uint32_t ah[4] = {w01[2 * kc2], w23[2 * kc2],
                              w01[2 * kc2 + 1], w23[2 * kc2 + 1]};
#pragma unroll
            for (int g = 0; g < 4; g++) {
                uint32_t vhf[4];
                const unsigned ro = (unsigned)((kc2 * 16 + lr) * VR + g * 32 + lk);
                LDSM_X4_T(vhf[0], vhf[1], vhf[2], vhf[3], vHb + ro);
                MMAH(accO[2 * g],     ah, vhf[0], vhf[1]);
                MMAH(accO[2 * g + 1], ah, vhf[2], vhf[3]);
            }
        }
        __syncthreads();
    }

    // ---- epilogue: reduce den, divide, write fp16 hi ----
    dsum0 += __shfl_xor_sync(0xffffffffu, dsum0, 1);
    dsum0 += __shfl_xor_sync(0xffffffffu, dsum0, 2);
    dsum1 += __shfl_xor_sync(0xffffffffu, dsum1, 1);
    dsum1 += __shfl_xor_sync(0xffffffffu, dsum1, 2);
    float inv0, inv1;
    RCPA(inv0, dsum0 + 1e-6f);
    RCPA(inv1, dsum1 + 1e-6f);

    const size_t rowg  = (size_t)(b * TQ) + q0 + wid * 16 + (lane >> 2);
    const int    colb2 = h * (HDQ / 2) + (lane & 3);
#pragma unroll
    for (int nt = 0; nt < 8; nt++) {
        ath[rowg * (DQ / 2) + colb2 + nt * 4] =
            packh2(accO[nt][0] * inv0, accO[nt][1] * inv0);
        ath[(rowg + 8) * (DQ / 2) + colb2 + nt * 4] =
            packh2(accO[nt][2] * inv1, accO[nt][3] * inv1);
    }
}

// ---------------------------------------------------------------------------
// kernel_launch
// ---------------------------------------------------------------------------
extern "C" void kernel_launch(void* const* d_in, const int* in_sizes, int n_in,
                              void* d_out, int out_size) {
    (void)in_sizes; (void)n_in; (void)out_size;
    const float* x    = (const float*)d_in[0];   // [B,T,D]
    const float* Wqkv = (const float*)d_in[1];   // [3D, D]
    const float* Wout = (const float*)d_in[2];   // [D, D]
    float* out = (float*)d_out;                  // [B,T,D]

    void *p_qkv, *p_xh, *p_w1h, *p_w2h, *p_ah;
    void *p_qnh, *p_knh, *p_vh;
    cudaGetSymbolAddress(&p_qkv, g_qkv);
    cudaGetSymbolAddress(&p_xh, g_xh);
    cudaGetSymbolAddress(&p_w1h, g_w1h); cudaGetSymbolAddress(&p_w2h, g_w2h);
    cudaGetSymbolAddress(&p_ah, g_ah);
    cudaGetSymbolAddress(&p_qnh, g_qnh);
    cudaGetSymbolAddress(&p_knh, g_knh);
    cudaGetSymbolAddress(&p_vh, g_vh2);

    static bool attr_done = false;
    if (!attr_done) {
        cudaFuncSetAttribute(gemm_f16_1p,
                             cudaFuncAttributeMaxDynamicSharedMemorySize, GEMM1_SMEM);
        cudaFuncSetAttribute(yat_attn_tc,
                             cudaFuncAttributeMaxDynamicSharedMemorySize, ATT_SMEM);
        attr_done = true;
    }

    const int M = BQ * TQ;  // 4096

    // 0) convert inputs to fp16 (hi only)
    conv_f16<<<(M * DQ / 4) / 256, 256>>>(x, (uint32_t*)p_xh, M * DQ / 4);
    conv_f16<<<(ROW3 * DQ / 4) / 256, 256>>>(Wqkv, (uint32_t*)p_w1h, ROW3 * DQ / 4);
    conv_f16<<<(DQ * DQ / 4) / 256, 256>>>(Wout, (uint32_t*)p_w2h, DQ * DQ / 4);

    // 1) qkv = x @ Wqkv^T : [4096,3072]  (fp16 1-pass)
    gemm_f16_1p<<<dim3(ROW3 / 128, M / 128), 256, GEMM1_SMEM>>>(
        (const uint16_t*)p_xh, (const uint16_t*)p_w1h,
        (float*)p_qkv, M, ROW3, DQ);

    // 2) normalize q,k -> fp16 hi head-major; convert v
    prep_qkv<<<(3 * M * HQ) / 8, 256>>>((const float*)p_qkv,
        (__half*)p_qnh, (__half*)p_knh, (__half*)p_vh);

    // 3) causal yat attention (S 1-pass, V 1-pass, fp32 den) -> fp16 att
    yat_attn_tc<<<dim3(TQ / 64, HQ, BQ), 128, ATT_SMEM>>>(
        (const __half*)p_qnh, (const __half*)p_knh, (const __half*)p_vh,
        (uint32_t*)p_ah);

    // 4) out = att @ Wout^T : [4096,1024]  (fp16 1-pass)
    gemm_f16_1p<<<dim3(DQ / 128, M / 128), 256, GEMM1_SMEM>>>(
        (const uint16_t*)p_ah, (const uint16_t*)p_w2h,
        out, M, DQ, DQ);
}

// round 14
// speedup vs baseline: 11.0566x; 1.0757x over previous
#include <cuda_runtime.h>
#include <cuda_fp16.h>
#include <cstddef>
#include <cstdint>

// Problem constants (fixed by setup_inputs)
#define BQ   2
#define TQ   2048
#define DQ   1024
#define HQ   16
#define HDQ  64
#define ROW3 3072   // 3*DQ

// Scratch (device globals — no allocation allowed). u32 = packed fp16x2.
__device__ uint32_t g_xh [(size_t)BQ * TQ * DQ / 2]; // x fp16 (hi only)
__device__ uint32_t g_w1h[(size_t)ROW3 * DQ / 2];    // Wqkv hi
__device__ uint32_t g_w2h[(size_t)DQ * DQ / 2];      // Wout hi
__device__ uint32_t g_ah [(size_t)BQ * TQ * DQ / 2]; // attention out (fp16 hi)
// head-major [b][h][t][64] fp16 tensors for attention
__device__ __half   g_qnh[(size_t)BQ * HQ * TQ * HDQ];
__device__ __half   g_knh[(size_t)BQ * HQ * TQ * HDQ];
__device__ __half   g_vh2[(size_t)BQ * HQ * TQ * HDQ];

typedef unsigned long long ull;

__device__ __forceinline__ unsigned su32(const void* p) {
    return (unsigned)__cvta_generic_to_shared(p);
}

// ---------------------------------------------------------------------------
// Warp-level tensor-core + async-copy primitives (base-target PTX)
// ---------------------------------------------------------------------------
#define LDSM_X4(r0, r1, r2, r3, addr) \
    asm volatile("ldmatrix.sync.aligned.m8n8.x4.shared.b16 {%0,%1,%2,%3}, [%4];" \
        : "=r"(r0), "=r"(r1), "=r"(r2), "=r"(r3) : "r"(addr))

#define LDSM_X4_T(r0, r1, r2, r3, addr) \
    asm volatile("ldmatrix.sync.aligned.m8n8.x4.trans.shared.b16 {%0,%1,%2,%3}, [%4];" \
        : "=r"(r0), "=r"(r1), "=r"(r2), "=r"(r3) : "r"(addr))

#define MMAH(c, a, b0, b1) \
    asm volatile("mma.sync.aligned.m16n8k16.row.col.f32.f16.f16.f32 " \
        "{%0,%1,%2,%3}, {%4,%5,%6,%7}, {%8,%9}, {%0,%1,%2,%3};" \
        : "+f"((c)[0]), "+f"((c)[1]), "+f"((c)[2]), "+f"((c)[3]) \
        : "r"((a)[0]), "r"((a)[1]), "r"((a)[2]), "r"((a)[3]), "r"(b0), "r"(b1))

#define CP16(dst, src) \
    asm volatile("cp.async.cg.shared.global [%0], [%1], 16;" :: "r"(dst), "l"(src))
#define CP_COMMIT() asm volatile("cp.async.commit_group;" ::: "memory")
#define CP_WAIT(n)  asm volatile("cp.async.wait_group %0;" :: "n"(n) : "memory")

// pack two fp16 (from floats) into one u32 (lo = first arg)
__device__ __forceinline__ uint32_t packh2(float lo, float hi) {
    __half2 t = __halves2half2(__float2half_rn(lo), __float2half_rn(hi));
    return *reinterpret_cast<uint32_t*>(&t);
}

#define RCPA(d, a) \
    asm("rcp.approx.f32 %0, %1;" : "=f"(d) : "f"(a))

// ---------------------------------------------------------------------------
// Convert: fp32 -> packed fp16 (hi only)
// ---------------------------------------------------------------------------
__global__ __launch_bounds__(256) void conv_f16(const float* __restrict__ src,
                                                uint32_t* __restrict__ hi, int n4) {
    const int i = blockIdx.x * blockDim.x + threadIdx.x;
    if (i < n4) {
        float4 f = ((const float4*)src)[i];
        hi[2 * i]     = packh2(f.x, f.y);
        hi[2 * i + 1] = packh2(f.z, f.w);
    }
}

// ---------------------------------------------------------------------------
// GEMM smem layout (shared by both GEMM kernels)
// ---------------------------------------------------------------------------
#define RSTR 80
#define NSTG 3
#define STG1 20480
#define OFF1_BH 10240
#define GEMM1_SMEM (NSTG * STG1)

extern __shared__ unsigned char g_dsm[];

// ---------------------------------------------------------------------------
// qkv GEMM with FUSED normalize epilogue:
//   C[4096,3072] = Xh @ W1h^T; per-head L2-normalize q,k; write fp16
//   head-major g_qnh/g_knh/g_vh2 directly (no fp32 intermediate, no prep).
// Each warp's 64-col N-range = exactly one head; a token-row's head lives in
// the 4 lanes sharing er -> register + shfl(1,2) norm reduction.
// ---------------------------------------------------------------------------
__global__ __launch_bounds__(256, 2) void gemm_qkv_fused(
    const uint16_t* __restrict__ Ah, const uint16_t* __restrict__ Bh,
    __half* __restrict__ qnh, __half* __restrict__ knh, __half* __restrict__ vh,
    int K) {

    const int tid  = threadIdx.x;
    const int wid  = tid >> 5;
    const int lane = tid & 31;
    const int wm   = wid & 3;
    const int wn   = wid >> 2;

    const int row0 = blockIdx.y * 128;
    const int col0 = blockIdx.x * 128;

    const int lr = (lane & 7) + ((lane >> 3) & 1) * 8;
    const int lk = (lane >> 4) * 16;

    const unsigned sb = su32(g_dsm);

    const int r0p = (tid * 2) >> 2,     s0p = (tid * 2) & 3;
    const int r1p = (tid * 2 + 1) >> 2, s1p = (tid * 2 + 1) & 3;

    auto issue = [&](int c) {
        const unsigned base = sb + (unsigned)(c % NSTG) * STG1;
        const int k0 = c * 32;
        const unsigned d0 = base + (unsigned)(r0p * RSTR + s0p * 16);
        const unsigned d1 = base + (unsigned)(r1p * RSTR + s1p * 16);
        const size_t a0 = (size_t)(row0 + r0p) * K + k0 + s0p * 8;
        const size_t a1 = (size_t)(row0 + r1p) * K + k0 + s1p * 8;
        CP16(d0, Ah + a0);
        CP16(d1, Ah + a1);
        const size_t b0 = (size_t)(col0 + r0p) * K + k0 + s0p * 8;
        const size_t b1 = (size_t)(col0 + r1p) * K + k0 + s1p * 8;
        CP16(d0 + OFF1_BH, Bh + b0);
        CP16(d1 + OFF1_BH, Bh + b1);
    };

    float acc[2][8][4];
#pragma unroll
    for (int mt = 0; mt < 2; mt++)
#pragma unroll
        for (int nt = 0; nt < 8; nt++)
#pragma unroll
            for (int e = 0; e < 4; e++) acc[mt][nt][e] = 0.0f;

    const int nchunks = K / 32;

    issue(0); CP_COMMIT();
    issue(1); CP_COMMIT();

    for (int j = 0; j < nchunks; j++) {
        CP_WAIT(1);
        __syncthreads();

        if (j + 2 < nchunks) issue(j + 2);
        CP_COMMIT();

        const unsigned base = sb + (unsigned)(j % NSTG) * STG1;
        const unsigned aH = base, bH = base + OFF1_BH;

#pragma unroll
        for (int ks = 0; ks < 2; ks++) {
            const unsigned kb = (unsigned)(ks * 32 + lk);
            uint32_t ah[2][4];
#pragma unroll
            for (int mt = 0; mt < 2; mt++) {
                const unsigned ro = (unsigned)((wm * 32 + mt * 16 + lr) * RSTR) + kb;
                LDSM_X4(ah[mt][0], ah[mt][1], ah[mt][2], ah[mt][3], aH + ro);
            }
            uint32_t bh[4][4];
#pragma unroll
            for (int np = 0; np < 4; np++) {
                const unsigned ro = (unsigned)((wn * 64 + np * 16 + lr) * RSTR) + kb;
                LDSM_X4(bh[np][0], bh[np][1], bh[np][2], bh[np][3], bH + ro);
            }
#pragma unroll
            for (int mt = 0; mt < 2; mt++)
#pragma unroll
                for (int nt = 0; nt < 8; nt++) {
                    const int np = nt >> 1, sel = nt & 1;
                    MMAH(acc[mt][nt], ah[mt], bh[np][sel], bh[np][sel + 2]);
                }
        }
    }

    // ---- fused epilogue: normalize (q,k) + fp16 head-major write ----
    const int er   = lane >> 2;
    const int ec   = (lane & 3) * 2;
    const int part = col0 >> 10;                       // 0=q, 1=k, 2=v
    const int hloc = ((col0 & 1023) >> 6) + wn;        // head 0..15
    __half* dstp = (part == 0) ? qnh : (part == 1 ? knh : vh);

#pragma unroll
    for (int mt = 0; mt < 2; mt++) {
        const int r0 = row0 + wm * 32 + mt * 16 + er;  // token (b*TQ + t)
        const int r1 = r0 + 8;
        float s0 = 1.0f, s1 = 1.0f;
        if (part < 2) {
            float ss0 = 0.0f, ss1 = 0.0f;
#pragma unroll
            for (int nt = 0; nt < 8; nt++) {
                ss0 += acc[mt][nt][0] * acc[mt][nt][0] + acc[mt][nt][1] * acc[mt][nt][1];
                ss1 += acc[mt][nt][2] * acc[mt][nt][2] + acc[mt][nt][3] * acc[mt][nt][3];
            }
            ss0 += __shfl_xor_sync(0xffffffffu, ss0, 1);
            ss0 += __shfl_xor_sync(0xffffffffu, ss0, 2);
            ss1 += __shfl_xor_sync(0xffffffffu, ss1, 1);
            ss1 += __shfl_xor_sync(0xffffffffu, ss1, 2);
            s0 = 1.0f / fmaxf(sqrtf(ss0), 1e-12f);
            s1 = 1.0f / fmaxf(sqrtf(ss1), 1e-12f);
        }
        const int b0 = r0 >> 11, t0 = r0 & (TQ - 1);
        const int b1 = r1 >> 11, t1 = r1 & (TQ - 1);
        const size_t base0 = (((size_t)(b0 * HQ + hloc)) * TQ + t0) * HDQ;
        const size_t base1 = (((size_t)(b1 * HQ + hloc)) * TQ + t1) * HDQ;
#pragma unroll
        for (int nt = 0; nt < 8; nt++) {
            const int d = nt * 8 + ec;
            *(uint32_t*)(dstp + base0 + d) = packh2(acc[mt][nt][0] * s0, acc[mt][nt][1] * s0);
            *(uint32_t*)(dstp + base1 + d) = packh2(acc[mt][nt][2] * s1, acc[mt][nt][3] * s1);
        }
    }
}

// ---------------------------------------------------------------------------
// 1-pass fp16 GEMM (fp32 output) — used for the out projection.
// ---------------------------------------------------------------------------
__global__ __launch_bounds__(256, 2) void gemm_f16_1p(
    const uint16_t* __restrict__ Ah, const uint16_t* __restrict__ Bh,
    float* __restrict__ C, int M, int N, int K) {

    const int tid  = threadIdx.x;
    const int wid  = tid >> 5;
    const int lane = tid & 31;
    const int wm   = wid & 3;
    const int wn   = wid >> 2;

    const int row0 = blockIdx.y * 128;
    const int col0 = blockIdx.x * 128;

    const int lr = (lane & 7) + ((lane >> 3) & 1) * 8;
    const int lk = (lane >> 4) * 16;

    const unsigned sb = su32(g_dsm);

    const int r0p = (tid * 2) >> 2,     s0p = (tid * 2) & 3;
    const int r1p = (tid * 2 + 1) >> 2, s1p = (tid * 2 + 1) & 3;

    auto issue = [&](int c) {
        const unsigned base = sb + (unsigned)(c % NSTG) * STG1;
        const int k0 = c * 32;
        const unsigned d0 = base + (unsigned)(r0p * RSTR + s0p * 16);
        const unsigned d1 = base + (unsigned)(r1p * RSTR + s1p * 16);
        const size_t a0 = (size_t)(row0 + r0p) * K + k0 + s0p * 8;
        const size_t a1 = (size_t)(row0 + r1p) * K + k0 + s1p * 8;
        CP16(d0, Ah + a0);
        CP16(d1, Ah + a1);
        const size_t b0 = (size_t)(col0 + r0p) * K + k0 + s0p * 8;
        const size_t b1 = (size_t)(col0 + r1p) * K + k0 + s1p * 8;
        CP16(d0 + OFF1_BH, Bh + b0);
        CP16(d1 + OFF1_BH, Bh + b1);
    };

    float acc[2][8][4];
#pragma unroll
    for (int mt = 0; mt < 2; mt++)
#pragma unroll
        for (int nt = 0; nt < 8; nt++)
#pragma unroll
            for (int e = 0; e < 4; e++) acc[mt][nt][e] = 0.0f;

    const int nchunks = K / 32;

    issue(0); CP_COMMIT();
    issue(1); CP_COMMIT();

    for (int j = 0; j < nchunks; j++) {
        CP_WAIT(1);
        __syncthreads();

        if (j + 2 < nchunks) issue(j + 2);
        CP_COMMIT();

        const unsigned base = sb + (unsigned)(j % NSTG) * STG1;
        const unsigned aH = base, bH = base + OFF1_BH;

#pragma unroll
        for (int ks = 0; ks < 2; ks++) {
            const unsigned kb = (unsigned)(ks * 32 + lk);
            uint32_t ah[2][4];
#pragma unroll
            for (int mt = 0; mt < 2; mt++) {
                const unsigned ro = (unsigned)((wm * 32 + mt * 16 + lr) * RSTR) + kb;
                LDSM_X4(ah[mt][0], ah[mt][1], ah[mt][2], ah[mt][3], aH + ro);
            }
            uint32_t bh[4][4];
#pragma unroll
            for (int np = 0; np < 4; np++) {
                const unsigned ro = (unsigned)((wn * 64 + np * 16 + lr) * RSTR) + kb;
                LDSM_X4(bh[np][0], bh[np][1], bh[np][2], bh[np][3], bH + ro);
            }
#pragma unroll
            for (int mt = 0; mt < 2; mt++)
#pragma unroll
                for (int nt = 0; nt < 8; nt++) {
                    const int np = nt >> 1, sel = nt & 1;
                    MMAH(acc[mt][nt], ah[mt], bh[np][sel], bh[np][sel + 2]);
                }
        }
    }

    const int er = lane >> 2;
    const int ec = (lane & 3) * 2;
#pragma unroll
    for (int mt = 0; mt < 2; mt++) {
        const int row = row0 + wm * 32 + mt * 16 + er;
#pragma unroll
        for (int nt = 0; nt < 8; nt++) {
            const int col = col0 + wn * 64 + nt * 8 + ec;
            *(float2*)(C + (size_t)row * N + col) =
                make_float2(acc[mt][nt][0], acc[mt][nt][1]);
            *(float2*)(C + (size_t)(row + 8) * N + col) =
                make_float2(acc[mt][nt][2], acc[mt][nt][3]);
        }
    }
}

// ---------------------------------------------------------------------------
// Causal yat attention: cp.async double-buffered fp16 K/V tiles.
// S phase fp16 1-pass (qh*kh); V phase 1-pass (wh*vh); den in fp32.
// One barrier per key tile (the end-of-loop sync was redundant: the next
// iteration's post-CP_WAIT barrier orders compute(kt) before issue(kt+2)).
// ---------------------------------------------------------------------------
#define VR 144
#define OFF_VH (64 * VR)
#define AST (128 * VR)        // 18432 B per stage
#define ATT_SMEM (2 * AST)    // 36864 B

__global__ __launch_bounds__(128) void yat_attn_tc(
    const __half* __restrict__ qnh,
    const __half* __restrict__ knh,
    const __half* __restrict__ vh,
    uint32_t* __restrict__ ath) {

    const int tid  = threadIdx.x;
    const int wid  = tid >> 5;
    const int lane = tid & 31;

    const int qt = (int)gridDim.x - 1 - (int)blockIdx.x;  // longest first
    const int h  = blockIdx.y;
    const int b  = blockIdx.z;
    const int q0 = qt * 64;

    const int lr = (lane & 7) + ((lane >> 3) & 1) * 8;
    const int lk = (lane >> 4) * 16;

    const unsigned sb = su32(g_dsm);
    const size_t headBase = ((size_t)(b * HQ + h)) * TQ;

    const int seg = tid & 7;
    const int rb  = tid >> 3;

    // ---- stage Q (hi) into stage 0, pull A-fragments ----
#pragma unroll
    for (int i = 0; i < 4; i++) {
        const int r = rb + 16 * i;
        const size_t so = (headBase + q0 + r) * HDQ + seg * 8;
        CP16(sb + (unsigned)(r * VR + seg * 16), qnh + so);
    }
    CP_COMMIT();
    CP_WAIT(0);
    __syncthreads();

    uint32_t qfh[4][4];
#pragma unroll
    for (int kc = 0; kc < 4; kc++) {
        const unsigned ro = (unsigned)((wid * 16 + lr) * VR + kc * 32 + lk);
        LDSM_X4(qfh[kc][0], qfh[kc][1], qfh[kc][2], qfh[kc][3], sb + ro);
    }
    __syncthreads();   // Q frags pulled; stage 0 free for K/V

    auto issueKV = [&](int kt) {
        const unsigned base = sb + (unsigned)(kt & 1) * AST;
        const size_t tok = headBase + (size_t)kt * 64;
#pragma unroll
        for (int i = 0; i < 4; i++) {
            const int r = rb + 16 * i;
            const size_t so = (tok + r) * HDQ + seg * 8;
            const unsigned dofs = (unsigned)(r * VR + seg * 16);
            CP16(base + dofs,          knh + so);
            CP16(base + OFF_VH + dofs, vh + so);
        }
    };

    float accO[8][4];
#pragma unroll
    for (int nt = 0; nt < 8; nt++)
#pragma unroll
        for (int e = 0; e < 4; e++) accO[nt][e] = 0.0f;
    float dsum0 = 0.0f, dsum1 = 0.0f;

    const int qg0 = q0 + wid * 16 + (lane >> 2);

    issueKV(0); CP_COMMIT();

    for (int kt = 0; kt <= qt; kt++) {
        CP_WAIT(0);
        __syncthreads();   // tile kt visible; all warps done with buffer kt&1

        if (kt + 1 <= qt) issueKV(kt + 1);
        CP_COMMIT();

        const unsigned base = sb + (unsigned)(kt & 1) * AST;
        const unsigned kH = base, vHb = base + OFF_VH;

        // ---- S = Qn Kn^T (fp16 1-pass) ----
        float sf[8][4];
#pragma unroll
        for (int nt = 0; nt < 8; nt++)
#pragma unroll
            for (int e = 0; e < 4; e++) sf[nt][e] = 0.0f;

#pragma unroll
        for (int kc = 0; kc < 4; kc++) {
#pragma unroll
            for (int g = 0; g < 4; g++) {
                uint32_t khf[4];
                const unsigned ro = (unsigned)((g * 16 + lr) * VR + kc * 32 + lk);
                LDSM_X4(khf[0], khf[1], khf[2], khf[3], kH + ro);
                MMAH(sf[2 * g],     qfh[kc], khf[0], khf[2]);
                MMAH(sf[2 * g + 1], qfh[kc], khf[1], khf[3]);
            }
        }

        // ---- transform to w, mask, den, pack fp16 A-fragments ----
        const bool diag = (kt == qt);
        uint32_t w01[8], w23[8];
#pragma unroll
        for (int nt = 0; nt < 8; nt++) {
            float w[4];
#pragma unroll
            for (int e = 0; e < 4; e++) {
                const float d = sf[nt][e];
                const float den = fmaxf(fmaf(-2.0f, d, 2.01f), 1e-6f);
                float rc; RCPA(rc, den);
                w[e] = d * d * rc;
            }
            if (diag) {
                const int kg = kt * 64 + nt * 8 + 2 * (lane & 3);
                if (kg     > qg0)     w[0] = 0.0f;
                if (kg + 1 > qg0)     w[1] = 0.0f;
                if (kg     > qg0 + 8) w[2] = 0.0f;
                if (kg + 1 > qg0 + 8) w[3] = 0.0f;
            }
            dsum0 += w[0] + w[1];
            dsum1 += w[2] + w[3];
            w01[nt] = packh2(w[0], w[1]);
            w23[nt] = packh2(w[2], w[3]);
        }

        // ---- O += wh @ Vh (fp16 1-pass, V via ldmatrix.trans) ----
#pragma unroll
        for (int kc2 = 0; kc2 < 4; kc2++) {
            uint32_t ah[4] = {w01[2 * kc2], w23[2 * kc2],
                              w01[2 * kc2 + 1], w23[2 * kc2 + 1]};
#pragma unroll
            for (int g = 0; g < 4; g++) {
                uint32_t vhf[4];
                const unsigned ro = (unsigned)((kc2 * 16 + lr) * VR + g * 32 + lk);
                LDSM_X4_T(vhf[0], vhf[1], vhf[2], vhf[3], vHb + ro);
                MMAH(accO[2 * g],     ah, vhf[0], vhf[1]);
                MMAH(accO[2 * g + 1], ah, vhf[2], vhf[3]);
            }
        }
        // no end-of-loop sync: next iteration's barrier provides the ordering
    }

    // ---- epilogue: reduce den, divide, write fp16 hi ----
    dsum0 += __shfl_xor_sync(0xffffffffu, dsum0, 1);
    dsum0 += __shfl_xor_sync(0xffffffffu, dsum0, 2);
    dsum1 += __shfl_xor_sync(0xffffffffu, dsum1, 1);
    dsum1 += __shfl_xor_sync(0xffffffffu, dsum1, 2);
    float inv0, inv1;
    RCPA(inv0, dsum0 + 1e-6f);
    RCPA(inv1, dsum1 + 1e-6f);

    const size_t rowg  = (size_t)(b * TQ) + q0 + wid * 16 + (lane >> 2);
    const int    colb2 = h * (HDQ / 2) + (lane & 3);
#pragma unroll
    for (int nt = 0; nt < 8; nt++) {
        ath[rowg * (DQ / 2) + colb2 + nt * 4] =
            packh2(accO[nt][0] * inv0, accO[nt][1] * inv0);
        ath[(rowg + 8) * (DQ / 2) + colb2 + nt * 4] =
            packh2(accO[nt][2] * inv1, accO[nt][3] * inv1);
    }
}

// ---------------------------------------------------------------------------
// kernel_launch
// ---------------------------------------------------------------------------
extern "C" void kernel_launch(void* const* d_in, const int* in_sizes, int n_in,
                              void* d_out, int out_size) {
    (void)in_sizes; (void)n_in; (void)out_size;
    const float* x    = (const float*)d_in[0];   // [B,T,D]
    const float* Wqkv = (const float*)d_in[1];   // [3D, D]
    const float* Wout = (const float*)d_in[2];   // [D, D]
    float* out = (float*)d_out;                  // [B,T,D]

    void *p_xh, *p_w1h, *p_w2h, *p_ah;
    void *p_qnh, *p_knh, *p_vh;
    cudaGetSymbolAddress(&p_xh, g_xh);
    cudaGetSymbolAddress(&p_w1h, g_w1h); cudaGetSymbolAddress(&p_w2h, g_w2h);
    cudaGetSymbolAddress(&p_ah, g_ah);
    cudaGetSymbolAddress(&p_qnh, g_qnh);
    cudaGetSymbolAddress(&p_knh, g_knh);
    cudaGetSymbolAddress(&p_vh, g_vh2);

    static bool attr_done = false;
    if (!attr_done) {
        cudaFuncSetAttribute(gemm_qkv_fused,
                             cudaFuncAttributeMaxDynamicSharedMemorySize, GEMM1_SMEM);
        cudaFuncSetAttribute(gemm_f16_1p,
                             cudaFuncAttributeMaxDynamicSharedMemorySize, GEMM1_SMEM);
        cudaFuncSetAttribute(yat_attn_tc,
                             cudaFuncAttributeMaxDynamicSharedMemorySize, ATT_SMEM);
        attr_done = true;
    }

    const int M = BQ * TQ;  // 4096

    // 0) convert inputs to fp16 (hi only)
    conv_f16<<<(M * DQ / 4) / 256, 256>>>(x, (uint32_t*)p_xh, M * DQ / 4);
    conv_f16<<<(ROW3 * DQ / 4) / 256, 256>>>(Wqkv, (uint32_t*)p_w1h, ROW3 * DQ / 4);
    conv_f16<<<(DQ * DQ / 4) / 256, 256>>>(Wout, (uint32_t*)p_w2h, DQ * DQ / 4);

    // 1) qkv GEMM with fused normalize + fp16 head-major epilogue
    gemm_qkv_fused<<<dim3(ROW3 / 128, M / 128), 256, GEMM1_SMEM>>>(
        (const uint16_t*)p_xh, (const uint16_t*)p_w1h,
        (__half*)p_qnh, (__half*)p_knh, (__half*)p_vh, DQ);

    // 2) causal yat attention (S 1-pass, V 1-pass, fp32 den) -> fp16 att
    yat_attn_tc<<<dim3(TQ / 64, HQ, BQ), 128, ATT_SMEM>>>(
        (const __half*)p_qnh, (const __half*)p_knh, (const __half*)p_vh,
        (uint32_t*)p_ah);

    // 3) out = att @ Wout^T : [4096,1024]  (fp16 1-pass)
    gemm_f16_1p<<<dim3(DQ / 128, M / 128), 256, GEMM1_SMEM>>>(
        (const uint16_t*)p_ah, (const uint16_t*)p_w2h,
        out, M, DQ, DQ);
}

// round 15
// speedup vs baseline: 11.8669x; 1.0733x over previous
#include <cuda_runtime.h>
#include <cuda_fp16.h>
#include <cstddef>
#include <cstdint>

// Problem constants (fixed by setup_inputs)
#define BQ   2
#define TQ   2048
#define DQ   1024
#define HQ   16
#define HDQ  64
#define ROW3 3072   // 3*DQ

// Scratch (device globals — no allocation allowed). u32 = packed fp16x2.
__device__ uint32_t g_xh [(size_t)BQ * TQ * DQ / 2]; // x fp16 (hi only)
__device__ uint32_t g_w1h[(size_t)ROW3 * DQ / 2];    // Wqkv hi
__device__ uint32_t g_w2h[(size_t)DQ * DQ / 2];      // Wout hi
__device__ uint32_t g_ah [(size_t)BQ * TQ * DQ / 2]; // attention out (fp16 hi)
// head-major [b][h][t][64] fp16 tensors for attention
__device__ __half   g_qnh[(size_t)BQ * HQ * TQ * HDQ];
__device__ __half   g_knh[(size_t)BQ * HQ * TQ * HDQ];
__device__ __half   g_vh2[(size_t)BQ * HQ * TQ * HDQ];

typedef unsigned long long ull;

__device__ __forceinline__ unsigned su32(const void* p) {
    return (unsigned)__cvta_generic_to_shared(p);
}

// ---------------------------------------------------------------------------
// Warp-level tensor-core + async-copy primitives (base-target PTX)
// ---------------------------------------------------------------------------
#define LDSM_X4(r0, r1, r2, r3, addr) \
    asm volatile("ldmatrix.sync.aligned.m8n8.x4.shared.b16 {%0,%1,%2,%3}, [%4];" \
        : "=r"(r0), "=r"(r1), "=r"(r2), "=r"(r3) : "r"(addr))

#define LDSM_X4_T(r0, r1, r2, r3, addr) \
    asm volatile("ldmatrix.sync.aligned.m8n8.x4.trans.shared.b16 {%0,%1,%2,%3}, [%4];" \
        : "=r"(r0), "=r"(r1), "=r"(r2), "=r"(r3) : "r"(addr))

#define MMAH(c, a, b0, b1) \
    asm volatile("mma.sync.aligned.m16n8k16.row.col.f32.f16.f16.f32 " \
        "{%0,%1,%2,%3}, {%4,%5,%6,%7}, {%8,%9}, {%0,%1,%2,%3};" \
        : "+f"((c)[0]), "+f"((c)[1]), "+f"((c)[2]), "+f"((c)[3]) \
        : "r"((a)[0]), "r"((a)[1]), "r"((a)[2]), "r"((a)[3]), "r"(b0), "r"(b1))

#define CP16(dst, src) \
    asm volatile("cp.async.cg.shared.global [%0], [%1], 16;" :: "r"(dst), "l"(src))
#define CP_COMMIT() asm volatile("cp.async.commit_group;" ::: "memory")
#define CP_WAIT(n)  asm volatile("cp.async.wait_group %0;" :: "n"(n) : "memory")

// pack two fp16 (from floats) into one u32 (lo = first arg)
__device__ __forceinline__ uint32_t packh2(float lo, float hi) {
    __half2 t = __halves2half2(__float2half_rn(lo), __float2half_rn(hi));
    return *reinterpret_cast<uint32_t*>(&t);
}

#define RCPA(d, a) \
    asm("rcp.approx.f32 %0, %1;" : "=f"(d) : "f"(a))

// ---------------------------------------------------------------------------
// Merged convert: x, Wqkv, Wout -> packed fp16 (hi only), single launch.
// ---------------------------------------------------------------------------
#define N_X4  ((BQ * TQ * DQ) / 4)     // 1048576
#define N_W14 ((ROW3 * DQ) / 4)        // 786432
#define N_W24 ((DQ * DQ) / 4)          // 262144

__global__ __launch_bounds__(256) void conv_all(const float* __restrict__ x,
                                                const float* __restrict__ w1,
                                                const float* __restrict__ w2,
                                                uint32_t* __restrict__ xh,
                                                uint32_t* __restrict__ w1h,
                                                uint32_t* __restrict__ w2h) {
    int i = blockIdx.x * blockDim.x + threadIdx.x;
    const float* src;
    uint32_t* dst;
    if (i < N_X4) {
        src = x; dst = xh;
    } else if (i < N_X4 + N_W14) {
        i -= N_X4; src = w1; dst = w1h;
    } else {
        i -= N_X4 + N_W14; src = w2; dst = w2h;
        if (i >= N_W24) return;
    }
    float4 f = ((const float4*)src)[i];
    dst[2 * i]     = packh2(f.x, f.y);
    dst[2 * i + 1] = packh2(f.z, f.w);
}

// ---------------------------------------------------------------------------
// GEMM smem layout (shared by both GEMM kernels)
// ---------------------------------------------------------------------------
#define RSTR 80
#define NSTG 3
#define STG1 20480
#define OFF1_BH 10240
#define GEMM1_SMEM (NSTG * STG1)

extern __shared__ unsigned char g_dsm[];

// ---------------------------------------------------------------------------
// qkv GEMM with FUSED normalize epilogue (unchanged from R14).
// ---------------------------------------------------------------------------
__global__ __launch_bounds__(256, 2) void gemm_qkv_fused(
    const uint16_t* __restrict__ Ah, const uint16_t* __restrict__ Bh,
    __half* __restrict__ qnh, __half* __restrict__ knh, __half* __restrict__ vh,
    int K) {

    const int tid  = threadIdx.x;
    const int wid  = tid >> 5;
    const int lane = tid & 31;
    const int wm   = wid & 3;
    const int wn   = wid >> 2;

    const int row0 = blockIdx.y * 128;
    const int col0 = blockIdx.x * 128;

    const int lr = (lane & 7) + ((lane >> 3) & 1) * 8;
    const int lk = (lane >> 4) * 16;

    const unsigned sb = su32(g_dsm);

    const int r0p = (tid * 2) >> 2,     s0p = (tid * 2) & 3;
    const int r1p = (tid * 2 + 1) >> 2, s1p = (tid * 2 + 1) & 3;

    auto issue = [&](int c) {
        const unsigned base = sb + (unsigned)(c % NSTG) * STG1;
        const int k0 = c * 32;
        const unsigned d0 = base + (unsigned)(r0p * RSTR + s0p * 16);
        const unsigned d1 = base + (unsigned)(r1p * RSTR + s1p * 16);
        const size_t a0 = (size_t)(row0 + r0p) * K + k0 + s0p * 8;
        const size_t a1 = (size_t)(row0 + r1p) * K + k0 + s1p * 8;
        CP16(d0, Ah + a0);
        CP16(d1, Ah + a1);
        const size_t b0 = (size_t)(col0 + r0p) * K + k0 + s0p * 8;
        const size_t b1 = (size_t)(col0 + r1p) * K + k0 + s1p * 8;
        CP16(d0 + OFF1_BH, Bh + b0);
        CP16(d1 + OFF1_BH, Bh + b1);
    };

    float acc[2][8][4];
#pragma unroll
    for (int mt = 0; mt < 2; mt++)
#pragma unroll
        for (int nt = 0; nt < 8; nt++)
#pragma unroll
            for (int e = 0; e < 4; e++) acc[mt][nt][e] = 0.0f;

    const int nchunks = K / 32;

    issue(0); CP_COMMIT();
    issue(1); CP_COMMIT();

    for (int j = 0; j < nchunks; j++) {
        CP_WAIT(1);
        __syncthreads();

        if (j + 2 < nchunks) issue(j + 2);
        CP_COMMIT();

        const unsigned base = sb + (unsigned)(j % NSTG) * STG1;
        const unsigned aH = base, bH = base + OFF1_BH;

#pragma unroll
        for (int ks = 0; ks < 2; ks++) {
            const unsigned kb = (unsigned)(ks * 32 + lk);
            uint32_t ah[2][4];
#pragma unroll
            for (int mt = 0; mt < 2; mt++) {
                const unsigned ro = (unsigned)((wm * 32 + mt * 16 + lr) * RSTR) + kb;
                LDSM_X4(ah[mt][0], ah[mt][1], ah[mt][2], ah[mt][3], aH + ro);
            }
            uint32_t bh[4][4];
#pragma unroll
            for (int np = 0; np < 4; np++) {
                const unsigned ro = (unsigned)((wn * 64 + np * 16 + lr) * RSTR) + kb;
                LDSM_X4(bh[np][0], bh[np][1], bh[np][2], bh[np][3], bH + ro);
            }
#pragma unroll
            for (int mt = 0; mt < 2; mt++)
#pragma unroll
                for (int nt = 0; nt < 8; nt++) {
                    const int np = nt >> 1, sel = nt & 1;
                    MMAH(acc[mt][nt], ah[mt], bh[np][sel], bh[np][sel + 2]);
                }
        }
    }

    // ---- fused epilogue: normalize (q,k) + fp16 head-major write ----
    const int er   = lane >> 2;
    const int ec   = (lane & 3) * 2;
    const int part = col0 >> 10;                       // 0=q, 1=k, 2=v
    const int hloc = ((col0 & 1023) >> 6) + wn;        // head 0..15
    __half* dstp = (part == 0) ? qnh : (part == 1 ? knh : vh);

#pragma unroll
    for (int mt = 0; mt < 2; mt++) {
        const int r0 = row0 + wm * 32 + mt * 16 + er;  // token (b*TQ + t)
        const int r1 = r0 + 8;
        float s0 = 1.0f, s1 = 1.0f;
        if (part < 2) {
            float ss0 = 0.0f, ss1 = 0.0f;
#pragma unroll
            for (int nt = 0; nt < 8; nt++) {
                ss0 += acc[mt][nt][0] * acc[mt][nt][0] + acc[mt][nt][1] * acc[mt][nt][1];
                ss1 += acc[mt][nt][2] * acc[mt][nt][2] + acc[mt][nt][3] * acc[mt][nt][3];
            }
            ss0 += __shfl_xor_sync(0xffffffffu, ss0, 1);
            ss0 += __shfl_xor_sync(0xffffffffu, ss0, 2);
            ss1 += __shfl_xor_sync(0xffffffffu, ss1, 1);
            ss1 += __shfl_xor_sync(0xffffffffu, ss1, 2);
            s0 = 1.0f / fmaxf(sqrtf(ss0), 1e-12f);
            s1 = 1.0f / fmaxf(sqrtf(ss1), 1e-12f);
        }
        const int b0 = r0 >> 11, t0 = r0 & (TQ - 1);
        const int b1 = r1 >> 11, t1 = r1 & (TQ - 1);
        const size_t base0 = (((size_t)(b0 * HQ + hloc)) * TQ + t0) * HDQ;
        const size_t base1 = (((size_t)(b1 * HQ + hloc)) * TQ + t1) * HDQ;
#pragma unroll
        for (int nt = 0; nt < 8; nt++) {
            const int d = nt * 8 + ec;
            *(uint32_t*)(dstp + base0 + d) = packh2(acc[mt][nt][0] * s0, acc[mt][nt][1] * s0);
            *(uint32_t*)(dstp + base1 + d) = packh2(acc[mt][nt][2] * s1, acc[mt][nt][3] * s1);
        }
    }
}

// ---------------------------------------------------------------------------
// 1-pass fp16 GEMM (fp32 output) — out projection (unchanged).
// ---------------------------------------------------------------------------
__global__ __launch_bounds__(256, 2) void gemm_f16_1p(
    const uint16_t* __restrict__ Ah, const uint16_t* __restrict__ Bh,
    float* __restrict__ C, int M, int N, int K) {

    const int tid  = threadIdx.x;
    const int wid  = tid >> 5;
    const int lane = tid & 31;
    const int wm   = wid & 3;
    const int wn   = wid >> 2;

    const int row0 = blockIdx.y * 128;
    const int col0 = blockIdx.x * 128;

    const int lr = (lane & 7) + ((lane >> 3) & 1) * 8;
    const int lk = (lane >> 4) * 16;

    const unsigned sb = su32(g_dsm);

    const int r0p = (tid * 2) >> 2,     s0p = (tid * 2) & 3;
    const int r1p = (tid * 2 + 1) >> 2, s1p = (tid * 2 + 1) & 3;

    auto issue = [&](int c) {
        const unsigned base = sb + (unsigned)(c % NSTG) * STG1;
        const int k0 = c * 32;
        const unsigned d0 = base + (unsigned)(r0p * RSTR + s0p * 16);
        const unsigned d1 = base + (unsigned)(r1p * RSTR + s1p * 16);
        const size_t a0 = (size_t)(row0 + r0p) * K + k0 + s0p * 8;
        const size_t a1 = (size_t)(row0 + r1p) * K + k0 + s1p * 8;
        CP16(d0, Ah + a0);
        CP16(d1, Ah + a1);
        const size_t b0 = (size_t)(col0 + r0p) * K + k0 + s0p * 8;
        const size_t b1 = (size_t)(col0 + r1p) * K + k0 + s1p * 8;
        CP16(d0 + OFF1_BH, Bh + b0);
        CP16(d1 + OFF1_BH, Bh + b1);
    };

    float acc[2][8][4];
#pragma unroll
    for (int mt = 0; mt < 2; mt++)
#pragma unroll
        for (int nt = 0; nt < 8; nt++)
#pragma unroll
            for (int e = 0; e < 4; e++) acc[mt][nt][e] = 0.0f;

    const int nchunks = K / 32;

    issue(0); CP_COMMIT();
    issue(1); CP_COMMIT();

    for (int j = 0; j < nchunks; j++) {
        CP_WAIT(1);
        __syncthreads();

        if (j + 2 < nchunks) issue(j + 2);
        CP_COMMIT();

        const unsigned base = sb + (unsigned)(j % NSTG) * STG1;
        const unsigned aH = base, bH = base + OFF1_BH;

#pragma unroll
        for (int ks = 0; ks < 2; ks++) {
            const unsigned kb = (unsigned)(ks * 32 + lk);
            uint32_t ah[2][4];
#pragma unroll
            for (int mt = 0; mt < 2; mt++) {
                const unsigned ro = (unsigned)((wm * 32 + mt * 16 + lr) * RSTR) + kb;
                LDSM_X4(ah[mt][0], ah[mt][1], ah[mt][2], ah[mt][3], aH + ro);
            }
            uint32_t bh[4][4];
#pragma unroll
            for (int np = 0; np < 4; np++) {
                const unsigned ro = (unsigned)((wn * 64 + np * 16 + lr) * RSTR) + kb;
                LDSM_X4(bh[np][0], bh[np][1], bh[np][2], bh[np][3], bH + ro);
            }
#pragma unroll
            for (int mt = 0; mt < 2; mt++)
#pragma unroll
                for (int nt = 0; nt < 8; nt++) {
                    const int np = nt >> 1, sel = nt & 1;
                    MMAH(acc[mt][nt], ah[mt], bh[np][sel], bh[np][sel + 2]);
                }
        }
    }

    const int er = lane >> 2;
    const int ec = (lane & 3) * 2;
#pragma unroll
    for (int mt = 0; mt < 2; mt++) {
        const int row = row0 + wm * 32 + mt * 16 + er;
#pragma unroll
        for (int nt = 0; nt < 8; nt++) {
            const int col = col0 + wn * 64 + nt * 8 + ec;
            *(float2*)(C + (size_t)row * N + col) =
                make_float2(acc[mt][nt][0], acc[mt][nt][1]);
            *(float2*)(C + (size_t)(row + 8) * N + col) =
                make_float2(acc[mt][nt][2], acc[mt][nt][3]);
        }
    }
}

// ---------------------------------------------------------------------------
// Causal yat attention, fine-grained S/T/V pipeline:
// per key tile, 4 groups of 16 keys; schedule S0,S1,T0,V0,S2,T1,V1,S3,T2,V2,
// T3,V3 so the transform overlaps in-flight tensor work. Denominator row-sums
// accumulated by an extra HMMA against a constant all-ones B fragment.
// ---------------------------------------------------------------------------
#define VR 144
#define OFF_VH (64 * VR)
#define AST (128 * VR)        // 18432 B per stage
#define ATT_SMEM (2 * AST)    // 36864 B
#define ONES2 0x3C003C00u     // fp16x2 {1.0, 1.0}

__global__ __launch_bounds__(128) void yat_attn_tc(
    const __half* __restrict__ qnh,
    const __half* __restrict__ knh,
    const __half* __restrict__ vh,
    uint32_t* __restrict__ ath) {

    const int tid  = threadIdx.x;
    const int wid  = tid >> 5;
    const int lane = tid & 31;

    const int qt = (int)gridDim.x - 1 - (int)blockIdx.x;  // longest first
    const int h  = blockIdx.y;
    const int b  = blockIdx.z;
    const int q0 = qt * 64;

    const int lr = (lane & 7) + ((lane >> 3) & 1) * 8;
    const int lk = (lane >> 4) * 16;

    const unsigned sb = su32(g_dsm);
    const size_t headBase = ((size_t)(b * HQ + h)) * TQ;

    const int seg = tid & 7;
    const int rb  = tid >> 3;

    // ---- stage Q (hi) into stage 0, pull A-fragments ----
#pragma unroll
    for (int i = 0; i < 4; i++) {
        const int r = rb + 16 * i;
        const size_t so = (headBase + q0 + r) * HDQ + seg * 8;
        CP16(sb + (unsigned)(r * VR + seg * 16), qnh + so);
    }
    CP_COMMIT();
    CP_WAIT(0);
    __syncthreads();

    uint32_t qfh[4][4];
#pragma unroll
    for (int kc = 0; kc < 4; kc++) {
        const unsigned ro = (unsigned)((wid * 16 + lr) * VR + kc * 32 + lk);
        LDSM_X4(qfh[kc][0], qfh[kc][1], qfh[kc][2], qfh[kc][3], sb + ro);
    }
    __syncthreads();   // Q frags pulled; stage 0 free for K/V

    auto issueKV = [&](int kt) {
        const unsigned base = sb + (unsigned)(kt & 1) * AST;
        const size_t tok = headBase + (size_t)kt * 64;
#pragma unroll
        for (int i = 0; i < 4; i++) {
            const int r = rb + 16 * i;
            const size_t so = (tok + r) * HDQ + seg * 8;
            const unsigned dofs = (unsigned)(r * VR + seg * 16);
            CP16(base + dofs,          knh + so);
            CP16(base + OFF_VH + dofs, vh + so);
        }
    };

    float accO[8][4];
#pragma unroll
    for (int nt = 0; nt < 8; nt++)
#pragma unroll
        for (int e = 0; e < 4; e++) accO[nt][e] = 0.0f;
    float accD[4] = {0.0f, 0.0f, 0.0f, 0.0f};

    const int qg0 = q0 + wid * 16 + (lane >> 2);

    issueKV(0); CP_COMMIT();

    for (int kt = 0; kt <= qt; kt++) {
        CP_WAIT(0);
        __syncthreads();   // tile kt visible; all warps done with buffer kt&1

        if (kt + 1 <= qt) issueKV(kt + 1);
        CP_COMMIT();

        const unsigned base = sb + (unsigned)(kt & 1) * AST;
        const unsigned kH = base, vHb = base + OFF_VH;
        const bool diag = (kt == qt);

        // S(g): S fragments for key group g (keys 16g..16g+15)
        auto S_group = [&](int g, float (&sfg)[2][4]) {
#pragma unroll
            for (int half = 0; half < 2; half++)
#pragma unroll
                for (int e = 0; e < 4; e++) sfg[half][e] = 0.0f;
#pragma unroll
            for (int kc = 0; kc < 4; kc++) {
                uint32_t khf[4];
                const unsigned ro = (unsigned)((g * 16 + lr) * VR + kc * 32 + lk);
                LDSM_X4(khf[0], khf[1], khf[2], khf[3], kH + ro);
                MMAH(sfg[0], qfh[kc], khf[0], khf[2]);
                MMAH(sfg[1], qfh[kc], khf[1], khf[3]);
            }
        };

        // T(g): transform S -> packed fp16 w A-fragment
        auto T_group = [&](int g, const float (&sfg)[2][4], uint32_t (&ah)[4]) {
#pragma unroll
            for (int half = 0; half < 2; half++) {
                float w[4];
#pragma unroll
                for (int e = 0; e < 4; e++) {
                    const float d = sfg[half][e];
                    const float den = fmaxf(fmaf(-2.0f, d, 2.01f), 1e-6f);
                    float rc; RCPA(rc, den);
                    w[e] = d * d * rc;
                }
                if (diag) {
                    const int kg = kt * 64 + (2 * g + half) * 8 + 2 * (lane & 3);
                    if (kg     > qg0)     w[0] = 0.0f;
                    if (kg + 1 > qg0)     w[1] = 0.0f;
                    if (kg     > qg0 + 8) w[2] = 0.0f;
                    if (kg + 1 > qg0 + 8) w[3] = 0.0f;
                }
                ah[2 * half]     = packh2(w[0], w[1]);
                ah[2 * half + 1] = packh2(w[2], w[3]);
            }
        };

        // V(g): O += w@V over this key group + denominator ones-MMA
        auto V_group = [&](int g, const uint32_t (&ah)[4]) {
#pragma unroll
            for (int og = 0; og < 4; og++) {
                uint32_t vhf[4];
                const unsigned ro = (unsigned)((g * 16 + lr) * VR + og * 32 + lk);
                LDSM_X4_T(vhf[0], vhf[1], vhf[2], vhf[3], vHb + ro);
                MMAH(accO[2 * og],     ah, vhf[0], vhf[1]);
                MMAH(accO[2 * og + 1], ah, vhf[2], vhf[3]);
            }
            MMAH(accD, ah, ONES2, ONES2);
        };

        float sfA[2][4], sfB[2][4];
        uint32_t ahA[4], ahB[4];
        S_group(0, sfA);
        S_group(1, sfB);
        T_group(0, sfA, ahA);
        V_group(0, ahA);
        S_group(2, sfA);
        T_group(1, sfB, ahB);
        V_group(1, ahB);
        S_group(3, sfB);
        T_group(2, sfA, ahA);
        V_group(2, ahA);
        T_group(3, sfB, ahB);
        V_group(3, ahB);
        // no end-of-loop sync: next iteration's barrier provides the ordering
    }

    // ---- epilogue: divide by den (row sums live in accD), write fp16 hi ----
    float inv0, inv1;
    RCPA(inv0, accD[0] + 1e-6f);
    RCPA(inv1, accD[2] + 1e-6f);

    const size_t rowg  = (size_t)(b * TQ) + q0 + wid * 16 + (lane >> 2);
    const int    colb2 = h * (HDQ / 2) + (lane & 3);
#pragma unroll
    for (int nt = 0; nt < 8; nt++) {
        ath[rowg * (DQ / 2) + colb2 + nt * 4] =
            packh2(accO[nt][0] * inv0, accO[nt][1] * inv0);
        ath[(rowg + 8) * (DQ / 2) + colb2 + nt * 4] =
            packh2(accO[nt][2] * inv1, accO[nt][3] * inv1);
    }
}

// ---------------------------------------------------------------------------
// kernel_launch
// ---------------------------------------------------------------------------
extern "C" void kernel_launch(void* const* d_in, const int* in_sizes, int n_in,
                              void* d_out, int out_size) {
    (void)in_sizes; (void)n_in; (void)out_size;
    const float* x    = (const float*)d_in[0];   // [B,T,D]
    const float* Wqkv = (const float*)d_in[1];   // [3D, D]
    const float* Wout = (const float*)d_in[2];   // [D, D]
    float* out = (float*)d_out;                  // [B,T,D]

    void *p_xh, *p_w1h, *p_w2h, *p_ah;
    void *p_qnh, *p_knh, *p_vh;
    cudaGetSymbolAddress(&p_xh, g_xh);
    cudaGetSymbolAddress(&p_w1h, g_w1h); cudaGetSymbolAddress(&p_w2h, g_w2h);
    cudaGetSymbolAddress(&p_ah, g_ah);
    cudaGetSymbolAddress(&p_qnh, g_qnh);
    cudaGetSymbolAddress(&p_knh, g_knh);
    cudaGetSymbolAddress(&p_vh, g_vh2);

    static bool attr_done = false;
    if (!attr_done) {
        cudaFuncSetAttribute(gemm_qkv_fused,
                             cudaFuncAttributeMaxDynamicSharedMemorySize, GEMM1_SMEM);
        cudaFuncSetAttribute(gemm_f16_1p,
                             cudaFuncAttributeMaxDynamicSharedMemorySize, GEMM1_SMEM);
        cudaFuncSetAttribute(yat_attn_tc,
                             cudaFuncAttributeMaxDynamicSharedMemorySize, ATT_SMEM);
        attr_done = true;
    }

    const int M = BQ * TQ;  // 4096

    // 0) convert all fp32 inputs to fp16 in one launch
    const int ntot = N_X4 + N_W14 + N_W24;
    conv_all<<<(ntot + 255) / 256, 256>>>(x, Wqkv, Wout,
        (uint32_t*)p_xh, (uint32_t*)p_w1h, (uint32_t*)p_w2h);

    // 1) qkv GEMM with fused normalize + fp16 head-major epilogue
    gemm_qkv_fused<<<dim3(ROW3 / 128, M / 128), 256, GEMM1_SMEM>>>(
        (const uint16_t*)p_xh, (const uint16_t*)p_w1h,
        (__half*)p_qnh, (__half*)p_knh, (__half*)p_vh, DQ);

    // 2) causal yat attention (pipelined S/T/V, ones-MMA den) -> fp16 att
    yat_attn_tc<<<dim3(TQ / 64, HQ, BQ), 128, ATT_SMEM>>>(
        (const __half*)p_qnh, (const __half*)p_knh, (const __half*)p_vh,
        (uint32_t*)p_ah);

    // 3) out = att @ Wout^T : [4096,1024]  (fp16 1-pass)
    gemm_f16_1p<<<dim3(DQ / 128, M / 128), 256, GEMM1_SMEM>>>(
        (const uint16_t*)p_ah, (const uint16_t*)p_w2h,
        out, M, DQ, DQ);
}